// round 4
// baseline (speedup 1.0000x reference)
#include <cuda_runtime.h>
#include <cuda_bf16.h>
#include <math.h>

#define B_   2
#define S_   2048
#define HID  2048
#define NH   16
#define HD   128
#define RK   64
#define BS_ROWS (B_*S_)        // 4096
#define HROWS   (B_*S_*NH)     // 65536

// -------- scratch (static __device__; no allocation allowed) --------
__device__ float g_Q[BS_ROWS*HID];
__device__ float g_K[BS_ROWS*HID];
__device__ float g_V[BS_ROWS*HID];
__device__ float g_qa[HROWS*RK];
__device__ float g_kc[HROWS*RK];
__device__ float g_vc[HROWS*RK];
__device__ float g_qg[HROWS*HD];
__device__ float g_oc[HROWS*RK];
__device__ float g_gated[BS_ROWS*HID];

// =====================================================================
// SGEMM: C[M,N] = A[M,K] @ B[K,N], fp32, all dims multiples of 128
// 128x128 block tile, BK=8, 256 threads, 8x8 microtile per thread.
// =====================================================================
__global__ __launch_bounds__(256) void sgemm128(
    const float* __restrict__ A, const float* __restrict__ Bm,
    float* __restrict__ C, int M, int N, int K)
{
    __shared__ float As[8][128];
    __shared__ float Bs[8][128];

    const int tid  = threadIdx.x;
    const int tx   = tid & 15;
    const int ty   = tid >> 4;
    const int row0 = blockIdx.y * 128;
    const int col0 = blockIdx.x * 128;

    const int aRow = tid >> 1;          // 0..127
    const int aCol = (tid & 1) << 2;    // 0 or 4
    const int bRow = tid >> 5;          // 0..7
    const int bCol = (tid & 31) << 2;   // 0..124

    const float* Ap = A  + (size_t)(row0 + aRow) * K + aCol;
    const float* Bp = Bm + (size_t)bRow * N + col0 + bCol;

    float acc[8][8];
#pragma unroll
    for (int i = 0; i < 8; i++)
#pragma unroll
        for (int j = 0; j < 8; j++) acc[i][j] = 0.f;

    for (int kt = 0; kt < K; kt += 8) {
        float4 a4 = *(const float4*)(Ap + kt);
        float4 b4 = *(const float4*)(Bp + (size_t)kt * N);
        As[aCol + 0][aRow] = a4.x;
        As[aCol + 1][aRow] = a4.y;
        As[aCol + 2][aRow] = a4.z;
        As[aCol + 3][aRow] = a4.w;
        *(float4*)&Bs[bRow][bCol] = b4;
        __syncthreads();

#pragma unroll
        for (int k = 0; k < 8; k++) {
            float ar[8], br[8];
#pragma unroll
            for (int i = 0; i < 4; i++) {
                float4 t = *(const float4*)&As[k][ty * 8 + i * 4];
                ar[i*4+0]=t.x; ar[i*4+1]=t.y; ar[i*4+2]=t.z; ar[i*4+3]=t.w;
                (void)0;
            }
#pragma unroll
            for (int j = 0; j < 2; j++) {
                float4 t = *(const float4*)&Bs[k][tx * 8 + j * 4];
                br[j*4+0]=t.x; br[j*4+1]=t.y; br[j*4+2]=t.z; br[j*4+3]=t.w;
            }
#pragma unroll
            for (int i = 0; i < 8; i++)
#pragma unroll
                for (int j = 0; j < 8; j++)
                    acc[i][j] += ar[i] * br[j];
        }
        __syncthreads();
    }

#pragma unroll
    for (int i = 0; i < 8; i++) {
        float* cp = C + (size_t)(row0 + ty * 8 + i) * N + col0 + tx * 8;
        float4 o0 = make_float4(acc[i][0], acc[i][1], acc[i][2], acc[i][3]);
        float4 o1 = make_float4(acc[i][4], acc[i][5], acc[i][6], acc[i][7]);
        *(float4*)cp       = o0;
        *(float4*)(cp + 4) = o1;
    }
}

// =====================================================================
// RoPE + per-head projections.
// One warp per head-row (b,s,h). 8 rows / block.
//   qa = rope(q) @ Wqa[128,64]; kc = rope(k) @ Wkc; vc = v @ Wvc;
//   qg = rope(q) @ Wqg[128,128]
// =====================================================================
__global__ __launch_bounds__(256) void rope_proj(
    const int*   __restrict__ pos_ids,
    const float* __restrict__ Wqa, const float* __restrict__ Wkc,
    const float* __restrict__ Wvc, const float* __restrict__ Wqg)
{
    __shared__ float sQ[8][128], sK[8][128], sV[8][128];
    const int warp = threadIdx.x >> 5;
    const int lane = threadIdx.x & 31;
    const int row  = blockIdx.x * 8 + warp;       // (b*S+s)*NH + h
    const int bs   = row >> 4;
    const int h    = row & 15;
    const int s    = bs & (S_ - 1);

    const size_t hoff = (size_t)bs * HID + h * HD;
    *(float4*)&sQ[warp][lane * 4] = *(const float4*)(g_Q + hoff + lane * 4);
    *(float4*)&sK[warp][lane * 4] = *(const float4*)(g_K + hoff + lane * 4);
    *(float4*)&sV[warp][lane * 4] = *(const float4*)(g_V + hoff + lane * 4);
    __syncwarp();

    // RoPE on dims [0,64): out[i]=x1*c - x2*s ; out[i+32]=x2*c + x1*s
    const float pos  = (float)pos_ids[s];
    const float invf = 1.0f / powf(10000.0f, (float)(2 * lane) * (1.0f / 64.0f));
    const float ang  = pos * invf;
    const float c = cosf(ang), sn = sinf(ang);
    {
        float x1 = sQ[warp][lane], x2 = sQ[warp][lane + 32];
        sQ[warp][lane]      = x1 * c - x2 * sn;
        sQ[warp][lane + 32] = x2 * c + x1 * sn;
        x1 = sK[warp][lane]; x2 = sK[warp][lane + 32];
        sK[warp][lane]      = x1 * c - x2 * sn;
        sK[warp][lane + 32] = x2 * c + x1 * sn;
    }
    __syncwarp();

    float a0=0,a1=0,b0=0,b1=0,c0=0,c1=0,g0=0,g1=0,g2=0,g3=0;
#pragma unroll 4
    for (int d = 0; d < 128; d++) {
        const float xq = sQ[warp][d];
        const float xk = sK[warp][d];
        const float xv = sV[warp][d];
        a0 += xq * __ldg(&Wqa[d * 64  + lane]);
        a1 += xq * __ldg(&Wqa[d * 64  + lane + 32]);
        b0 += xk * __ldg(&Wkc[d * 64  + lane]);
        b1 += xk * __ldg(&Wkc[d * 64  + lane + 32]);
        c0 += xv * __ldg(&Wvc[d * 64  + lane]);
        c1 += xv * __ldg(&Wvc[d * 64  + lane + 32]);
        g0 += xq * __ldg(&Wqg[d * 128 + lane]);
        g1 += xq * __ldg(&Wqg[d * 128 + lane + 32]);
        g2 += xq * __ldg(&Wqg[d * 128 + lane + 64]);
        g3 += xq * __ldg(&Wqg[d * 128 + lane + 96]);
    }
    g_qa[(size_t)row * 64 + lane]       = a0;
    g_qa[(size_t)row * 64 + lane + 32]  = a1;
    g_kc[(size_t)row * 64 + lane]       = b0;
    g_kc[(size_t)row * 64 + lane + 32]  = b1;
    g_vc[(size_t)row * 64 + lane]       = c0;
    g_vc[(size_t)row * 64 + lane + 32]  = c1;
    g_qg[(size_t)row * 128 + lane]      = g0;
    g_qg[(size_t)row * 128 + lane + 32] = g1;
    g_qg[(size_t)row * 128 + lane + 64] = g2;
    g_qg[(size_t)row * 128 + lane + 96] = g3;
}

// =====================================================================
// Flash attention, fp32: per (b,h): softmax(qa kc^T / 8) @ vc
// Q-tile 64 rows, K-tile 64. 256 threads, 4x4 microtile per thread.
// =====================================================================
#define AP 68  // row pad: 16B-aligned rows, low smem bank conflict
__global__ __launch_bounds__(256) void attn_kernel()
{
    extern __shared__ float sm[];
    float (*Qs)[AP] = (float(*)[AP])(sm);
    float (*Ks)[AP] = (float(*)[AP])(sm + 64 * AP);
    float (*Vs)[AP] = (float(*)[AP])(sm + 2 * 64 * AP);
    float (*Ps)[AP] = (float(*)[AP])(sm + 3 * 64 * AP);
    float* mrow = sm + 4 * 64 * AP;
    float* lrow = mrow + 64;
    float* arow = lrow + 64;

    const int tid = threadIdx.x;
    const int tx  = tid & 15;
    const int ty  = tid >> 4;
    const int b   = blockIdx.y >> 4;
    const int h   = blockIdx.y & 15;
    const int q0  = blockIdx.x * 64;
    const int i0  = ty * 4, j0 = tx * 4;

    for (int idx = tid; idx < 64 * 16; idx += 256) {
        const int r = idx >> 4, c4 = (idx & 15) << 2;
        *(float4*)&Qs[r][c4] =
            *(const float4*)(g_qa + ((size_t)(b * S_ + q0 + r) * NH + h) * RK + c4);
    }
    if (tid < 64) { mrow[tid] = -INFINITY; lrow[tid] = 0.f; }

    float acc[4][4];
#pragma unroll
    for (int i = 0; i < 4; i++)
#pragma unroll
        for (int j = 0; j < 4; j++) acc[i][j] = 0.f;

    for (int kt = 0; kt < S_; kt += 64) {
        __syncthreads();  // previous tile's consumers done; Qs/stat init visible
        for (int idx = tid; idx < 64 * 16; idx += 256) {
            const int r = idx >> 4, c4 = (idx & 15) << 2;
            const size_t base = ((size_t)(b * S_ + kt + r) * NH + h) * RK + c4;
            *(float4*)&Ks[r][c4] = *(const float4*)(g_kc + base);
            *(float4*)&Vs[r][c4] = *(const float4*)(g_vc + base);
        }
        __syncthreads();

        // S = Q K^T  (64x64x64)
        float s[4][4];
#pragma unroll
        for (int i = 0; i < 4; i++)
#pragma unroll
            for (int j = 0; j < 4; j++) s[i][j] = 0.f;

#pragma unroll 4
        for (int r = 0; r < 64; r += 4) {
            float4 aa[4], bb[4];
#pragma unroll
            for (int ii = 0; ii < 4; ii++) aa[ii] = *(const float4*)&Qs[i0 + ii][r];
#pragma unroll
            for (int jj = 0; jj < 4; jj++) bb[jj] = *(const float4*)&Ks[j0 + jj][r];
#pragma unroll
            for (int ii = 0; ii < 4; ii++)
#pragma unroll
                for (int jj = 0; jj < 4; jj++)
                    s[ii][jj] += aa[ii].x * bb[jj].x + aa[ii].y * bb[jj].y
                               + aa[ii].z * bb[jj].z + aa[ii].w * bb[jj].w;
        }
#pragma unroll
        for (int ii = 0; ii < 4; ii++)
#pragma unroll
            for (int jj = 0; jj < 4; jj++)
                Ps[i0 + ii][j0 + jj] = s[ii][jj] * 0.125f;
        __syncthreads();

        // Online softmax row stats: one thread per row
        if (tid < 64) {
            const int r = tid;
            float m_old = mrow[r];
            float mt = m_old;
#pragma unroll 8
            for (int j = 0; j < 64; j++) mt = fmaxf(mt, Ps[r][j]);
            const float alpha = expf(m_old - mt);
            float sum = 0.f;
#pragma unroll 8
            for (int j = 0; j < 64; j++) {
                const float p = expf(Ps[r][j] - mt);
                Ps[r][j] = p;
                sum += p;
            }
            lrow[r] = lrow[r] * alpha + sum;
            mrow[r] = mt;
            arow[r] = alpha;
        }
        __syncthreads();

        float al[4];
#pragma unroll
        for (int ii = 0; ii < 4; ii++) al[ii] = arow[i0 + ii];
#pragma unroll
        for (int ii = 0; ii < 4; ii++)
#pragma unroll
            for (int jj = 0; jj < 4; jj++) acc[ii][jj] *= al[ii];

        // O += P @ V  (64x64x64)
#pragma unroll 4
        for (int r = 0; r < 64; r += 4) {
            float4 pp[4], vv[4];
#pragma unroll
            for (int ii = 0; ii < 4; ii++) pp[ii] = *(const float4*)&Ps[i0 + ii][r];
#pragma unroll
            for (int rr = 0; rr < 4; rr++) vv[rr] = *(const float4*)&Vs[r + rr][j0];
#pragma unroll
            for (int ii = 0; ii < 4; ii++) {
                acc[ii][0] += pp[ii].x*vv[0].x + pp[ii].y*vv[1].x + pp[ii].z*vv[2].x + pp[ii].w*vv[3].x;
                acc[ii][1] += pp[ii].x*vv[0].y + pp[ii].y*vv[1].y + pp[ii].z*vv[2].y + pp[ii].w*vv[3].y;
                acc[ii][2] += pp[ii].x*vv[0].z + pp[ii].y*vv[1].z + pp[ii].z*vv[2].z + pp[ii].w*vv[3].z;
                acc[ii][3] += pp[ii].x*vv[0].w + pp[ii].y*vv[1].w + pp[ii].z*vv[2].w + pp[ii].w*vv[3].w;
            }
        }
    }

#pragma unroll
    for (int ii = 0; ii < 4; ii++) {
        const float inv_l = 1.0f / lrow[i0 + ii];
        float* op = g_oc + ((size_t)(b * S_ + q0 + i0 + ii) * NH + h) * RK + j0;
#pragma unroll
        for (int jj = 0; jj < 4; jj++) op[jj] = acc[ii][jj] * inv_l;
    }
}

// =====================================================================
// uplift = out_c @ Wov[64,128]; gated = silu(qg) * uplift
// One warp per head-row.
// =====================================================================
__global__ __launch_bounds__(256) void uplift_gate(const float* __restrict__ Wov)
{
    __shared__ float xs[8][64];
    const int warp = threadIdx.x >> 5;
    const int lane = threadIdx.x & 31;
    const int row  = blockIdx.x * 8 + warp;     // (b*S+s)*NH + h

    *(float2*)&xs[warp][lane * 2] =
        *(const float2*)(g_oc + (size_t)row * 64 + lane * 2);
    __syncwarp();

    float acc[4] = {0.f, 0.f, 0.f, 0.f};
#pragma unroll 4
    for (int r = 0; r < 64; r++) {
        const float x = xs[warp][r];
        acc[0] += x * __ldg(&Wov[r * 128 + lane]);
        acc[1] += x * __ldg(&Wov[r * 128 + lane + 32]);
        acc[2] += x * __ldg(&Wov[r * 128 + lane + 64]);
        acc[3] += x * __ldg(&Wov[r * 128 + lane + 96]);
    }
    const int bs = row >> 4, h = row & 15;
    float* gp = g_gated + (size_t)bs * HID + h * HD;
#pragma unroll
    for (int k = 0; k < 4; k++) {
        const float g   = g_qg[(size_t)row * 128 + lane + 32 * k];
        const float sil = g / (1.0f + expf(-g));
        gp[lane + 32 * k] = sil * acc[k];
    }
}

// =====================================================================
extern "C" void kernel_launch(void* const* d_in, const int* in_sizes, int n_in,
                              void* d_out, int out_size)
{
    const float* hs  = (const float*)d_in[0];
    const int*   pos = (const int*)  d_in[1];
    const float* Wq  = (const float*)d_in[2];
    const float* Wk  = (const float*)d_in[3];
    const float* Wv  = (const float*)d_in[4];
    const float* Wkc = (const float*)d_in[5];
    const float* Wvc = (const float*)d_in[6];
    const float* Wqa = (const float*)d_in[7];
    const float* Wqg = (const float*)d_in[8];
    const float* Wov = (const float*)d_in[9];
    const float* Wo  = (const float*)d_in[10];
    float* out = (float*)d_out;

    float *pQ, *pK, *pV, *pG;
    cudaGetSymbolAddress((void**)&pQ, g_Q);
    cudaGetSymbolAddress((void**)&pK, g_K);
    cudaGetSymbolAddress((void**)&pV, g_V);
    cudaGetSymbolAddress((void**)&pG, g_gated);

    const dim3 gg(HID / 128, BS_ROWS / 128);
    sgemm128<<<gg, 256>>>(hs, Wq, pQ, BS_ROWS, HID, HID);
    sgemm128<<<gg, 256>>>(hs, Wk, pK, BS_ROWS, HID, HID);
    sgemm128<<<gg, 256>>>(hs, Wv, pV, BS_ROWS, HID, HID);

    rope_proj<<<HROWS / 8, 256>>>(pos, Wqa, Wkc, Wvc, Wqg);

    const int att_smem = (4 * 64 * AP + 192) * (int)sizeof(float);
    cudaFuncSetAttribute(attn_kernel,
                         cudaFuncAttributeMaxDynamicSharedMemorySize, att_smem);
    attn_kernel<<<dim3(S_ / 64, B_ * NH), 256, att_smem>>>();

    uplift_gate<<<HROWS / 8, 256>>>(Wov);

    sgemm128<<<gg, 256>>>(pG, Wo, out, BS_ROWS, HID, HID);
}

// round 6
// speedup vs baseline: 1.6839x; 1.6839x over previous
#include <cuda_runtime.h>
#include <cuda_bf16.h>
#include <math.h>
#include <stdint.h>

#define B_   2
#define S_   2048
#define HID  2048
#define NH   16
#define HD   128
#define RK   64
#define BS_ROWS (B_*S_)        // 4096
#define HROWS   (B_*S_*NH)     // 65536

// ===================== scratch (static __device__) =====================
__device__ __nv_bfloat16 g_hs_h[BS_ROWS*HID],  g_hs_l[BS_ROWS*HID];
__device__ __nv_bfloat16 g_WqT_h[HID*HID], g_WqT_l[HID*HID];
__device__ __nv_bfloat16 g_WkT_h[HID*HID], g_WkT_l[HID*HID];
__device__ __nv_bfloat16 g_WvT_h[HID*HID], g_WvT_l[HID*HID];
__device__ __nv_bfloat16 g_WoT_h[HID*HID], g_WoT_l[HID*HID];
__device__ __nv_bfloat16 g_Qr_h[BS_ROWS*HID], g_Qr_l[BS_ROWS*HID];
__device__ __nv_bfloat16 g_Kr_h[BS_ROWS*HID], g_Kr_l[BS_ROWS*HID];
__device__ __nv_bfloat16 g_V_h [BS_ROWS*HID], g_V_l [BS_ROWS*HID];
__device__ __nv_bfloat16 g_Wcat_h[256*HD], g_Wcat_l[256*HD];   // [Wqa|Wqg]^T padded
__device__ __nv_bfloat16 g_WkcT_h[256*HD], g_WkcT_l[256*HD];
__device__ __nv_bfloat16 g_WvcT_h[256*HD], g_WvcT_l[256*HD];
__device__ __nv_bfloat16 g_WovT_h[256*RK], g_WovT_l[256*RK];
__device__ float g_qa[HROWS*RK];
__device__ float g_kc[HROWS*RK];
__device__ float g_vc[HROWS*RK];
__device__ float g_qg[HROWS*HD];
__device__ __nv_bfloat16 g_oc_h[HROWS*RK], g_oc_l[HROWS*RK];
__device__ __nv_bfloat16 g_gat_h[BS_ROWS*HID], g_gat_l[BS_ROWS*HID];
__device__ float g_cos[S_*32], g_sin[S_*32];

// ===================== PTX helpers (sm_80-era only; sm_100 base target) ====
__device__ __forceinline__ uint32_t smem_u32(const void* p) {
    uint32_t a;
    asm("{ .reg .u64 t; cvta.to.shared.u64 t, %1; cvt.u32.u64 %0, t; }" : "=r"(a) : "l"(p));
    return a;
}
__device__ __forceinline__ void cpasync16(uint32_t dst, const void* src) {
    asm volatile("cp.async.cg.shared.global [%0], [%1], 16;" :: "r"(dst), "l"(src));
}
__device__ __forceinline__ void ldsm4(uint32_t* r, uint32_t addr) {
    asm volatile("ldmatrix.sync.aligned.m8n8.x4.shared.b16 {%0,%1,%2,%3}, [%4];"
        : "=r"(r[0]), "=r"(r[1]), "=r"(r[2]), "=r"(r[3]) : "r"(addr));
}
__device__ __forceinline__ void mma16816(float* c, const uint32_t* a, const uint32_t* b) {
    asm volatile(
        "mma.sync.aligned.m16n8k16.row.col.f32.bf16.bf16.f32 "
        "{%0,%1,%2,%3}, {%4,%5,%6,%7}, {%8,%9}, {%0,%1,%2,%3};"
        : "+f"(c[0]), "+f"(c[1]), "+f"(c[2]), "+f"(c[3])
        : "r"(a[0]), "r"(a[1]), "r"(a[2]), "r"(a[3]), "r"(b[0]), "r"(b[1]));
}
__device__ __forceinline__ void bsplit(float v, __nv_bfloat16& h, __nv_bfloat16& l) {
    h = __float2bfloat16(v);
    l = __float2bfloat16(v - __bfloat162float(h));
}

// ===================== prep kernels =====================
__global__ void build_trig(const int* __restrict__ pos) {
    int idx = blockIdx.x * blockDim.x + threadIdx.x;
    if (idx >= S_ * 32) return;
    int s = idx >> 5, i = idx & 31;
    float p = (float)pos[s];
    float inv = 1.0f / powf(10000.0f, (float)(2 * i) * (1.0f / 64.0f));
    float a = p * inv;
    g_cos[idx] = cosf(a);
    g_sin[idx] = sinf(a);
}

__global__ void split2(const float* __restrict__ in, __nv_bfloat16* oh, __nv_bfloat16* ol, int n) {
    for (int i = blockIdx.x * blockDim.x + threadIdx.x; i < n; i += gridDim.x * blockDim.x) {
        __nv_bfloat16 h, l; bsplit(in[i], h, l); oh[i] = h; ol[i] = l;
    }
}

// out[c][r] = split(in[r][c]) for R x C, R,C mult of 32
__global__ void transpose_split(const float* __restrict__ in,
                                __nv_bfloat16* __restrict__ oh, __nv_bfloat16* __restrict__ ol,
                                int R, int C) {
    __shared__ float t[32][33];
    int bc = blockIdx.x * 32, br = blockIdx.y * 32;
    int x = threadIdx.x, y = threadIdx.y;
#pragma unroll
    for (int j = 0; j < 32; j += 8)
        t[y + j][x] = in[(size_t)(br + y + j) * C + bc + x];
    __syncthreads();
#pragma unroll
    for (int j = 0; j < 32; j += 8) {
        float v = t[x][y + j];
        __nv_bfloat16 h, l; bsplit(v, h, l);
        size_t o = (size_t)(bc + y + j) * R + br + x;
        oh[o] = h; ol[o] = l;
    }
}

__global__ void zero2(__nv_bfloat16* a, __nv_bfloat16* b, int n) {
    int i = blockIdx.x * blockDim.x + threadIdx.x;
    if (i < n) { a[i] = __float2bfloat16(0.f); b[i] = __float2bfloat16(0.f); }
}

// out[(row_off+n)*Kd + k] = split(in[k*N + n]); small weights
__global__ void tpad(const float* __restrict__ in, __nv_bfloat16* oh, __nv_bfloat16* ol,
                     int Kd, int N, int row_off) {
    int i = blockIdx.x * blockDim.x + threadIdx.x;
    if (i >= N * Kd) return;
    int n = i / Kd, k = i % Kd;
    __nv_bfloat16 h, l; bsplit(in[k * N + n], h, l);
    oh[(size_t)(row_off + n) * Kd + k] = h;
    ol[(size_t)(row_off + n) * Kd + k] = l;
}

// ===================== split-bf16 warp-MMA GEMM ==========================
// C[M,N] = (Ah+Al)[M,K] @ (Bh+Bl)[N,K]^T   (B stored transposed, K-major)
// CTA tile 128x128, KC=64, 8 warps (4x2), warp tile 32x64, mma.m16n8k16.
// 3 passes: AhBh + AhBl + AlBh (error-compensated; lo*lo dropped).
// Epilogue modes (gr = global row, gc = global col; skip gc >= Nvalid):
// 0: outf[gr*ostride+gc] = v
// 1: split -> oh/ol[gr*ostride+gc]
// 2: rope(first 64 dims per head) + split -> oh/ol  (s = gr & 2047)
// 3: gc<64 -> outf(g_qa)[gr*64+gc]; 64<=gc<192 -> g_qg[gr*128+gc-64]
// 4: g=silu(g_qg[gr*128+gc]); split(g*v) -> oh/ol[gr*128+gc]
#define STAGE_B 65536   // Ah 16K | Al 16K | Bh 16K | Bl 16K

__global__ __launch_bounds__(256) void gemm_bf16s(
    const __nv_bfloat16* __restrict__ Ah, const __nv_bfloat16* __restrict__ Al,
    const __nv_bfloat16* __restrict__ Bh, const __nv_bfloat16* __restrict__ Bl,
    int Kdim, int mode, int Nvalid, int ostride,
    float* __restrict__ outf, __nv_bfloat16* __restrict__ oh, __nv_bfloat16* __restrict__ ol)
{
    extern __shared__ __align__(128) char smem[];
    const uint32_t sb = smem_u32(smem);
    const int tid  = threadIdx.x;
    const int wid  = tid >> 5, lane = tid & 31;
    const int row0 = blockIdx.x * 128, n0 = blockIdx.y * 128;
    const int wm   = wid >> 1, wn = wid & 1;

    float acc[2][8][4];
#pragma unroll
    for (int mi = 0; mi < 2; mi++)
#pragma unroll
        for (int ni = 0; ni < 8; ni++)
#pragma unroll
            for (int j = 0; j < 4; j++) acc[mi][ni][j] = 0.f;

    const int NIT = Kdim >> 6;

    auto load_chunk = [&](int it, int s) {
        const int kc0 = it << 6;
        const uint32_t base = sb + (uint32_t)s * STAGE_B;
#pragma unroll
        for (int q = 0; q < 4; q++) {
            int g = tid + q * 256;            // 0..1023 : 128 rows x 8 granules
            int r = g >> 3, cg = g & 7;
            uint32_t sw = (uint32_t)(r * 128 + ((cg ^ (r & 7)) << 4));
            size_t ga = (size_t)(row0 + r) * Kdim + kc0 + cg * 8;
            size_t gb = (size_t)(n0   + r) * Kdim + kc0 + cg * 8;
            cpasync16(base +         sw, Ah + ga);
            cpasync16(base + 16384 + sw, Al + ga);
            cpasync16(base + 32768 + sw, Bh + gb);
            cpasync16(base + 49152 + sw, Bl + gb);
        }
        asm volatile("cp.async.commit_group;" ::: "memory");
    };

    auto compute = [&](int s) {
        const uint32_t aB = sb + (uint32_t)s * STAGE_B;
        const uint32_t bB = aB + 32768;
#pragma unroll
        for (int ks = 0; ks < 4; ks++) {
            uint32_t ahf[2][4], alf[2][4], bhf[8][2], blf[8][2];
#pragma unroll
            for (int mi = 0; mi < 2; mi++) {
                int r  = wm * 32 + mi * 16 + (lane & 15);
                int cg = ks * 2 + (lane >> 4);
                uint32_t sw = (uint32_t)(r * 128 + ((cg ^ (r & 7)) << 4));
                ldsm4(ahf[mi], aB + sw);
                ldsm4(alf[mi], aB + 16384 + sw);
            }
#pragma unroll
            for (int bi = 0; bi < 4; bi++) {
                int r  = wn * 64 + bi * 16 + (lane & 15);
                int cg = ks * 2 + (lane >> 4);
                uint32_t sw = (uint32_t)(r * 128 + ((cg ^ (r & 7)) << 4));
                uint32_t t[4];
                ldsm4(t, bB + sw);
                bhf[bi*2][0]   = t[0]; bhf[bi*2][1]   = t[2];
                bhf[bi*2+1][0] = t[1]; bhf[bi*2+1][1] = t[3];
                ldsm4(t, bB + 16384 + sw);
                blf[bi*2][0]   = t[0]; blf[bi*2][1]   = t[2];
                blf[bi*2+1][0] = t[1]; blf[bi*2+1][1] = t[3];
            }
#pragma unroll
            for (int mi = 0; mi < 2; mi++)
#pragma unroll
                for (int ni = 0; ni < 8; ni++) {
                    mma16816(acc[mi][ni], ahf[mi], bhf[ni]);
                    mma16816(acc[mi][ni], ahf[mi], blf[ni]);
                    mma16816(acc[mi][ni], alf[mi], bhf[ni]);
                }
        }
    };

    load_chunk(0, 0);
    for (int it = 0; it < NIT; ++it) {
        if (it + 1 < NIT) {
            load_chunk(it + 1, (it + 1) & 1);
            asm volatile("cp.async.wait_group 1;" ::: "memory");
        } else {
            asm volatile("cp.async.wait_group 0;" ::: "memory");
        }
        __syncthreads();
        compute(it & 1);
        __syncthreads();
    }

    // ---- stage C through smem (stride 132 floats), fused epilogue ----
    float* sC = (float*)smem;
#pragma unroll
    for (int mi = 0; mi < 2; mi++)
#pragma unroll
        for (int ni = 0; ni < 8; ni++) {
            int m0 = wm * 32 + mi * 16 + (lane >> 2);
            int c0 = wn * 64 + ni * 8 + (lane & 3) * 2;
            sC[m0 * 132 + c0]           = acc[mi][ni][0];
            sC[m0 * 132 + c0 + 1]       = acc[mi][ni][1];
            sC[(m0 + 8) * 132 + c0]     = acc[mi][ni][2];
            sC[(m0 + 8) * 132 + c0 + 1] = acc[mi][ni][3];
        }
    __syncthreads();

    for (int x = tid; x < 128 * 128; x += 256) {
        int r = x >> 7, c = x & 127;
        int gr = row0 + r, gc = n0 + c;
        if (gc >= Nvalid) continue;
        float v = sC[r * 132 + c];
        if (mode == 0) {
            outf[(size_t)gr * ostride + gc] = v;
        } else if (mode == 1) {
            __nv_bfloat16 h, l; bsplit(v, h, l);
            size_t o = (size_t)gr * ostride + gc; oh[o] = h; ol[o] = l;
        } else if (mode == 2) {
            int d = gc & 127;
            float outv = v;
            if (d < 64) {
                int i = d & 31;
                int sdx = (gr & (S_ - 1)) * 32 + i;
                float co = g_cos[sdx], si = g_sin[sdx];
                float p = (d < 32) ? sC[r * 132 + c + 32] : sC[r * 132 + c - 32];
                outv = (d < 32) ? v * co - p * si : v * co + p * si;
            }
            __nv_bfloat16 h, l; bsplit(outv, h, l);
            size_t o = (size_t)gr * ostride + gc; oh[o] = h; ol[o] = l;
        } else if (mode == 3) {
            if (gc < 64) outf[(size_t)gr * 64 + gc] = v;
            else         g_qg[(size_t)gr * 128 + (gc - 64)] = v;
        } else { // 4
            float g = g_qg[(size_t)gr * 128 + gc];
            float sil = g / (1.0f + expf(-g));
            __nv_bfloat16 h, l; bsplit(sil * v, h, l);
            size_t o = (size_t)gr * 128 + gc; oh[o] = h; ol[o] = l;
        }
    }
}

// ===================== flash attention (fp32, unchanged math) ============
#define AP 68
__global__ __launch_bounds__(256) void attn_kernel()
{
    extern __shared__ float sm[];
    float (*Qs)[AP] = (float(*)[AP])(sm);
    float (*Ks)[AP] = (float(*)[AP])(sm + 64 * AP);
    float (*Vs)[AP] = (float(*)[AP])(sm + 2 * 64 * AP);
    float (*Ps)[AP] = (float(*)[AP])(sm + 3 * 64 * AP);
    float* mrow = sm + 4 * 64 * AP;
    float* lrow = mrow + 64;
    float* arow = lrow + 64;

    const int tid = threadIdx.x;
    const int tx  = tid & 15;
    const int ty  = tid >> 4;
    const int b   = blockIdx.y >> 4;
    const int h   = blockIdx.y & 15;
    const int q0  = blockIdx.x * 64;
    const int i0  = ty * 4, j0 = tx * 4;

    for (int idx = tid; idx < 64 * 16; idx += 256) {
        const int r = idx >> 4, c4 = (idx & 15) << 2;
        *(float4*)&Qs[r][c4] =
            *(const float4*)(g_qa + ((size_t)(b * S_ + q0 + r) * NH + h) * RK + c4);
    }
    if (tid < 64) { mrow[tid] = -INFINITY; lrow[tid] = 0.f; }

    float acc[4][4];
#pragma unroll
    for (int i = 0; i < 4; i++)
#pragma unroll
        for (int j = 0; j < 4; j++) acc[i][j] = 0.f;

    for (int kt = 0; kt < S_; kt += 64) {
        __syncthreads();
        for (int idx = tid; idx < 64 * 16; idx += 256) {
            const int r = idx >> 4, c4 = (idx & 15) << 2;
            const size_t base = ((size_t)(b * S_ + kt + r) * NH + h) * RK + c4;
            *(float4*)&Ks[r][c4] = *(const float4*)(g_kc + base);
            *(float4*)&Vs[r][c4] = *(const float4*)(g_vc + base);
        }
        __syncthreads();

        float s[4][4];
#pragma unroll
        for (int i = 0; i < 4; i++)
#pragma unroll
            for (int j = 0; j < 4; j++) s[i][j] = 0.f;
#pragma unroll 4
        for (int r = 0; r < 64; r += 4) {
            float4 aa[4], bb[4];
#pragma unroll
            for (int ii = 0; ii < 4; ii++) aa[ii] = *(const float4*)&Qs[i0 + ii][r];
#pragma unroll
            for (int jj = 0; jj < 4; jj++) bb[jj] = *(const float4*)&Ks[j0 + jj][r];
#pragma unroll
            for (int ii = 0; ii < 4; ii++)
#pragma unroll
                for (int jj = 0; jj < 4; jj++)
                    s[ii][jj] += aa[ii].x * bb[jj].x + aa[ii].y * bb[jj].y
                               + aa[ii].z * bb[jj].z + aa[ii].w * bb[jj].w;
        }
#pragma unroll
        for (int ii = 0; ii < 4; ii++)
#pragma unroll
            for (int jj = 0; jj < 4; jj++)
                Ps[i0 + ii][j0 + jj] = s[ii][jj] * 0.125f;
        __syncthreads();

        if (tid < 64) {
            const int r = tid;
            float m_old = mrow[r];
            float mt = m_old;
#pragma unroll 8
            for (int j = 0; j < 64; j++) mt = fmaxf(mt, Ps[r][j]);
            const float alpha = expf(m_old - mt);
            float sum = 0.f;
#pragma unroll 8
            for (int j = 0; j < 64; j++) {
                const float p = expf(Ps[r][j] - mt);
                Ps[r][j] = p;
                sum += p;
            }
            lrow[r] = lrow[r] * alpha + sum;
            mrow[r] = mt;
            arow[r] = alpha;
        }
        __syncthreads();

        float al[4];
#pragma unroll
        for (int ii = 0; ii < 4; ii++) al[ii] = arow[i0 + ii];
#pragma unroll
        for (int ii = 0; ii < 4; ii++)
#pragma unroll
            for (int jj = 0; jj < 4; jj++) acc[ii][jj] *= al[ii];

#pragma unroll 4
        for (int r = 0; r < 64; r += 4) {
            float4 pp[4], vv[4];
#pragma unroll
            for (int ii = 0; ii < 4; ii++) pp[ii] = *(const float4*)&Ps[i0 + ii][r];
#pragma unroll
            for (int rr = 0; rr < 4; rr++) vv[rr] = *(const float4*)&Vs[r + rr][j0];
#pragma unroll
            for (int ii = 0; ii < 4; ii++) {
                acc[ii][0] += pp[ii].x*vv[0].x + pp[ii].y*vv[1].x + pp[ii].z*vv[2].x + pp[ii].w*vv[3].x;
                acc[ii][1] += pp[ii].x*vv[0].y + pp[ii].y*vv[1].y + pp[ii].z*vv[2].y + pp[ii].w*vv[3].y;
                acc[ii][2] += pp[ii].x*vv[0].z + pp[ii].y*vv[1].z + pp[ii].z*vv[2].z + pp[ii].w*vv[3].z;
                acc[ii][3] += pp[ii].x*vv[0].w + pp[ii].y*vv[1].w + pp[ii].z*vv[2].w + pp[ii].w*vv[3].w;
            }
        }
    }

#pragma unroll
    for (int ii = 0; ii < 4; ii++) {
        const float inv_l = 1.0f / lrow[i0 + ii];
        const size_t ob = ((size_t)(b * S_ + q0 + i0 + ii) * NH + h) * RK + j0;
#pragma unroll
        for (int jj = 0; jj < 4; jj++) {
            __nv_bfloat16 hh, ll; bsplit(acc[ii][jj] * inv_l, hh, ll);
            g_oc_h[ob + jj] = hh; g_oc_l[ob + jj] = ll;
        }
    }
}

// ===================== launch =====================
#define SYMF(p, s) cudaGetSymbolAddress((void**)&p, s)

extern "C" void kernel_launch(void* const* d_in, const int* in_sizes, int n_in,
                              void* d_out, int out_size)
{
    const float* hs  = (const float*)d_in[0];
    const int*   pos = (const int*)  d_in[1];
    const float* Wq  = (const float*)d_in[2];
    const float* Wk  = (const float*)d_in[3];
    const float* Wv  = (const float*)d_in[4];
    const float* Wkc = (const float*)d_in[5];
    const float* Wvc = (const float*)d_in[6];
    const float* Wqa = (const float*)d_in[7];
    const float* Wqg = (const float*)d_in[8];
    const float* Wov = (const float*)d_in[9];
    const float* Wo  = (const float*)d_in[10];
    float* out = (float*)d_out;

    __nv_bfloat16 *hsh,*hsl,*wqh,*wql,*wkh,*wkl,*wvh,*wvl,*woh,*wol;
    __nv_bfloat16 *qrh,*qrl,*krh,*krl,*vh,*vl;
    __nv_bfloat16 *cth,*ctl,*kch,*kcl,*vch,*vcl,*ovh,*ovl;
    __nv_bfloat16 *och,*ocl,*gth,*gtl;
    float *qa,*kc,*vc;
    SYMF(hsh,g_hs_h);  SYMF(hsl,g_hs_l);
    SYMF(wqh,g_WqT_h); SYMF(wql,g_WqT_l);
    SYMF(wkh,g_WkT_h); SYMF(wkl,g_WkT_l);
    SYMF(wvh,g_WvT_h); SYMF(wvl,g_WvT_l);
    SYMF(woh,g_WoT_h); SYMF(wol,g_WoT_l);
    SYMF(qrh,g_Qr_h);  SYMF(qrl,g_Qr_l);
    SYMF(krh,g_Kr_h);  SYMF(krl,g_Kr_l);
    SYMF(vh, g_V_h);   SYMF(vl, g_V_l);
    SYMF(cth,g_Wcat_h);SYMF(ctl,g_Wcat_l);
    SYMF(kch,g_WkcT_h);SYMF(kcl,g_WkcT_l);
    SYMF(vch,g_WvcT_h);SYMF(vcl,g_WvcT_l);
    SYMF(ovh,g_WovT_h);SYMF(ovl,g_WovT_l);
    SYMF(och,g_oc_h);  SYMF(ocl,g_oc_l);
    SYMF(gth,g_gat_h); SYMF(gtl,g_gat_l);
    SYMF(qa, g_qa);    SYMF(kc, g_kc);    SYMF(vc, g_vc);

    // prep
    build_trig<<<(S_*32 + 255)/256, 256>>>(pos);
    split2<<<4096, 256>>>(hs, hsh, hsl, BS_ROWS*HID);
    transpose_split<<<dim3(64,64), dim3(32,8)>>>(Wq, wqh, wql, HID, HID);
    transpose_split<<<dim3(64,64), dim3(32,8)>>>(Wk, wkh, wkl, HID, HID);
    transpose_split<<<dim3(64,64), dim3(32,8)>>>(Wv, wvh, wvl, HID, HID);
    transpose_split<<<dim3(64,64), dim3(32,8)>>>(Wo, woh, wol, HID, HID);
    zero2<<<(256*HD+255)/256, 256>>>(cth, ctl, 256*HD);
    zero2<<<(256*HD+255)/256, 256>>>(kch, kcl, 256*HD);
    zero2<<<(256*HD+255)/256, 256>>>(vch, vcl, 256*HD);
    zero2<<<(256*RK+255)/256, 256>>>(ovh, ovl, 256*RK);
    tpad<<<(64*128+255)/256, 256>>>(Wqa, cth, ctl, 128, 64, 0);
    tpad<<<(128*128+255)/256, 256>>>(Wqg, cth, ctl, 128, 128, 64);
    tpad<<<(64*128+255)/256, 256>>>(Wkc, kch, kcl, 128, 64, 0);
    tpad<<<(64*128+255)/256, 256>>>(Wvc, vch, vcl, 128, 64, 0);
    tpad<<<(128*64+255)/256, 256>>>(Wov, ovh, ovl, 64, 128, 0);

    const int gsmem = 2 * STAGE_B;   // 128 KB (epilogue reuses 67.6 KB of it)
    cudaFuncSetAttribute(gemm_bf16s, cudaFuncAttributeMaxDynamicSharedMemorySize, gsmem);

    // Q/K/V projections (rope+split fused for Q,K; split for V)
    gemm_bf16s<<<dim3(32,16), 256, gsmem>>>(hsh, hsl, wqh, wql, HID, 2, HID, HID,
                                            nullptr, qrh, qrl);
    gemm_bf16s<<<dim3(32,16), 256, gsmem>>>(hsh, hsl, wkh, wkl, HID, 2, HID, HID,
                                            nullptr, krh, krl);
    gemm_bf16s<<<dim3(32,16), 256, gsmem>>>(hsh, hsl, wvh, wvl, HID, 1, HID, HID,
                                            nullptr, vh, vl);
    // head projections: qa|qg, kc, vc  (A viewed as [65536 x 128])
    gemm_bf16s<<<dim3(512,2), 256, gsmem>>>(qrh, qrl, cth, ctl, 128, 3, 192, 0,
                                            qa, nullptr, nullptr);
    gemm_bf16s<<<dim3(512,1), 256, gsmem>>>(krh, krl, kch, kcl, 128, 0, 64, 64,
                                            kc, nullptr, nullptr);
    gemm_bf16s<<<dim3(512,1), 256, gsmem>>>(vh, vl, vch, vcl, 128, 0, 64, 64,
                                            vc, nullptr, nullptr);
    // attention
    const int att_smem = (4 * 64 * AP + 192) * (int)sizeof(float);
    cudaFuncSetAttribute(attn_kernel,
                         cudaFuncAttributeMaxDynamicSharedMemorySize, att_smem);
    attn_kernel<<<dim3(S_/64, B_*NH), 256, att_smem>>>();
    // uplift + gate (writes gated split)
    gemm_bf16s<<<dim3(512,1), 256, gsmem>>>(och, ocl, ovh, ovl, 64, 4, 128, 128,
                                            nullptr, gth, gtl);
    // final projection
    gemm_bf16s<<<dim3(32,16), 256, gsmem>>>(gth, gtl, woh, wol, HID, 0, HID, HID,
                                            out, nullptr, nullptr);
}

// round 9
// speedup vs baseline: 2.5978x; 1.5427x over previous
#include <cuda_runtime.h>
#include <cuda_bf16.h>
#include <math.h>
#include <stdint.h>

#define B_   2
#define S_   2048
#define HID  2048
#define NH   16
#define HD   128
#define RK   64
#define BS_ROWS (B_*S_)        // 4096
#define HROWS   (B_*S_*NH)     // 65536

// ===================== scratch (static __device__) =====================
__device__ __nv_bfloat16 g_hs_h[BS_ROWS*HID],  g_hs_l[BS_ROWS*HID];
__device__ __nv_bfloat16 g_WqT_h[HID*HID], g_WqT_l[HID*HID];
__device__ __nv_bfloat16 g_WkT_h[HID*HID], g_WkT_l[HID*HID];
__device__ __nv_bfloat16 g_WvT_h[HID*HID], g_WvT_l[HID*HID];
__device__ __nv_bfloat16 g_WoT_h[HID*HID], g_WoT_l[HID*HID];
__device__ __nv_bfloat16 g_Qr_h[BS_ROWS*HID], g_Qr_l[BS_ROWS*HID];
__device__ __nv_bfloat16 g_Kr_h[BS_ROWS*HID], g_Kr_l[BS_ROWS*HID];
__device__ __nv_bfloat16 g_V_h [BS_ROWS*HID], g_V_l [BS_ROWS*HID];
__device__ __nv_bfloat16 g_Wcat_h[256*HD], g_Wcat_l[256*HD];   // [Wqa|Wqg]^T padded
__device__ __nv_bfloat16 g_WkcT_h[256*HD], g_WkcT_l[256*HD];
__device__ __nv_bfloat16 g_WvcT_h[256*HD], g_WvcT_l[256*HD];
__device__ __nv_bfloat16 g_WovT_h[256*RK], g_WovT_l[256*RK];
__device__ __nv_bfloat16 g_qa_h[HROWS*RK], g_qa_l[HROWS*RK];   // pre-scaled 1/8
__device__ __nv_bfloat16 g_kc_h[HROWS*RK], g_kc_l[HROWS*RK];
__device__ __nv_bfloat16 g_vc_h[HROWS*RK], g_vc_l[HROWS*RK];
__device__ float g_qg[HROWS*HD];
__device__ __nv_bfloat16 g_oc_h[HROWS*RK], g_oc_l[HROWS*RK];
__device__ __nv_bfloat16 g_gat_h[BS_ROWS*HID], g_gat_l[BS_ROWS*HID];
__device__ float g_cos[S_*32], g_sin[S_*32];

// ===================== PTX helpers (sm_80-era only; sm_100 base target) ====
__device__ __forceinline__ uint32_t smem_u32(const void* p) {
    uint32_t a;
    asm("{ .reg .u64 t; cvta.to.shared.u64 t, %1; cvt.u32.u64 %0, t; }" : "=r"(a) : "l"(p));
    return a;
}
__device__ __forceinline__ void cpasync16(uint32_t dst, const void* src) {
    asm volatile("cp.async.cg.shared.global [%0], [%1], 16;" :: "r"(dst), "l"(src));
}
__device__ __forceinline__ void ldsm4(uint32_t* r, uint32_t addr) {
    asm volatile("ldmatrix.sync.aligned.m8n8.x4.shared.b16 {%0,%1,%2,%3}, [%4];"
        : "=r"(r[0]), "=r"(r[1]), "=r"(r[2]), "=r"(r[3]) : "r"(addr));
}
__device__ __forceinline__ void ldsm4t(uint32_t* r, uint32_t addr) {
    asm volatile("ldmatrix.sync.aligned.m8n8.x4.trans.shared.b16 {%0,%1,%2,%3}, [%4];"
        : "=r"(r[0]), "=r"(r[1]), "=r"(r[2]), "=r"(r[3]) : "r"(addr));
}
__device__ __forceinline__ void mma16816(float* c, const uint32_t* a, const uint32_t* b) {
    asm volatile(
        "mma.sync.aligned.m16n8k16.row.col.f32.bf16.bf16.f32 "
        "{%0,%1,%2,%3}, {%4,%5,%6,%7}, {%8,%9}, {%0,%1,%2,%3};"
        : "+f"(c[0]), "+f"(c[1]), "+f"(c[2]), "+f"(c[3])
        : "r"(a[0]), "r"(a[1]), "r"(a[2]), "r"(a[3]), "r"(b[0]), "r"(b[1]));
}
__device__ __forceinline__ void bsplit(float v, __nv_bfloat16& h, __nv_bfloat16& l) {
    h = __float2bfloat16(v);
    l = __float2bfloat16(v - __bfloat162float(h));
}
// pack two floats into bf16x2 hi-reg + residual lo-reg
__device__ __forceinline__ void packsplit(float lo, float hi, uint32_t& ph, uint32_t& pl) {
    __nv_bfloat16 hl = __float2bfloat16(lo), hh = __float2bfloat16(hi);
    ph = (uint32_t)__bfloat16_as_ushort(hl) | ((uint32_t)__bfloat16_as_ushort(hh) << 16);
    __nv_bfloat16 ll = __float2bfloat16(lo - __bfloat162float(hl));
    __nv_bfloat16 lh = __float2bfloat16(hi - __bfloat162float(hh));
    pl = (uint32_t)__bfloat16_as_ushort(ll) | ((uint32_t)__bfloat16_as_ushort(lh) << 16);
}

// ===================== prep kernels =====================
__global__ void build_trig(const int* __restrict__ pos) {
    int idx = blockIdx.x * blockDim.x + threadIdx.x;
    if (idx >= S_ * 32) return;
    int s = idx >> 5, i = idx & 31;
    float p = (float)pos[s];
    float inv = 1.0f / powf(10000.0f, (float)(2 * i) * (1.0f / 64.0f));
    float a = p * inv;
    g_cos[idx] = cosf(a);
    g_sin[idx] = sinf(a);
}

__global__ void split2(const float* __restrict__ in, __nv_bfloat16* oh, __nv_bfloat16* ol, int n) {
    for (int i = blockIdx.x * blockDim.x + threadIdx.x; i < n; i += gridDim.x * blockDim.x) {
        __nv_bfloat16 h, l; bsplit(in[i], h, l); oh[i] = h; ol[i] = l;
    }
}

// out[c][r] = split(in[r][c]) for R x C, R,C mult of 32
__global__ void transpose_split(const float* __restrict__ in,
                                __nv_bfloat16* __restrict__ oh, __nv_bfloat16* __restrict__ ol,
                                int R, int C) {
    __shared__ float t[32][33];
    int bc = blockIdx.x * 32, br = blockIdx.y * 32;
    int x = threadIdx.x, y = threadIdx.y;
#pragma unroll
    for (int j = 0; j < 32; j += 8)
        t[y + j][x] = in[(size_t)(br + y + j) * C + bc + x];
    __syncthreads();
#pragma unroll
    for (int j = 0; j < 32; j += 8) {
        float v = t[x][y + j];
        __nv_bfloat16 h, l; bsplit(v, h, l);
        size_t o = (size_t)(bc + y + j) * R + br + x;
        oh[o] = h; ol[o] = l;
    }
}

__global__ void zero2(__nv_bfloat16* a, __nv_bfloat16* b, int n) {
    int i = blockIdx.x * blockDim.x + threadIdx.x;
    if (i < n) { a[i] = __float2bfloat16(0.f); b[i] = __float2bfloat16(0.f); }
}

// out[(row_off+n)*Kd + k] = split(in[k*N + n]); small weights
__global__ void tpad(const float* __restrict__ in, __nv_bfloat16* oh, __nv_bfloat16* ol,
                     int Kd, int N, int row_off) {
    int i = blockIdx.x * blockDim.x + threadIdx.x;
    if (i >= N * Kd) return;
    int n = i / Kd, k = i % Kd;
    __nv_bfloat16 h, l; bsplit(in[k * N + n], h, l);
    oh[(size_t)(row_off + n) * Kd + k] = h;
    ol[(size_t)(row_off + n) * Kd + k] = l;
}

// ===================== split-bf16 warp-MMA GEMM ==========================
// C[M,N] = (Ah+Al)[M,K] @ (Bh+Bl)[N,K]^T   (B stored transposed, K-major)
// CTA tile 128x128, KC=64, 8 warps (4x2), warp tile 32x64, mma.m16n8k16.
// 3 passes: AhBh + AhBl + AlBh.
// Modes: 0 outf; 1 split->oh/ol; 2 rope+split->oh/ol;
//        3 gc<64: split(v*0.125)->oh/ol (stride 64), else g_qg fp32;
//        4 silu(g_qg)*v -> split oh/ol (stride 128)
#define STAGE_B 65536   // Ah 16K | Al 16K | Bh 16K | Bl 16K

__global__ __launch_bounds__(256) void gemm_bf16s(
    const __nv_bfloat16* __restrict__ Ah, const __nv_bfloat16* __restrict__ Al,
    const __nv_bfloat16* __restrict__ Bh, const __nv_bfloat16* __restrict__ Bl,
    int Kdim, int mode, int Nvalid, int ostride,
    float* __restrict__ outf, __nv_bfloat16* __restrict__ oh, __nv_bfloat16* __restrict__ ol)
{
    extern __shared__ __align__(128) char smem[];
    const uint32_t sb = smem_u32(smem);
    const int tid  = threadIdx.x;
    const int wid  = tid >> 5, lane = tid & 31;
    const int row0 = blockIdx.x * 128, n0 = blockIdx.y * 128;
    const int wm   = wid >> 1, wn = wid & 1;

    float acc[2][8][4];
#pragma unroll
    for (int mi = 0; mi < 2; mi++)
#pragma unroll
        for (int ni = 0; ni < 8; ni++)
#pragma unroll
            for (int j = 0; j < 4; j++) acc[mi][ni][j] = 0.f;

    const int NIT = Kdim >> 6;

    auto load_chunk = [&](int it, int s) {
        const int kc0 = it << 6;
        const uint32_t base = sb + (uint32_t)s * STAGE_B;
#pragma unroll
        for (int q = 0; q < 4; q++) {
            int g = tid + q * 256;
            int r = g >> 3, cg = g & 7;
            uint32_t sw = (uint32_t)(r * 128 + ((cg ^ (r & 7)) << 4));
            size_t ga = (size_t)(row0 + r) * Kdim + kc0 + cg * 8;
            size_t gb = (size_t)(n0   + r) * Kdim + kc0 + cg * 8;
            cpasync16(base +         sw, Ah + ga);
            cpasync16(base + 16384 + sw, Al + ga);
            cpasync16(base + 32768 + sw, Bh + gb);
            cpasync16(base + 49152 + sw, Bl + gb);
        }
        asm volatile("cp.async.commit_group;" ::: "memory");
    };

    auto compute = [&](int s) {
        const uint32_t aB = sb + (uint32_t)s * STAGE_B;
        const uint32_t bB = aB + 32768;
#pragma unroll
        for (int ks = 0; ks < 4; ks++) {
            uint32_t ahf[2][4], alf[2][4], bhf[8][2], blf[8][2];
#pragma unroll
            for (int mi = 0; mi < 2; mi++) {
                int r  = wm * 32 + mi * 16 + (lane & 15);
                int cg = ks * 2 + (lane >> 4);
                uint32_t sw = (uint32_t)(r * 128 + ((cg ^ (r & 7)) << 4));
                ldsm4(ahf[mi], aB + sw);
                ldsm4(alf[mi], aB + 16384 + sw);
            }
#pragma unroll
            for (int bi = 0; bi < 4; bi++) {
                int r  = wn * 64 + bi * 16 + (lane & 15);
                int cg = ks * 2 + (lane >> 4);
                uint32_t sw = (uint32_t)(r * 128 + ((cg ^ (r & 7)) << 4));
                uint32_t t[4];
                ldsm4(t, bB + sw);
                bhf[bi*2][0]   = t[0]; bhf[bi*2][1]   = t[2];
                bhf[bi*2+1][0] = t[1]; bhf[bi*2+1][1] = t[3];
                ldsm4(t, bB + 16384 + sw);
                blf[bi*2][0]   = t[0]; blf[bi*2][1]   = t[2];
                blf[bi*2+1][0] = t[1]; blf[bi*2+1][1] = t[3];
            }
#pragma unroll
            for (int mi = 0; mi < 2; mi++)
#pragma unroll
                for (int ni = 0; ni < 8; ni++) {
                    mma16816(acc[mi][ni], ahf[mi], bhf[ni]);
                    mma16816(acc[mi][ni], ahf[mi], blf[ni]);
                    mma16816(acc[mi][ni], alf[mi], bhf[ni]);
                }
        }
    };

    load_chunk(0, 0);
    for (int it = 0; it < NIT; ++it) {
        if (it + 1 < NIT) {
            load_chunk(it + 1, (it + 1) & 1);
            asm volatile("cp.async.wait_group 1;" ::: "memory");
        } else {
            asm volatile("cp.async.wait_group 0;" ::: "memory");
        }
        __syncthreads();
        compute(it & 1);
        __syncthreads();
    }

    // ---- stage C through smem, fused epilogue ----
    float* sC = (float*)smem;
#pragma unroll
    for (int mi = 0; mi < 2; mi++)
#pragma unroll
        for (int ni = 0; ni < 8; ni++) {
            int m0 = wm * 32 + mi * 16 + (lane >> 2);
            int c0 = wn * 64 + ni * 8 + (lane & 3) * 2;
            sC[m0 * 132 + c0]           = acc[mi][ni][0];
            sC[m0 * 132 + c0 + 1]       = acc[mi][ni][1];
            sC[(m0 + 8) * 132 + c0]     = acc[mi][ni][2];
            sC[(m0 + 8) * 132 + c0 + 1] = acc[mi][ni][3];
        }
    __syncthreads();

    for (int x = tid; x < 128 * 128; x += 256) {
        int r = x >> 7, c = x & 127;
        int gr = row0 + r, gc = n0 + c;
        if (gc >= Nvalid) continue;
        float v = sC[r * 132 + c];
        if (mode == 0) {
            outf[(size_t)gr * ostride + gc] = v;
        } else if (mode == 1) {
            __nv_bfloat16 h, l; bsplit(v, h, l);
            size_t o = (size_t)gr * ostride + gc; oh[o] = h; ol[o] = l;
        } else if (mode == 2) {
            int d = gc & 127;
            float outv = v;
            if (d < 64) {
                int i = d & 31;
                int sdx = (gr & (S_ - 1)) * 32 + i;
                float co = g_cos[sdx], si = g_sin[sdx];
                float p = (d < 32) ? sC[r * 132 + c + 32] : sC[r * 132 + c - 32];
                outv = (d < 32) ? v * co - p * si : v * co + p * si;
            }
            __nv_bfloat16 h, l; bsplit(outv, h, l);
            size_t o = (size_t)gr * ostride + gc; oh[o] = h; ol[o] = l;
        } else if (mode == 3) {
            if (gc < 64) {
                __nv_bfloat16 h, l; bsplit(v * 0.125f, h, l);
                size_t o = (size_t)gr * 64 + gc; oh[o] = h; ol[o] = l;
            } else g_qg[(size_t)gr * 128 + (gc - 64)] = v;
        } else { // 4
            float g = g_qg[(size_t)gr * 128 + gc];
            float sil = g / (1.0f + expf(-g));
            __nv_bfloat16 h, l; bsplit(sil * v, h, l);
            size_t o = (size_t)gr * 128 + gc; oh[o] = h; ol[o] = l;
        }
    }
}

// ===================== tensor-core flash attention ========================
// grid (S/128, B*NH), 256 thr. Warp w owns q rows [q0+16w, q0+16w+16).
// K-tiles of 64 keys, cp.async double buffered. Split-bf16 3-pass on both
// QK^T and P*V. P stays in registers (S C-frag == PV A-frag layout).
// smem: Qh 0 | Ql 16K | stage s at 32768+s*32768: Kh,Kl,Vh,Vl (8K each)
#define ATT_SMEM 98304

__global__ __launch_bounds__(256) void attn_mma()
{
    extern __shared__ __align__(128) char smem[];
    const uint32_t sb = smem_u32(smem);
    const int tid = threadIdx.x, wid = tid >> 5, lane = tid & 31;
    const int b = blockIdx.y >> 4, h = blockIdx.y & 15;
    const int q0 = blockIdx.x * 128;

    // Q load (grouped with first K/V tile)
    for (int i = tid; i < 1024; i += 256) {
        int r = i >> 3, g = i & 7;
        uint32_t sw = (uint32_t)(r * 128 + ((g ^ (r & 7)) << 4));
        size_t gl = ((size_t)((b * S_ + q0 + r) * NH + h)) * RK + g * 8;
        cpasync16(sb + sw,         g_qa_h + gl);
        cpasync16(sb + 16384 + sw, g_qa_l + gl);
    }
    auto load_kv = [&](int t, int s) {
        const uint32_t kb = sb + 32768 + (uint32_t)s * 32768;
        for (int i = tid; i < 512; i += 256) {
            int r = i >> 3, g = i & 7;
            uint32_t sw = (uint32_t)(r * 128 + ((g ^ (r & 7)) << 4));
            size_t gl = ((size_t)((b * S_ + t * 64 + r) * NH + h)) * RK + g * 8;
            cpasync16(kb + sw,         g_kc_h + gl);
            cpasync16(kb + 8192 + sw,  g_kc_l + gl);
            cpasync16(kb + 16384 + sw, g_vc_h + gl);
            cpasync16(kb + 24576 + sw, g_vc_l + gl);
        }
    };
    load_kv(0, 0);
    asm volatile("cp.async.commit_group;" ::: "memory");

    float m1 = -INFINITY, m2 = -INFINITY, l1 = 0.f, l2 = 0.f;
    float ao[8][4];
#pragma unroll
    for (int nf = 0; nf < 8; nf++)
#pragma unroll
        for (int j = 0; j < 4; j++) ao[nf][j] = 0.f;
    uint32_t qh[4][4], qlo[4][4];
    int qloaded = 0;

    for (int t = 0; t < 32; ++t) {
        if (t + 1 < 32) {
            load_kv(t + 1, (t + 1) & 1);
            asm volatile("cp.async.commit_group;" ::: "memory");
            asm volatile("cp.async.wait_group 1;" ::: "memory");
        } else {
            asm volatile("cp.async.wait_group 0;" ::: "memory");
        }
        __syncthreads();
        if (!qloaded) {
            qloaded = 1;
#pragma unroll
            for (int kc = 0; kc < 4; kc++) {
                int r = wid * 16 + (lane & 15), cg = kc * 2 + (lane >> 4);
                uint32_t sw = (uint32_t)(r * 128 + ((cg ^ (r & 7)) << 4));
                ldsm4(qh[kc],  sb + sw);
                ldsm4(qlo[kc], sb + 16384 + sw);
            }
        }
        const uint32_t kb = sb + 32768 + (uint32_t)(t & 1) * 32768;

        // ---- S = Q K^T (128 x 64 tile; this warp: 16 x 64) ----
        float sa[8][4];
#pragma unroll
        for (int ni = 0; ni < 8; ni++)
#pragma unroll
            for (int j = 0; j < 4; j++) sa[ni][j] = 0.f;
#pragma unroll
        for (int kc = 0; kc < 4; kc++) {
            uint32_t kh[8][2], kl[8][2];
#pragma unroll
            for (int bi = 0; bi < 4; bi++) {
                int r = bi * 16 + (lane & 15), cg = kc * 2 + (lane >> 4);
                uint32_t sw = (uint32_t)(r * 128 + ((cg ^ (r & 7)) << 4));
                uint32_t t4[4];
                ldsm4(t4, kb + sw);
                kh[bi*2][0]=t4[0]; kh[bi*2][1]=t4[2]; kh[bi*2+1][0]=t4[1]; kh[bi*2+1][1]=t4[3];
                ldsm4(t4, kb + 8192 + sw);
                kl[bi*2][0]=t4[0]; kl[bi*2][1]=t4[2]; kl[bi*2+1][0]=t4[1]; kl[bi*2+1][1]=t4[3];
            }
#pragma unroll
            for (int ni = 0; ni < 8; ni++) {
                mma16816(sa[ni], qh[kc],  kh[ni]);
                mma16816(sa[ni], qh[kc],  kl[ni]);
                mma16816(sa[ni], qlo[kc], kh[ni]);
            }
        }

        // ---- online softmax (rows r1=16w+(lane>>2), r2=r1+8) ----
        float mx1 = -INFINITY, mx2 = -INFINITY;
#pragma unroll
        for (int ni = 0; ni < 8; ni++) {
            mx1 = fmaxf(mx1, fmaxf(sa[ni][0], sa[ni][1]));
            mx2 = fmaxf(mx2, fmaxf(sa[ni][2], sa[ni][3]));
        }
        mx1 = fmaxf(mx1, __shfl_xor_sync(0xffffffffu, mx1, 1));
        mx1 = fmaxf(mx1, __shfl_xor_sync(0xffffffffu, mx1, 2));
        mx2 = fmaxf(mx2, __shfl_xor_sync(0xffffffffu, mx2, 1));
        mx2 = fmaxf(mx2, __shfl_xor_sync(0xffffffffu, mx2, 2));
        float nm1 = fmaxf(m1, mx1), nm2 = fmaxf(m2, mx2);
        float al1 = __expf(m1 - nm1), al2 = __expf(m2 - nm2);
        float s1 = 0.f, s2 = 0.f;
#pragma unroll
        for (int ni = 0; ni < 8; ni++) {
            sa[ni][0] = __expf(sa[ni][0] - nm1); s1 += sa[ni][0];
            sa[ni][1] = __expf(sa[ni][1] - nm1); s1 += sa[ni][1];
            sa[ni][2] = __expf(sa[ni][2] - nm2); s2 += sa[ni][2];
            sa[ni][3] = __expf(sa[ni][3] - nm2); s2 += sa[ni][3];
        }
        s1 += __shfl_xor_sync(0xffffffffu, s1, 1);
        s1 += __shfl_xor_sync(0xffffffffu, s1, 2);
        s2 += __shfl_xor_sync(0xffffffffu, s2, 1);
        s2 += __shfl_xor_sync(0xffffffffu, s2, 2);
        l1 = l1 * al1 + s1; l2 = l2 * al2 + s2;
        m1 = nm1; m2 = nm2;
#pragma unroll
        for (int nf = 0; nf < 8; nf++) {
            ao[nf][0] *= al1; ao[nf][1] *= al1;
            ao[nf][2] *= al2; ao[nf][3] *= al2;
        }

        // ---- O += P V  (P from regs; V B-frags via ldsm.trans) ----
#pragma unroll
        for (int j = 0; j < 4; j++) {
            uint32_t ph[4], pl[4];
            packsplit(sa[2*j][0],   sa[2*j][1],   ph[0], pl[0]);
            packsplit(sa[2*j][2],   sa[2*j][3],   ph[1], pl[1]);
            packsplit(sa[2*j+1][0], sa[2*j+1][1], ph[2], pl[2]);
            packsplit(sa[2*j+1][2], sa[2*j+1][3], ph[3], pl[3]);
            uint32_t vh[8][2], vl[8][2];
#pragma unroll
            for (int q = 0; q < 4; q++) {
                int row = j * 16 + ((lane >> 3) & 1) * 8 + (lane & 7);
                int g   = q * 2 + (lane >> 4);
                uint32_t sw = (uint32_t)(row * 128 + ((g ^ (row & 7)) << 4));
                uint32_t t4[4];
                ldsm4t(t4, kb + 16384 + sw);
                vh[q*2][0]=t4[0]; vh[q*2][1]=t4[1]; vh[q*2+1][0]=t4[2]; vh[q*2+1][1]=t4[3];
                ldsm4t(t4, kb + 24576 + sw);
                vl[q*2][0]=t4[0]; vl[q*2][1]=t4[1]; vl[q*2+1][0]=t4[2]; vl[q*2+1][1]=t4[3];
            }
#pragma unroll
            for (int nf = 0; nf < 8; nf++) {
                mma16816(ao[nf], ph, vh[nf]);
                mma16816(ao[nf], pl, vh[nf]);
                mma16816(ao[nf], ph, vl[nf]);
            }
        }
        __syncthreads();
    }

    // ---- epilogue: split out_c ----
    float il1 = 1.f / l1, il2 = 1.f / l2;
    int r1 = q0 + wid * 16 + (lane >> 2);
    int cb = 2 * (lane & 3);
    size_t b1 = ((size_t)((b * S_ + r1) * NH + h)) * RK;
    size_t b2 = ((size_t)((b * S_ + r1 + 8) * NH + h)) * RK;
#pragma unroll
    for (int nf = 0; nf < 8; nf++) {
        int c = nf * 8 + cb;
        __nv_bfloat16 hh, ll;
        bsplit(ao[nf][0] * il1, hh, ll); g_oc_h[b1 + c]     = hh; g_oc_l[b1 + c]     = ll;
        bsplit(ao[nf][1] * il1, hh, ll); g_oc_h[b1 + c + 1] = hh; g_oc_l[b1 + c + 1] = ll;
        bsplit(ao[nf][2] * il2, hh, ll); g_oc_h[b2 + c]     = hh; g_oc_l[b2 + c]     = ll;
        bsplit(ao[nf][3] * il2, hh, ll); g_oc_h[b2 + c + 1] = hh; g_oc_l[b2 + c + 1] = ll;
    }
}

// ===================== launch =====================
#define SYMF(p, s) cudaGetSymbolAddress((void**)&p, s)

extern "C" void kernel_launch(void* const* d_in, const int* in_sizes, int n_in,
                              void* d_out, int out_size)
{
    const float* hs  = (const float*)d_in[0];
    const int*   pos = (const int*)  d_in[1];
    const float* Wq  = (const float*)d_in[2];
    const float* Wk  = (const float*)d_in[3];
    const float* Wv  = (const float*)d_in[4];
    const float* Wkc = (const float*)d_in[5];
    const float* Wvc = (const float*)d_in[6];
    const float* Wqa = (const float*)d_in[7];
    const float* Wqg = (const float*)d_in[8];
    const float* Wov = (const float*)d_in[9];
    const float* Wo  = (const float*)d_in[10];
    float* out = (float*)d_out;

    __nv_bfloat16 *hsh,*hsl,*wqh,*wql,*wkh,*wkl,*wvh,*wvl,*woh,*wol;
    __nv_bfloat16 *qrh,*qrl,*krh,*krl,*vh,*vl;
    __nv_bfloat16 *cth,*ctl,*kch,*kcl,*vch,*vcl,*ovh,*ovl;
    __nv_bfloat16 *och,*ocl,*gth,*gtl;
    __nv_bfloat16 *qah,*qal,*kkh,*kkl,*vvh,*vvl;
    SYMF(hsh,g_hs_h);  SYMF(hsl,g_hs_l);
    SYMF(wqh,g_WqT_h); SYMF(wql,g_WqT_l);
    SYMF(wkh,g_WkT_h); SYMF(wkl,g_WkT_l);
    SYMF(wvh,g_WvT_h); SYMF(wvl,g_WvT_l);
    SYMF(woh,g_WoT_h); SYMF(wol,g_WoT_l);
    SYMF(qrh,g_Qr_h);  SYMF(qrl,g_Qr_l);
    SYMF(krh,g_Kr_h);  SYMF(krl,g_Kr_l);
    SYMF(vh, g_V_h);   SYMF(vl, g_V_l);
    SYMF(cth,g_Wcat_h);SYMF(ctl,g_Wcat_l);
    SYMF(kch,g_WkcT_h);SYMF(kcl,g_WkcT_l);
    SYMF(vch,g_WvcT_h);SYMF(vcl,g_WvcT_l);
    SYMF(ovh,g_WovT_h);SYMF(ovl,g_WovT_l);
    SYMF(och,g_oc_h);  SYMF(ocl,g_oc_l);
    SYMF(gth,g_gat_h); SYMF(gtl,g_gat_l);
    SYMF(qah,g_qa_h);  SYMF(qal,g_qa_l);
    SYMF(kkh,g_kc_h);  SYMF(kkl,g_kc_l);
    SYMF(vvh,g_vc_h);  SYMF(vvl,g_vc_l);

    // prep
    build_trig<<<(S_*32 + 255)/256, 256>>>(pos);
    split2<<<4096, 256>>>(hs, hsh, hsl, BS_ROWS*HID);
    transpose_split<<<dim3(64,64), dim3(32,8)>>>(Wq, wqh, wql, HID, HID);
    transpose_split<<<dim3(64,64), dim3(32,8)>>>(Wk, wkh, wkl, HID, HID);
    transpose_split<<<dim3(64,64), dim3(32,8)>>>(Wv, wvh, wvl, HID, HID);
    transpose_split<<<dim3(64,64), dim3(32,8)>>>(Wo, woh, wol, HID, HID);
    zero2<<<(256*HD+255)/256, 256>>>(cth, ctl, 256*HD);
    zero2<<<(256*HD+255)/256, 256>>>(kch, kcl, 256*HD);
    zero2<<<(256*HD+255)/256, 256>>>(vch, vcl, 256*HD);
    zero2<<<(256*RK+255)/256, 256>>>(ovh, ovl, 256*RK);
    tpad<<<(64*128+255)/256, 256>>>(Wqa, cth, ctl, 128, 64, 0);
    tpad<<<(128*128+255)/256, 256>>>(Wqg, cth, ctl, 128, 128, 64);
    tpad<<<(64*128+255)/256, 256>>>(Wkc, kch, kcl, 128, 64, 0);
    tpad<<<(64*128+255)/256, 256>>>(Wvc, vch, vcl, 128, 64, 0);
    tpad<<<(128*64+255)/256, 256>>>(Wov, ovh, ovl, 64, 128, 0);

    const int gsmem = 2 * STAGE_B;
    cudaFuncSetAttribute(gemm_bf16s, cudaFuncAttributeMaxDynamicSharedMemorySize, gsmem);

    // Q/K/V projections
    gemm_bf16s<<<dim3(32,16), 256, gsmem>>>(hsh, hsl, wqh, wql, HID, 2, HID, HID,
                                            nullptr, qrh, qrl);
    gemm_bf16s<<<dim3(32,16), 256, gsmem>>>(hsh, hsl, wkh, wkl, HID, 2, HID, HID,
                                            nullptr, krh, krl);
    gemm_bf16s<<<dim3(32,16), 256, gsmem>>>(hsh, hsl, wvh, wvl, HID, 1, HID, HID,
                                            nullptr, vh, vl);
    // head projections: qa|qg (qa split+scaled), kc split, vc split
    gemm_bf16s<<<dim3(512,2), 256, gsmem>>>(qrh, qrl, cth, ctl, 128, 3, 192, 64,
                                            nullptr, qah, qal);
    gemm_bf16s<<<dim3(512,1), 256, gsmem>>>(krh, krl, kch, kcl, 128, 1, 64, 64,
                                            nullptr, kkh, kkl);
    gemm_bf16s<<<dim3(512,1), 256, gsmem>>>(vh, vl, vch, vcl, 128, 1, 64, 64,
                                            nullptr, vvh, vvl);
    // attention (tensor cores)
    cudaFuncSetAttribute(attn_mma, cudaFuncAttributeMaxDynamicSharedMemorySize, ATT_SMEM);
    attn_mma<<<dim3(S_/128, B_*NH), 256, ATT_SMEM>>>();
    // uplift + gate
    gemm_bf16s<<<dim3(512,1), 256, gsmem>>>(och, ocl, ovh, ovl, 64, 4, 128, 128,
                                            nullptr, gth, gtl);
    // final projection
    gemm_bf16s<<<dim3(32,16), 256, gsmem>>>(gth, gtl, woh, wol, HID, 0, HID, HID,
                                            out, nullptr, nullptr);
}

// round 10
// speedup vs baseline: 2.9233x; 1.1253x over previous
#include <cuda_runtime.h>
#include <cuda_bf16.h>
#include <math.h>
#include <stdint.h>

#define B_   2
#define S_   2048
#define HID  2048
#define NH   16
#define HD   128
#define RK   64
#define BS_ROWS (B_*S_)        // 4096
#define HROWS   (B_*S_*NH)     // 65536

// ===================== scratch (static __device__) =====================
__device__ __nv_bfloat16 g_hs_h[BS_ROWS*HID],  g_hs_l[BS_ROWS*HID];
__device__ __nv_bfloat16 g_WqT_h[HID*HID], g_WqT_l[HID*HID];
__device__ __nv_bfloat16 g_WkT_h[HID*HID], g_WkT_l[HID*HID];
__device__ __nv_bfloat16 g_WoT_h[HID*HID], g_WoT_l[HID*HID];
__device__ __nv_bfloat16 g_MvT_h[1024*HID], g_MvT_l[1024*HID];   // folded (Wv·Wvc)^T
__device__ __nv_bfloat16 g_Qr_h[BS_ROWS*HID], g_Qr_l[BS_ROWS*HID];
__device__ __nv_bfloat16 g_Kr_h[BS_ROWS*HID], g_Kr_l[BS_ROWS*HID];
__device__ __nv_bfloat16 g_Wcat_h[256*HD], g_Wcat_l[256*HD];   // [Wqa|Wqg]^T padded
__device__ __nv_bfloat16 g_WkcT_h[256*HD], g_WkcT_l[256*HD];
__device__ __nv_bfloat16 g_WovT_h[256*RK], g_WovT_l[256*RK];
__device__ __nv_bfloat16 g_qa_h[HROWS*RK], g_qa_l[HROWS*RK];   // pre-scaled 1/8
__device__ __nv_bfloat16 g_kc_h[HROWS*RK], g_kc_l[HROWS*RK];
__device__ __nv_bfloat16 g_vc_h[HROWS*RK], g_vc_l[HROWS*RK];
__device__ float g_qg[HROWS*HD];
__device__ __nv_bfloat16 g_oc_h[HROWS*RK], g_oc_l[HROWS*RK];
__device__ __nv_bfloat16 g_gat_h[BS_ROWS*HID], g_gat_l[BS_ROWS*HID];
__device__ float g_cos[S_*32], g_sin[S_*32];

// ===================== PTX helpers (sm_80-era only; sm_100 base target) ====
__device__ __forceinline__ uint32_t smem_u32(const void* p) {
    uint32_t a;
    asm("{ .reg .u64 t; cvta.to.shared.u64 t, %1; cvt.u32.u64 %0, t; }" : "=r"(a) : "l"(p));
    return a;
}
__device__ __forceinline__ void cpasync16(uint32_t dst, const void* src) {
    asm volatile("cp.async.cg.shared.global [%0], [%1], 16;" :: "r"(dst), "l"(src));
}
__device__ __forceinline__ void ldsm4(uint32_t* r, uint32_t addr) {
    asm volatile("ldmatrix.sync.aligned.m8n8.x4.shared.b16 {%0,%1,%2,%3}, [%4];"
        : "=r"(r[0]), "=r"(r[1]), "=r"(r[2]), "=r"(r[3]) : "r"(addr));
}
__device__ __forceinline__ void ldsm4t(uint32_t* r, uint32_t addr) {
    asm volatile("ldmatrix.sync.aligned.m8n8.x4.trans.shared.b16 {%0,%1,%2,%3}, [%4];"
        : "=r"(r[0]), "=r"(r[1]), "=r"(r[2]), "=r"(r[3]) : "r"(addr));
}
__device__ __forceinline__ void mma16816(float* c, const uint32_t* a, const uint32_t* b) {
    asm volatile(
        "mma.sync.aligned.m16n8k16.row.col.f32.bf16.bf16.f32 "
        "{%0,%1,%2,%3}, {%4,%5,%6,%7}, {%8,%9}, {%0,%1,%2,%3};"
        : "+f"(c[0]), "+f"(c[1]), "+f"(c[2]), "+f"(c[3])
        : "r"(a[0]), "r"(a[1]), "r"(a[2]), "r"(a[3]), "r"(b[0]), "r"(b[1]));
}
__device__ __forceinline__ void bsplit(float v, __nv_bfloat16& h, __nv_bfloat16& l) {
    h = __float2bfloat16(v);
    l = __float2bfloat16(v - __bfloat162float(h));
}
__device__ __forceinline__ void packsplit(float lo, float hi, uint32_t& ph, uint32_t& pl) {
    __nv_bfloat16 hl = __float2bfloat16(lo), hh = __float2bfloat16(hi);
    ph = (uint32_t)__bfloat16_as_ushort(hl) | ((uint32_t)__bfloat16_as_ushort(hh) << 16);
    __nv_bfloat16 ll = __float2bfloat16(lo - __bfloat162float(hl));
    __nv_bfloat16 lh = __float2bfloat16(hi - __bfloat162float(hh));
    pl = (uint32_t)__bfloat16_as_ushort(ll) | ((uint32_t)__bfloat16_as_ushort(lh) << 16);
}

// ===================== prep kernels =====================
__global__ void build_trig(const int* __restrict__ pos) {
    int idx = blockIdx.x * blockDim.x + threadIdx.x;
    if (idx >= S_ * 32) return;
    int s = idx >> 5, i = idx & 31;
    float p = (float)pos[s];
    float inv = 1.0f / powf(10000.0f, (float)(2 * i) * (1.0f / 64.0f));
    float a = p * inv;
    g_cos[idx] = cosf(a);
    g_sin[idx] = sinf(a);
}

__global__ void split2(const float* __restrict__ in, __nv_bfloat16* oh, __nv_bfloat16* ol, int n) {
    for (int i = blockIdx.x * blockDim.x + threadIdx.x; i < n; i += gridDim.x * blockDim.x) {
        __nv_bfloat16 h, l; bsplit(in[i], h, l); oh[i] = h; ol[i] = l;
    }
}

// out[c][r] = split(in[r][c]) for R x C, R,C mult of 32
__global__ void transpose_split(const float* __restrict__ in,
                                __nv_bfloat16* __restrict__ oh, __nv_bfloat16* __restrict__ ol,
                                int R, int C) {
    __shared__ float t[32][33];
    int bc = blockIdx.x * 32, br = blockIdx.y * 32;
    int x = threadIdx.x, y = threadIdx.y;
#pragma unroll
    for (int j = 0; j < 32; j += 8)
        t[y + j][x] = in[(size_t)(br + y + j) * C + bc + x];
    __syncthreads();
#pragma unroll
    for (int j = 0; j < 32; j += 8) {
        float v = t[x][y + j];
        __nv_bfloat16 h, l; bsplit(v, h, l);
        size_t o = (size_t)(bc + y + j) * R + br + x;
        oh[o] = h; ol[o] = l;
    }
}

__global__ void zero2(__nv_bfloat16* a, __nv_bfloat16* b, int n) {
    int i = blockIdx.x * blockDim.x + threadIdx.x;
    if (i < n) { a[i] = __float2bfloat16(0.f); b[i] = __float2bfloat16(0.f); }
}

// out[(row_off+n)*Kd + k] = split(in[k*N + n]); small weights
__global__ void tpad(const float* __restrict__ in, __nv_bfloat16* oh, __nv_bfloat16* ol,
                     int Kd, int N, int row_off) {
    int i = blockIdx.x * blockDim.x + threadIdx.x;
    if (i >= N * Kd) return;
    int n = i / Kd, k = i % Kd;
    __nv_bfloat16 h, l; bsplit(in[k * N + n], h, l);
    oh[(size_t)(row_off + n) * Kd + k] = h;
    ol[(size_t)(row_off + n) * Kd + k] = l;
}

// MvT[(h*64+r)*2048 + e] = split( sum_d Wv[e, h*128+d] * Wvc[d, r] )
// grid (32 e-tiles, 16 heads), 256 thr, dyn smem 64KB
__global__ void fold_v(const float* __restrict__ Wv, const float* __restrict__ Wvc,
                       __nv_bfloat16* __restrict__ oh, __nv_bfloat16* __restrict__ ol) {
    extern __shared__ float fsm[];
    float* sWv = fsm;           // [64][128]
    float* sVc = fsm + 64*128;  // [128][64]
    const int h = blockIdx.y, e0 = blockIdx.x * 64;
    const int t = threadIdx.x;
    for (int i = t; i < 64 * 128; i += 256) {
        int e = i >> 7, d = i & 127;
        sWv[i] = Wv[(size_t)(e0 + e) * HID + h * HD + d];
    }
    for (int i = t; i < 128 * 64; i += 256)
        sVc[i] = Wvc[i];
    __syncthreads();
    const int r = t & 63, eg = t >> 6;
    float acc[16];
#pragma unroll
    for (int ei = 0; ei < 16; ei++) acc[ei] = 0.f;
    for (int d = 0; d < 128; d++) {
        float v = sVc[d * 64 + r];
#pragma unroll
        for (int ei = 0; ei < 16; ei++)
            acc[ei] += sWv[(eg * 16 + ei) * 128 + d] * v;
    }
    size_t base = (size_t)(h * 64 + r) * HID + e0 + eg * 16;
#pragma unroll
    for (int ei = 0; ei < 16; ei++) {
        __nv_bfloat16 hh, ll; bsplit(acc[ei], hh, ll);
        oh[base + ei] = hh; ol[base + ei] = ll;
    }
}

// ===================== split-bf16 warp-MMA GEMM core =====================
// C[M,N] = (Ah+Al)[M,K] @ (Bh+Bl)[N,K]^T   (B stored transposed, K-major)
// CTA tile 128x128, KC=64, 8 warps (4x2), warp tile 32x64, mma.m16n8k16.
// 3 passes: AhBh + AhBl + AlBh.
// Modes: 0 outf; 1 split->oh/ol; 2 rope+split->oh/ol;
//        3 gc<64: split(v*0.125)->oh/ol (stride 64), else g_qg fp32;
//        4 silu(g_qg)*v -> split oh/ol (stride 128)
#define STAGE_B 65536   // Ah 16K | Al 16K | Bh 16K | Bl 16K

__device__ __forceinline__ void gemm_core(
    const __nv_bfloat16* __restrict__ Ah, const __nv_bfloat16* __restrict__ Al,
    const __nv_bfloat16* __restrict__ Bh, const __nv_bfloat16* __restrict__ Bl,
    int Kdim, int mode, int Nvalid, int ostride,
    float* __restrict__ outf, __nv_bfloat16* __restrict__ oh, __nv_bfloat16* __restrict__ ol,
    char* smem, int row0, int n0)
{
    const uint32_t sb = smem_u32(smem);
    const int tid  = threadIdx.x;
    const int wid  = tid >> 5, lane = tid & 31;
    const int wm   = wid >> 1, wn = wid & 1;

    float acc[2][8][4];
#pragma unroll
    for (int mi = 0; mi < 2; mi++)
#pragma unroll
        for (int ni = 0; ni < 8; ni++)
#pragma unroll
            for (int j = 0; j < 4; j++) acc[mi][ni][j] = 0.f;

    const int NIT = Kdim >> 6;

    auto load_chunk = [&](int it, int s) {
        const int kc0 = it << 6;
        const uint32_t base = sb + (uint32_t)s * STAGE_B;
#pragma unroll
        for (int q = 0; q < 4; q++) {
            int g = tid + q * 256;
            int r = g >> 3, cg = g & 7;
            uint32_t sw = (uint32_t)(r * 128 + ((cg ^ (r & 7)) << 4));
            size_t ga = (size_t)(row0 + r) * Kdim + kc0 + cg * 8;
            size_t gb = (size_t)(n0   + r) * Kdim + kc0 + cg * 8;
            cpasync16(base +         sw, Ah + ga);
            cpasync16(base + 16384 + sw, Al + ga);
            cpasync16(base + 32768 + sw, Bh + gb);
            cpasync16(base + 49152 + sw, Bl + gb);
        }
        asm volatile("cp.async.commit_group;" ::: "memory");
    };

    auto compute = [&](int s) {
        const uint32_t aB = sb + (uint32_t)s * STAGE_B;
        const uint32_t bB = aB + 32768;
#pragma unroll
        for (int ks = 0; ks < 4; ks++) {
            uint32_t ahf[2][4], alf[2][4], bhf[8][2], blf[8][2];
#pragma unroll
            for (int mi = 0; mi < 2; mi++) {
                int r  = wm * 32 + mi * 16 + (lane & 15);
                int cg = ks * 2 + (lane >> 4);
                uint32_t sw = (uint32_t)(r * 128 + ((cg ^ (r & 7)) << 4));
                ldsm4(ahf[mi], aB + sw);
                ldsm4(alf[mi], aB + 16384 + sw);
            }
#pragma unroll
            for (int bi = 0; bi < 4; bi++) {
                int r  = wn * 64 + bi * 16 + (lane & 15);
                int cg = ks * 2 + (lane >> 4);
                uint32_t sw = (uint32_t)(r * 128 + ((cg ^ (r & 7)) << 4));
                uint32_t t[4];
                ldsm4(t, bB + sw);
                bhf[bi*2][0]   = t[0]; bhf[bi*2][1]   = t[2];
                bhf[bi*2+1][0] = t[1]; bhf[bi*2+1][1] = t[3];
                ldsm4(t, bB + 16384 + sw);
                blf[bi*2][0]   = t[0]; blf[bi*2][1]   = t[2];
                blf[bi*2+1][0] = t[1]; blf[bi*2+1][1] = t[3];
            }
#pragma unroll
            for (int mi = 0; mi < 2; mi++)
#pragma unroll
                for (int ni = 0; ni < 8; ni++) {
                    mma16816(acc[mi][ni], ahf[mi], bhf[ni]);
                    mma16816(acc[mi][ni], ahf[mi], blf[ni]);
                    mma16816(acc[mi][ni], alf[mi], bhf[ni]);
                }
        }
    };

    load_chunk(0, 0);
    for (int it = 0; it < NIT; ++it) {
        if (it + 1 < NIT) {
            load_chunk(it + 1, (it + 1) & 1);
            asm volatile("cp.async.wait_group 1;" ::: "memory");
        } else {
            asm volatile("cp.async.wait_group 0;" ::: "memory");
        }
        __syncthreads();
        compute(it & 1);
        __syncthreads();
    }

    // ---- stage C through smem, fused epilogue ----
    float* sC = (float*)smem;
#pragma unroll
    for (int mi = 0; mi < 2; mi++)
#pragma unroll
        for (int ni = 0; ni < 8; ni++) {
            int m0 = wm * 32 + mi * 16 + (lane >> 2);
            int c0 = wn * 64 + ni * 8 + (lane & 3) * 2;
            sC[m0 * 132 + c0]           = acc[mi][ni][0];
            sC[m0 * 132 + c0 + 1]       = acc[mi][ni][1];
            sC[(m0 + 8) * 132 + c0]     = acc[mi][ni][2];
            sC[(m0 + 8) * 132 + c0 + 1] = acc[mi][ni][3];
        }
    __syncthreads();

    for (int x = tid; x < 128 * 128; x += 256) {
        int r = x >> 7, c = x & 127;
        int gr = row0 + r, gc = n0 + c;
        if (gc >= Nvalid) continue;
        float v = sC[r * 132 + c];
        if (mode == 0) {
            outf[(size_t)gr * ostride + gc] = v;
        } else if (mode == 1) {
            __nv_bfloat16 h, l; bsplit(v, h, l);
            size_t o = (size_t)gr * ostride + gc; oh[o] = h; ol[o] = l;
        } else if (mode == 2) {
            int d = gc & 127;
            float outv = v;
            if (d < 64) {
                int i = d & 31;
                int sdx = (gr & (S_ - 1)) * 32 + i;
                float co = g_cos[sdx], si = g_sin[sdx];
                float p = (d < 32) ? sC[r * 132 + c + 32] : sC[r * 132 + c - 32];
                outv = (d < 32) ? v * co - p * si : v * co + p * si;
            }
            __nv_bfloat16 h, l; bsplit(outv, h, l);
            size_t o = (size_t)gr * ostride + gc; oh[o] = h; ol[o] = l;
        } else if (mode == 3) {
            if (gc < 64) {
                __nv_bfloat16 h, l; bsplit(v * 0.125f, h, l);
                size_t o = (size_t)gr * 64 + gc; oh[o] = h; ol[o] = l;
            } else g_qg[(size_t)gr * 128 + (gc - 64)] = v;
        } else { // 4
            float g = g_qg[(size_t)gr * 128 + gc];
            float sil = g / (1.0f + expf(-g));
            __nv_bfloat16 h, l; bsplit(sil * v, h, l);
            size_t o = (size_t)gr * 128 + gc; oh[o] = h; ol[o] = l;
        }
    }
}

__global__ __launch_bounds__(256) void gemm_one(
    const __nv_bfloat16* Ah, const __nv_bfloat16* Al,
    const __nv_bfloat16* Bh, const __nv_bfloat16* Bl,
    int Kdim, int mode, int Nvalid, int ostride,
    float* outf, __nv_bfloat16* oh, __nv_bfloat16* ol)
{
    extern __shared__ __align__(128) char smem[];
    gemm_core(Ah, Al, Bh, Bl, Kdim, mode, Nvalid, ostride, outf, oh, ol,
              smem, blockIdx.x * 128, blockIdx.y * 128);
}

// merged Q/K/V-fold projections: grid (32, 16, 3)
__global__ __launch_bounds__(256) void gemm_qkv(
    const __nv_bfloat16* Ah, const __nv_bfloat16* Al,
    const __nv_bfloat16* WqH, const __nv_bfloat16* WqL,
    const __nv_bfloat16* WkH, const __nv_bfloat16* WkL,
    const __nv_bfloat16* MvH, const __nv_bfloat16* MvL,
    __nv_bfloat16* qh_, __nv_bfloat16* ql_,
    __nv_bfloat16* kh_, __nv_bfloat16* kl_,
    __nv_bfloat16* vh_, __nv_bfloat16* vl_)
{
    extern __shared__ __align__(128) char smem[];
    const int r0 = blockIdx.x * 128, c0 = blockIdx.y * 128;
    if (blockIdx.z == 0) {
        gemm_core(Ah, Al, WqH, WqL, HID, 2, HID, HID, nullptr, qh_, ql_, smem, r0, c0);
    } else if (blockIdx.z == 1) {
        gemm_core(Ah, Al, WkH, WkL, HID, 2, HID, HID, nullptr, kh_, kl_, smem, r0, c0);
    } else {
        if (blockIdx.y >= 8) return;
        gemm_core(Ah, Al, MvH, MvL, HID, 1, 1024, 1024, nullptr, vh_, vl_, smem, r0, c0);
    }
}

// merged head projections: grid (512, 2, 2)
__global__ __launch_bounds__(256) void gemm_heads(
    const __nv_bfloat16* qrh, const __nv_bfloat16* qrl,
    const __nv_bfloat16* cth, const __nv_bfloat16* ctl,
    const __nv_bfloat16* krh, const __nv_bfloat16* krl,
    const __nv_bfloat16* kch, const __nv_bfloat16* kcl,
    __nv_bfloat16* qah, __nv_bfloat16* qal,
    __nv_bfloat16* kkh, __nv_bfloat16* kkl)
{
    extern __shared__ __align__(128) char smem[];
    const int r0 = blockIdx.x * 128, c0 = blockIdx.y * 128;
    if (blockIdx.z == 0) {
        gemm_core(qrh, qrl, cth, ctl, 128, 3, 192, 64, nullptr, qah, qal, smem, r0, c0);
    } else {
        if (blockIdx.y >= 1) return;
        gemm_core(krh, krl, kch, kcl, 128, 1, 64, 64, nullptr, kkh, kkl, smem, r0, 0);
    }
}

// ===================== tensor-core flash attention ========================
#define ATT_SMEM 98304

__global__ __launch_bounds__(256) void attn_mma()
{
    extern __shared__ __align__(128) char smem[];
    const uint32_t sb = smem_u32(smem);
    const int tid = threadIdx.x, wid = tid >> 5, lane = tid & 31;
    const int b = blockIdx.y >> 4, h = blockIdx.y & 15;
    const int q0 = blockIdx.x * 128;

    for (int i = tid; i < 1024; i += 256) {
        int r = i >> 3, g = i & 7;
        uint32_t sw = (uint32_t)(r * 128 + ((g ^ (r & 7)) << 4));
        size_t gl = ((size_t)((b * S_ + q0 + r) * NH + h)) * RK + g * 8;
        cpasync16(sb + sw,         g_qa_h + gl);
        cpasync16(sb + 16384 + sw, g_qa_l + gl);
    }
    auto load_kv = [&](int t, int s) {
        const uint32_t kb = sb + 32768 + (uint32_t)s * 32768;
        for (int i = tid; i < 512; i += 256) {
            int r = i >> 3, g = i & 7;
            uint32_t sw = (uint32_t)(r * 128 + ((g ^ (r & 7)) << 4));
            size_t gl = ((size_t)((b * S_ + t * 64 + r) * NH + h)) * RK + g * 8;
            cpasync16(kb + sw,         g_kc_h + gl);
            cpasync16(kb + 8192 + sw,  g_kc_l + gl);
            cpasync16(kb + 16384 + sw, g_vc_h + gl);
            cpasync16(kb + 24576 + sw, g_vc_l + gl);
        }
    };
    load_kv(0, 0);
    asm volatile("cp.async.commit_group;" ::: "memory");

    float m1 = -INFINITY, m2 = -INFINITY, l1 = 0.f, l2 = 0.f;
    float ao[8][4];
#pragma unroll
    for (int nf = 0; nf < 8; nf++)
#pragma unroll
        for (int j = 0; j < 4; j++) ao[nf][j] = 0.f;
    uint32_t qh[4][4], qlo[4][4];
    int qloaded = 0;

    for (int t = 0; t < 32; ++t) {
        if (t + 1 < 32) {
            load_kv(t + 1, (t + 1) & 1);
            asm volatile("cp.async.commit_group;" ::: "memory");
            asm volatile("cp.async.wait_group 1;" ::: "memory");
        } else {
            asm volatile("cp.async.wait_group 0;" ::: "memory");
        }
        __syncthreads();
        if (!qloaded) {
            qloaded = 1;
#pragma unroll
            for (int kc = 0; kc < 4; kc++) {
                int r = wid * 16 + (lane & 15), cg = kc * 2 + (lane >> 4);
                uint32_t sw = (uint32_t)(r * 128 + ((cg ^ (r & 7)) << 4));
                ldsm4(qh[kc],  sb + sw);
                ldsm4(qlo[kc], sb + 16384 + sw);
            }
        }
        const uint32_t kb = sb + 32768 + (uint32_t)(t & 1) * 32768;

        float sa[8][4];
#pragma unroll
        for (int ni = 0; ni < 8; ni++)
#pragma unroll
            for (int j = 0; j < 4; j++) sa[ni][j] = 0.f;
#pragma unroll
        for (int kc = 0; kc < 4; kc++) {
            uint32_t kh[8][2], kl[8][2];
#pragma unroll
            for (int bi = 0; bi < 4; bi++) {
                int r = bi * 16 + (lane & 15), cg = kc * 2 + (lane >> 4);
                uint32_t sw = (uint32_t)(r * 128 + ((cg ^ (r & 7)) << 4));
                uint32_t t4[4];
                ldsm4(t4, kb + sw);
                kh[bi*2][0]=t4[0]; kh[bi*2][1]=t4[2]; kh[bi*2+1][0]=t4[1]; kh[bi*2+1][1]=t4[3];
                ldsm4(t4, kb + 8192 + sw);
                kl[bi*2][0]=t4[0]; kl[bi*2][1]=t4[2]; kl[bi*2+1][0]=t4[1]; kl[bi*2+1][1]=t4[3];
            }
#pragma unroll
            for (int ni = 0; ni < 8; ni++) {
                mma16816(sa[ni], qh[kc],  kh[ni]);
                mma16816(sa[ni], qh[kc],  kl[ni]);
                mma16816(sa[ni], qlo[kc], kh[ni]);
            }
        }

        float mx1 = -INFINITY, mx2 = -INFINITY;
#pragma unroll
        for (int ni = 0; ni < 8; ni++) {
            mx1 = fmaxf(mx1, fmaxf(sa[ni][0], sa[ni][1]));
            mx2 = fmaxf(mx2, fmaxf(sa[ni][2], sa[ni][3]));
        }
        mx1 = fmaxf(mx1, __shfl_xor_sync(0xffffffffu, mx1, 1));
        mx1 = fmaxf(mx1, __shfl_xor_sync(0xffffffffu, mx1, 2));
        mx2 = fmaxf(mx2, __shfl_xor_sync(0xffffffffu, mx2, 1));
        mx2 = fmaxf(mx2, __shfl_xor_sync(0xffffffffu, mx2, 2));
        float nm1 = fmaxf(m1, mx1), nm2 = fmaxf(m2, mx2);
        float al1 = __expf(m1 - nm1), al2 = __expf(m2 - nm2);
        float s1 = 0.f, s2 = 0.f;
#pragma unroll
        for (int ni = 0; ni < 8; ni++) {
            sa[ni][0] = __expf(sa[ni][0] - nm1); s1 += sa[ni][0];
            sa[ni][1] = __expf(sa[ni][1] - nm1); s1 += sa[ni][1];
            sa[ni][2] = __expf(sa[ni][2] - nm2); s2 += sa[ni][2];
            sa[ni][3] = __expf(sa[ni][3] - nm2); s2 += sa[ni][3];
        }
        s1 += __shfl_xor_sync(0xffffffffu, s1, 1);
        s1 += __shfl_xor_sync(0xffffffffu, s1, 2);
        s2 += __shfl_xor_sync(0xffffffffu, s2, 1);
        s2 += __shfl_xor_sync(0xffffffffu, s2, 2);
        l1 = l1 * al1 + s1; l2 = l2 * al2 + s2;
        m1 = nm1; m2 = nm2;
#pragma unroll
        for (int nf = 0; nf < 8; nf++) {
            ao[nf][0] *= al1; ao[nf][1] *= al1;
            ao[nf][2] *= al2; ao[nf][3] *= al2;
        }

#pragma unroll
        for (int j = 0; j < 4; j++) {
            uint32_t ph[4], pl[4];
            packsplit(sa[2*j][0],   sa[2*j][1],   ph[0], pl[0]);
            packsplit(sa[2*j][2],   sa[2*j][3],   ph[1], pl[1]);
            packsplit(sa[2*j+1][0], sa[2*j+1][1], ph[2], pl[2]);
            packsplit(sa[2*j+1][2], sa[2*j+1][3], ph[3], pl[3]);
            uint32_t vh[8][2], vl[8][2];
#pragma unroll
            for (int q = 0; q < 4; q++) {
                int row = j * 16 + ((lane >> 3) & 1) * 8 + (lane & 7);
                int g   = q * 2 + (lane >> 4);
                uint32_t sw = (uint32_t)(row * 128 + ((g ^ (row & 7)) << 4));
                uint32_t t4[4];
                ldsm4t(t4, kb + 16384 + sw);
                vh[q*2][0]=t4[0]; vh[q*2][1]=t4[1]; vh[q*2+1][0]=t4[2]; vh[q*2+1][1]=t4[3];
                ldsm4t(t4, kb + 24576 + sw);
                vl[q*2][0]=t4[0]; vl[q*2][1]=t4[1]; vl[q*2+1][0]=t4[2]; vl[q*2+1][1]=t4[3];
            }
#pragma unroll
            for (int nf = 0; nf < 8; nf++) {
                mma16816(ao[nf], ph, vh[nf]);
                mma16816(ao[nf], pl, vh[nf]);
                mma16816(ao[nf], ph, vl[nf]);
            }
        }
        __syncthreads();
    }

    float il1 = 1.f / l1, il2 = 1.f / l2;
    int r1 = q0 + wid * 16 + (lane >> 2);
    int cb = 2 * (lane & 3);
    size_t b1 = ((size_t)((b * S_ + r1) * NH + h)) * RK;
    size_t b2 = ((size_t)((b * S_ + r1 + 8) * NH + h)) * RK;
#pragma unroll
    for (int nf = 0; nf < 8; nf++) {
        int c = nf * 8 + cb;
        __nv_bfloat16 hh, ll;
        bsplit(ao[nf][0] * il1, hh, ll); g_oc_h[b1 + c]     = hh; g_oc_l[b1 + c]     = ll;
        bsplit(ao[nf][1] * il1, hh, ll); g_oc_h[b1 + c + 1] = hh; g_oc_l[b1 + c + 1] = ll;
        bsplit(ao[nf][2] * il2, hh, ll); g_oc_h[b2 + c]     = hh; g_oc_l[b2 + c]     = ll;
        bsplit(ao[nf][3] * il2, hh, ll); g_oc_h[b2 + c + 1] = hh; g_oc_l[b2 + c + 1] = ll;
    }
}

// ===================== launch =====================
#define SYMF(p, s) cudaGetSymbolAddress((void**)&p, s)

extern "C" void kernel_launch(void* const* d_in, const int* in_sizes, int n_in,
                              void* d_out, int out_size)
{
    const float* hs  = (const float*)d_in[0];
    const int*   pos = (const int*)  d_in[1];
    const float* Wq  = (const float*)d_in[2];
    const float* Wk  = (const float*)d_in[3];
    const float* Wv  = (const float*)d_in[4];
    const float* Wkc = (const float*)d_in[5];
    const float* Wvc = (const float*)d_in[6];
    const float* Wqa = (const float*)d_in[7];
    const float* Wqg = (const float*)d_in[8];
    const float* Wov = (const float*)d_in[9];
    const float* Wo  = (const float*)d_in[10];
    float* out = (float*)d_out;

    __nv_bfloat16 *hsh,*hsl,*wqh,*wql,*wkh,*wkl,*woh,*wol,*mvh,*mvl;
    __nv_bfloat16 *qrh,*qrl,*krh,*krl;
    __nv_bfloat16 *cth,*ctl,*kch,*kcl,*ovh,*ovl;
    __nv_bfloat16 *och,*ocl,*gth,*gtl;
    __nv_bfloat16 *qah,*qal,*kkh,*kkl,*vvh,*vvl;
    SYMF(hsh,g_hs_h);  SYMF(hsl,g_hs_l);
    SYMF(wqh,g_WqT_h); SYMF(wql,g_WqT_l);
    SYMF(wkh,g_WkT_h); SYMF(wkl,g_WkT_l);
    SYMF(woh,g_WoT_h); SYMF(wol,g_WoT_l);
    SYMF(mvh,g_MvT_h); SYMF(mvl,g_MvT_l);
    SYMF(qrh,g_Qr_h);  SYMF(qrl,g_Qr_l);
    SYMF(krh,g_Kr_h);  SYMF(krl,g_Kr_l);
    SYMF(cth,g_Wcat_h);SYMF(ctl,g_Wcat_l);
    SYMF(kch,g_WkcT_h);SYMF(kcl,g_WkcT_l);
    SYMF(ovh,g_WovT_h);SYMF(ovl,g_WovT_l);
    SYMF(och,g_oc_h);  SYMF(ocl,g_oc_l);
    SYMF(gth,g_gat_h); SYMF(gtl,g_gat_l);
    SYMF(qah,g_qa_h);  SYMF(qal,g_qa_l);
    SYMF(kkh,g_kc_h);  SYMF(kkl,g_kc_l);
    SYMF(vvh,g_vc_h);  SYMF(vvl,g_vc_l);

    // prep
    build_trig<<<(S_*32 + 255)/256, 256>>>(pos);
    split2<<<4096, 256>>>(hs, hsh, hsl, BS_ROWS*HID);
    transpose_split<<<dim3(64,64), dim3(32,8)>>>(Wq, wqh, wql, HID, HID);
    transpose_split<<<dim3(64,64), dim3(32,8)>>>(Wk, wkh, wkl, HID, HID);
    transpose_split<<<dim3(64,64), dim3(32,8)>>>(Wo, woh, wol, HID, HID);
    cudaFuncSetAttribute(fold_v, cudaFuncAttributeMaxDynamicSharedMemorySize, 65536);
    fold_v<<<dim3(32,16), 256, 65536>>>(Wv, Wvc, mvh, mvl);
    zero2<<<(256*HD+255)/256, 256>>>(cth, ctl, 256*HD);
    zero2<<<(256*HD+255)/256, 256>>>(kch, kcl, 256*HD);
    zero2<<<(256*RK+255)/256, 256>>>(ovh, ovl, 256*RK);
    tpad<<<(64*128+255)/256, 256>>>(Wqa, cth, ctl, 128, 64, 0);
    tpad<<<(128*128+255)/256, 256>>>(Wqg, cth, ctl, 128, 128, 64);
    tpad<<<(64*128+255)/256, 256>>>(Wkc, kch, kcl, 128, 64, 0);
    tpad<<<(128*64+255)/256, 256>>>(Wov, ovh, ovl, 64, 128, 0);

    const int gsmem = 2 * STAGE_B;
    cudaFuncSetAttribute(gemm_one,  cudaFuncAttributeMaxDynamicSharedMemorySize, gsmem);
    cudaFuncSetAttribute(gemm_qkv,  cudaFuncAttributeMaxDynamicSharedMemorySize, gsmem);
    cudaFuncSetAttribute(gemm_heads,cudaFuncAttributeMaxDynamicSharedMemorySize, gsmem);

    // Q (rope+split), K (rope+split), V-folded -> vc split   [one launch]
    gemm_qkv<<<dim3(32,16,3), 256, gsmem>>>(hsh, hsl,
                                            wqh, wql, wkh, wkl, mvh, mvl,
                                            qrh, qrl, krh, krl, vvh, vvl);
    // head projections: qa|qg and kc                          [one launch]
    gemm_heads<<<dim3(512,2,2), 256, gsmem>>>(qrh, qrl, cth, ctl,
                                              krh, krl, kch, kcl,
                                              qah, qal, kkh, kkl);
    // attention (tensor cores)
    cudaFuncSetAttribute(attn_mma, cudaFuncAttributeMaxDynamicSharedMemorySize, ATT_SMEM);
    attn_mma<<<dim3(S_/128, B_*NH), 256, ATT_SMEM>>>();
    // uplift + gate
    gemm_one<<<dim3(512,1), 256, gsmem>>>(och, ocl, ovh, ovl, 64, 4, 128, 128,
                                          nullptr, gth, gtl);
    // final projection
    gemm_one<<<dim3(32,16), 256, gsmem>>>(gth, gtl, woh, wol, HID, 0, HID, HID,
                                          out, nullptr, nullptr);
}

// round 11
// speedup vs baseline: 3.1393x; 1.0739x over previous
#include <cuda_runtime.h>
#include <cuda_bf16.h>
#include <math.h>
#include <stdint.h>

#define B_   2
#define S_   2048
#define HID  2048
#define NH   16
#define HD   128
#define RK   64
#define BS_ROWS (B_*S_)        // 4096
#define HROWS   (B_*S_*NH)     // 65536

// ===================== scratch (static __device__) =====================
__device__ __nv_bfloat16 g_hs_h[BS_ROWS*HID],  g_hs_l[BS_ROWS*HID];
__device__ __nv_bfloat16 g_WqT_h[HID*HID], g_WqT_l[HID*HID];
__device__ __nv_bfloat16 g_WkT_h[HID*HID], g_WkT_l[HID*HID];
__device__ __nv_bfloat16 g_WoT_h[HID*HID], g_WoT_l[HID*HID];
__device__ __nv_bfloat16 g_MvT_h[1024*HID], g_MvT_l[1024*HID];   // folded (Wv·Wvc)^T
__device__ __nv_bfloat16 g_Qr_h[BS_ROWS*HID], g_Qr_l[BS_ROWS*HID];
__device__ __nv_bfloat16 g_Kr_h[BS_ROWS*HID], g_Kr_l[BS_ROWS*HID];
__device__ __nv_bfloat16 g_Wcat_h[256*HD], g_Wcat_l[256*HD];   // [Wqa|Wqg]^T padded
__device__ __nv_bfloat16 g_WkcT_h[256*HD], g_WkcT_l[256*HD];
__device__ __nv_bfloat16 g_WovT_h[256*RK], g_WovT_l[256*RK];
__device__ __nv_bfloat16 g_qa_h[HROWS*RK], g_qa_l[HROWS*RK];   // pre-scaled 1/8
__device__ __nv_bfloat16 g_kc_h[HROWS*RK], g_kc_l[HROWS*RK];
__device__ __nv_bfloat16 g_vc_h[HROWS*RK], g_vc_l[HROWS*RK];
__device__ float g_qg[HROWS*HD];
__device__ __nv_bfloat16 g_oc_h[HROWS*RK], g_oc_l[HROWS*RK];
__device__ __nv_bfloat16 g_gat_h[BS_ROWS*HID], g_gat_l[BS_ROWS*HID];
__device__ float g_cos[S_*32], g_sin[S_*32];

// ===================== PTX helpers (sm_80-era only; sm_100 base target) ====
__device__ __forceinline__ uint32_t smem_u32(const void* p) {
    uint32_t a;
    asm("{ .reg .u64 t; cvta.to.shared.u64 t, %1; cvt.u32.u64 %0, t; }" : "=r"(a) : "l"(p));
    return a;
}
__device__ __forceinline__ void cpasync16(uint32_t dst, const void* src) {
    asm volatile("cp.async.cg.shared.global [%0], [%1], 16;" :: "r"(dst), "l"(src));
}
__device__ __forceinline__ void ldsm4(uint32_t* r, uint32_t addr) {
    asm volatile("ldmatrix.sync.aligned.m8n8.x4.shared.b16 {%0,%1,%2,%3}, [%4];"
        : "=r"(r[0]), "=r"(r[1]), "=r"(r[2]), "=r"(r[3]) : "r"(addr));
}
__device__ __forceinline__ void ldsm4t(uint32_t* r, uint32_t addr) {
    asm volatile("ldmatrix.sync.aligned.m8n8.x4.trans.shared.b16 {%0,%1,%2,%3}, [%4];"
        : "=r"(r[0]), "=r"(r[1]), "=r"(r[2]), "=r"(r[3]) : "r"(addr));
}
__device__ __forceinline__ void mma16816(float* c, const uint32_t* a, const uint32_t* b) {
    asm volatile(
        "mma.sync.aligned.m16n8k16.row.col.f32.bf16.bf16.f32 "
        "{%0,%1,%2,%3}, {%4,%5,%6,%7}, {%8,%9}, {%0,%1,%2,%3};"
        : "+f"(c[0]), "+f"(c[1]), "+f"(c[2]), "+f"(c[3])
        : "r"(a[0]), "r"(a[1]), "r"(a[2]), "r"(a[3]), "r"(b[0]), "r"(b[1]));
}
__device__ __forceinline__ void bsplit(float v, __nv_bfloat16& h, __nv_bfloat16& l) {
    h = __float2bfloat16(v);
    l = __float2bfloat16(v - __bfloat162float(h));
}
__device__ __forceinline__ void packsplit(float lo, float hi, uint32_t& ph, uint32_t& pl) {
    __nv_bfloat16 hl = __float2bfloat16(lo), hh = __float2bfloat16(hi);
    ph = (uint32_t)__bfloat16_as_ushort(hl) | ((uint32_t)__bfloat16_as_ushort(hh) << 16);
    __nv_bfloat16 ll = __float2bfloat16(lo - __bfloat162float(hl));
    __nv_bfloat16 lh = __float2bfloat16(hi - __bfloat162float(hh));
    pl = (uint32_t)__bfloat16_as_ushort(ll) | ((uint32_t)__bfloat16_as_ushort(lh) << 16);
}

// ===================== prep kernels =====================
__global__ void build_trig(const int* __restrict__ pos) {
    int idx = blockIdx.x * blockDim.x + threadIdx.x;
    if (idx >= S_ * 32) return;
    int s = idx >> 5, i = idx & 31;
    float p = (float)pos[s];
    float inv = 1.0f / powf(10000.0f, (float)(2 * i) * (1.0f / 64.0f));
    float a = p * inv;
    g_cos[idx] = cosf(a);
    g_sin[idx] = sinf(a);
}

__global__ void split2(const float* __restrict__ in, __nv_bfloat16* oh, __nv_bfloat16* ol, int n) {
    for (int i = blockIdx.x * blockDim.x + threadIdx.x; i < n; i += gridDim.x * blockDim.x) {
        __nv_bfloat16 h, l; bsplit(in[i], h, l); oh[i] = h; ol[i] = l;
    }
}

// 3 transposes in one launch: out[c][r] = split(in[r][c]), 2048x2048 each
__global__ void transpose3(const float* __restrict__ Wq, const float* __restrict__ Wk,
                           const float* __restrict__ Wo,
                           __nv_bfloat16* __restrict__ qh, __nv_bfloat16* __restrict__ ql,
                           __nv_bfloat16* __restrict__ kh, __nv_bfloat16* __restrict__ kl,
                           __nv_bfloat16* __restrict__ oh, __nv_bfloat16* __restrict__ ol) {
    __shared__ float t[32][33];
    const float* in = (blockIdx.z == 0) ? Wq : (blockIdx.z == 1) ? Wk : Wo;
    __nv_bfloat16* dh = (blockIdx.z == 0) ? qh : (blockIdx.z == 1) ? kh : oh;
    __nv_bfloat16* dl = (blockIdx.z == 0) ? ql : (blockIdx.z == 1) ? kl : ol;
    int bc = blockIdx.x * 32, br = blockIdx.y * 32;
    int x = threadIdx.x, y = threadIdx.y;
#pragma unroll
    for (int j = 0; j < 32; j += 8)
        t[y + j][x] = in[(size_t)(br + y + j) * HID + bc + x];
    __syncthreads();
#pragma unroll
    for (int j = 0; j < 32; j += 8) {
        float v = t[x][y + j];
        __nv_bfloat16 h, l; bsplit(v, h, l);
        size_t o = (size_t)(bc + y + j) * HID + br + x;
        dh[o] = h; dl[o] = l;
    }
}

// all small-weight prep in one launch: cat (qa|qg, pad), kc (pad), ov
__global__ void prep_small(const float* __restrict__ Wqa, const float* __restrict__ Wqg,
                           const float* __restrict__ Wkc, const float* __restrict__ Wov) {
    int idx = blockIdx.x * blockDim.x + threadIdx.x;
    if (idx < 32768) {                 // cat: 256 rows x 128
        int n = idx >> 7, k = idx & 127;
        float v = (n < 64) ? Wqa[k * 64 + n] : (n < 192) ? Wqg[k * 128 + (n - 64)] : 0.f;
        __nv_bfloat16 h, l; bsplit(v, h, l);
        g_Wcat_h[idx] = h; g_Wcat_l[idx] = l;
    } else if (idx < 49152) {          // kc: 128 rows x 128 (rows 64+ zero)
        int i2 = idx - 32768;
        int n = i2 >> 7, k = i2 & 127;
        float v = (n < 64) ? Wkc[k * 64 + n] : 0.f;
        __nv_bfloat16 h, l; bsplit(v, h, l);
        g_WkcT_h[i2] = h; g_WkcT_l[i2] = l;
    } else if (idx < 57344) {          // ov: 128 rows x 64
        int i2 = idx - 49152;
        int n = i2 >> 6, k = i2 & 63;
        __nv_bfloat16 h, l; bsplit(Wov[k * 128 + n], h, l);
        g_WovT_h[i2] = h; g_WovT_l[i2] = l;
    }
}

// MvT[(h*64+r)*2048 + e] = split( sum_d Wv[e, h*128+d] * Wvc[d, r] )
__global__ void fold_v(const float* __restrict__ Wv, const float* __restrict__ Wvc,
                       __nv_bfloat16* __restrict__ oh, __nv_bfloat16* __restrict__ ol) {
    extern __shared__ float fsm[];
    float* sWv = fsm;           // [64][128]
    float* sVc = fsm + 64*128;  // [128][64]
    const int h = blockIdx.y, e0 = blockIdx.x * 64;
    const int t = threadIdx.x;
    for (int i = t; i < 64 * 128; i += 256) {
        int e = i >> 7, d = i & 127;
        sWv[i] = Wv[(size_t)(e0 + e) * HID + h * HD + d];
    }
    for (int i = t; i < 128 * 64; i += 256)
        sVc[i] = Wvc[i];
    __syncthreads();
    const int r = t & 63, eg = t >> 6;
    float acc[16];
#pragma unroll
    for (int ei = 0; ei < 16; ei++) acc[ei] = 0.f;
    for (int d = 0; d < 128; d++) {
        float v = sVc[d * 64 + r];
#pragma unroll
        for (int ei = 0; ei < 16; ei++)
            acc[ei] += sWv[(eg * 16 + ei) * 128 + d] * v;
    }
    size_t base = (size_t)(h * 64 + r) * HID + e0 + eg * 16;
#pragma unroll
    for (int ei = 0; ei < 16; ei++) {
        __nv_bfloat16 hh, ll; bsplit(acc[ei], hh, ll);
        oh[base + ei] = hh; ol[base + ei] = ll;
    }
}

// ===================== split-bf16 warp-MMA GEMM core =====================
// 3-stage cp.async pipeline (D=3, prefetch 1), ONE barrier per K-chunk.
#define STAGE_B 65536   // Ah 16K | Al 16K | Bh 16K | Bl 16K
#define GSMEM   (3 * STAGE_B)

__device__ __forceinline__ void gemm_core(
    const __nv_bfloat16* __restrict__ Ah, const __nv_bfloat16* __restrict__ Al,
    const __nv_bfloat16* __restrict__ Bh, const __nv_bfloat16* __restrict__ Bl,
    int Kdim, int mode, int Nvalid, int ostride,
    float* __restrict__ outf, __nv_bfloat16* __restrict__ oh, __nv_bfloat16* __restrict__ ol,
    char* smem, int row0, int n0)
{
    const uint32_t sb = smem_u32(smem);
    const int tid  = threadIdx.x;
    const int wid  = tid >> 5, lane = tid & 31;
    const int wm   = wid >> 1, wn = wid & 1;

    float acc[2][8][4];
#pragma unroll
    for (int mi = 0; mi < 2; mi++)
#pragma unroll
        for (int ni = 0; ni < 8; ni++)
#pragma unroll
            for (int j = 0; j < 4; j++) acc[mi][ni][j] = 0.f;

    const int NIT = Kdim >> 6;

    auto load_chunk = [&](int it, int s) {
        const int kc0 = it << 6;
        const uint32_t base = sb + (uint32_t)s * STAGE_B;
#pragma unroll
        for (int q = 0; q < 4; q++) {
            int g = tid + q * 256;
            int r = g >> 3, cg = g & 7;
            uint32_t sw = (uint32_t)(r * 128 + ((cg ^ (r & 7)) << 4));
            size_t ga = (size_t)(row0 + r) * Kdim + kc0 + cg * 8;
            size_t gb = (size_t)(n0   + r) * Kdim + kc0 + cg * 8;
            cpasync16(base +         sw, Ah + ga);
            cpasync16(base + 16384 + sw, Al + ga);
            cpasync16(base + 32768 + sw, Bh + gb);
            cpasync16(base + 49152 + sw, Bl + gb);
        }
        asm volatile("cp.async.commit_group;" ::: "memory");
    };

    auto compute = [&](int s) {
        const uint32_t aB = sb + (uint32_t)s * STAGE_B;
        const uint32_t bB = aB + 32768;
#pragma unroll
        for (int ks = 0; ks < 4; ks++) {
            uint32_t ahf[2][4], alf[2][4], bhf[8][2], blf[8][2];
#pragma unroll
            for (int mi = 0; mi < 2; mi++) {
                int r  = wm * 32 + mi * 16 + (lane & 15);
                int cg = ks * 2 + (lane >> 4);
                uint32_t sw = (uint32_t)(r * 128 + ((cg ^ (r & 7)) << 4));
                ldsm4(ahf[mi], aB + sw);
                ldsm4(alf[mi], aB + 16384 + sw);
            }
#pragma unroll
            for (int bi = 0; bi < 4; bi++) {
                int r  = wn * 64 + bi * 16 + (lane & 15);
                int cg = ks * 2 + (lane >> 4);
                uint32_t sw = (uint32_t)(r * 128 + ((cg ^ (r & 7)) << 4));
                uint32_t t[4];
                ldsm4(t, bB + sw);
                bhf[bi*2][0]   = t[0]; bhf[bi*2][1]   = t[2];
                bhf[bi*2+1][0] = t[1]; bhf[bi*2+1][1] = t[3];
                ldsm4(t, bB + 16384 + sw);
                blf[bi*2][0]   = t[0]; blf[bi*2][1]   = t[2];
                blf[bi*2+1][0] = t[1]; blf[bi*2+1][1] = t[3];
            }
#pragma unroll
            for (int mi = 0; mi < 2; mi++)
#pragma unroll
                for (int ni = 0; ni < 8; ni++) {
                    mma16816(acc[mi][ni], ahf[mi], bhf[ni]);
                    mma16816(acc[mi][ni], ahf[mi], blf[ni]);
                    mma16816(acc[mi][ni], alf[mi], bhf[ni]);
                }
        }
    };

    load_chunk(0, 0);
    int stage = 0;
    for (int it = 0; it < NIT; ++it) {
        if (it + 1 < NIT) {
            int ns = stage + 1; if (ns == 3) ns = 0;
            load_chunk(it + 1, ns);
            asm volatile("cp.async.wait_group 1;" ::: "memory");
        } else {
            asm volatile("cp.async.wait_group 0;" ::: "memory");
        }
        __syncthreads();
        compute(stage);
        if (++stage == 3) stage = 0;
    }
    __syncthreads();   // protect smem reuse for epilogue staging

    // ---- stage C through smem, fused epilogue ----
    float* sC = (float*)smem;
#pragma unroll
    for (int mi = 0; mi < 2; mi++)
#pragma unroll
        for (int ni = 0; ni < 8; ni++) {
            int m0 = wm * 32 + mi * 16 + (lane >> 2);
            int c0 = wn * 64 + ni * 8 + (lane & 3) * 2;
            sC[m0 * 132 + c0]           = acc[mi][ni][0];
            sC[m0 * 132 + c0 + 1]       = acc[mi][ni][1];
            sC[(m0 + 8) * 132 + c0]     = acc[mi][ni][2];
            sC[(m0 + 8) * 132 + c0 + 1] = acc[mi][ni][3];
        }
    __syncthreads();

    for (int x = tid; x < 128 * 128; x += 256) {
        int r = x >> 7, c = x & 127;
        int gr = row0 + r, gc = n0 + c;
        if (gc >= Nvalid) continue;
        float v = sC[r * 132 + c];
        if (mode == 0) {
            outf[(size_t)gr * ostride + gc] = v;
        } else if (mode == 1) {
            __nv_bfloat16 h, l; bsplit(v, h, l);
            size_t o = (size_t)gr * ostride + gc; oh[o] = h; ol[o] = l;
        } else if (mode == 2) {
            int d = gc & 127;
            float outv = v;
            if (d < 64) {
                int i = d & 31;
                int sdx = (gr & (S_ - 1)) * 32 + i;
                float co = g_cos[sdx], si = g_sin[sdx];
                float p = (d < 32) ? sC[r * 132 + c + 32] : sC[r * 132 + c - 32];
                outv = (d < 32) ? v * co - p * si : v * co + p * si;
            }
            __nv_bfloat16 h, l; bsplit(outv, h, l);
            size_t o = (size_t)gr * ostride + gc; oh[o] = h; ol[o] = l;
        } else if (mode == 3) {
            if (gc < 64) {
                __nv_bfloat16 h, l; bsplit(v * 0.125f, h, l);
                size_t o = (size_t)gr * 64 + gc; oh[o] = h; ol[o] = l;
            } else g_qg[(size_t)gr * 128 + (gc - 64)] = v;
        } else { // 4
            float g = g_qg[(size_t)gr * 128 + gc];
            float sil = g / (1.0f + expf(-g));
            __nv_bfloat16 h, l; bsplit(sil * v, h, l);
            size_t o = (size_t)gr * 128 + gc; oh[o] = h; ol[o] = l;
        }
    }
}

__global__ __launch_bounds__(256) void gemm_one(
    const __nv_bfloat16* Ah, const __nv_bfloat16* Al,
    const __nv_bfloat16* Bh, const __nv_bfloat16* Bl,
    int Kdim, int mode, int Nvalid, int ostride,
    float* outf, __nv_bfloat16* oh, __nv_bfloat16* ol)
{
    extern __shared__ __align__(128) char smem[];
    gemm_core(Ah, Al, Bh, Bl, Kdim, mode, Nvalid, ostride, outf, oh, ol,
              smem, blockIdx.x * 128, blockIdx.y * 128);
}

// merged Q/K/V-fold projections: grid (32, 16, 3)
__global__ __launch_bounds__(256) void gemm_qkv(
    const __nv_bfloat16* Ah, const __nv_bfloat16* Al,
    const __nv_bfloat16* WqH, const __nv_bfloat16* WqL,
    const __nv_bfloat16* WkH, const __nv_bfloat16* WkL,
    const __nv_bfloat16* MvH, const __nv_bfloat16* MvL,
    __nv_bfloat16* qh_, __nv_bfloat16* ql_,
    __nv_bfloat16* kh_, __nv_bfloat16* kl_,
    __nv_bfloat16* vh_, __nv_bfloat16* vl_)
{
    extern __shared__ __align__(128) char smem[];
    const int r0 = blockIdx.x * 128, c0 = blockIdx.y * 128;
    if (blockIdx.z == 0) {
        gemm_core(Ah, Al, WqH, WqL, HID, 2, HID, HID, nullptr, qh_, ql_, smem, r0, c0);
    } else if (blockIdx.z == 1) {
        gemm_core(Ah, Al, WkH, WkL, HID, 2, HID, HID, nullptr, kh_, kl_, smem, r0, c0);
    } else {
        if (blockIdx.y >= 8) return;
        gemm_core(Ah, Al, MvH, MvL, HID, 1, 1024, 1024, nullptr, vh_, vl_, smem, r0, c0);
    }
}

// merged head projections: grid (512, 2, 2)
__global__ __launch_bounds__(256) void gemm_heads(
    const __nv_bfloat16* qrh, const __nv_bfloat16* qrl,
    const __nv_bfloat16* cth, const __nv_bfloat16* ctl,
    const __nv_bfloat16* krh, const __nv_bfloat16* krl,
    const __nv_bfloat16* kch, const __nv_bfloat16* kcl,
    __nv_bfloat16* qah, __nv_bfloat16* qal,
    __nv_bfloat16* kkh, __nv_bfloat16* kkl)
{
    extern __shared__ __align__(128) char smem[];
    const int r0 = blockIdx.x * 128, c0 = blockIdx.y * 128;
    if (blockIdx.z == 0) {
        gemm_core(qrh, qrl, cth, ctl, 128, 3, 192, 64, nullptr, qah, qal, smem, r0, c0);
    } else {
        if (blockIdx.y >= 1) return;
        gemm_core(krh, krl, kch, kcl, 128, 1, 64, 64, nullptr, kkh, kkl, smem, r0, 0);
    }
}

// ===================== tensor-core flash attention ========================
// K-tiles of 128 keys, 2-stage cp.async. 16 iterations.
// smem: Qh 0 | Ql 16K | stage s at 32768+s*65536: Kh,Kl,Vh,Vl (16K each)
#define ATT_SMEM (32768 + 2 * 65536)

__global__ __launch_bounds__(256, 1) void attn_mma()
{
    extern __shared__ __align__(128) char smem[];
    const uint32_t sb = smem_u32(smem);
    const int tid = threadIdx.x, wid = tid >> 5, lane = tid & 31;
    const int b = blockIdx.y >> 4, h = blockIdx.y & 15;
    const int q0 = blockIdx.x * 128;

    for (int i = tid; i < 1024; i += 256) {
        int r = i >> 3, g = i & 7;
        uint32_t sw = (uint32_t)(r * 128 + ((g ^ (r & 7)) << 4));
        size_t gl = ((size_t)((b * S_ + q0 + r) * NH + h)) * RK + g * 8;
        cpasync16(sb + sw,         g_qa_h + gl);
        cpasync16(sb + 16384 + sw, g_qa_l + gl);
    }
    auto load_kv = [&](int t, int s) {
        const uint32_t kb = sb + 32768 + (uint32_t)s * 65536;
        for (int i = tid; i < 1024; i += 256) {
            int r = i >> 3, g = i & 7;
            uint32_t sw = (uint32_t)(r * 128 + ((g ^ (r & 7)) << 4));
            size_t gl = ((size_t)((b * S_ + t * 128 + r) * NH + h)) * RK + g * 8;
            cpasync16(kb + sw,         g_kc_h + gl);
            cpasync16(kb + 16384 + sw, g_kc_l + gl);
            cpasync16(kb + 32768 + sw, g_vc_h + gl);
            cpasync16(kb + 49152 + sw, g_vc_l + gl);
        }
    };
    load_kv(0, 0);
    asm volatile("cp.async.commit_group;" ::: "memory");

    float m1 = -INFINITY, m2 = -INFINITY, l1 = 0.f, l2 = 0.f;
    float ao[8][4];
#pragma unroll
    for (int nf = 0; nf < 8; nf++)
#pragma unroll
        for (int j = 0; j < 4; j++) ao[nf][j] = 0.f;
    uint32_t qh[4][4], qlo[4][4];
    int qloaded = 0;

    for (int t = 0; t < 16; ++t) {
        if (t + 1 < 16) {
            load_kv(t + 1, (t + 1) & 1);
            asm volatile("cp.async.commit_group;" ::: "memory");
            asm volatile("cp.async.wait_group 1;" ::: "memory");
        } else {
            asm volatile("cp.async.wait_group 0;" ::: "memory");
        }
        __syncthreads();
        if (!qloaded) {
            qloaded = 1;
#pragma unroll
            for (int kc = 0; kc < 4; kc++) {
                int r = wid * 16 + (lane & 15), cg = kc * 2 + (lane >> 4);
                uint32_t sw = (uint32_t)(r * 128 + ((cg ^ (r & 7)) << 4));
                ldsm4(qh[kc],  sb + sw);
                ldsm4(qlo[kc], sb + 16384 + sw);
            }
        }
        const uint32_t kb = sb + 32768 + (uint32_t)(t & 1) * 65536;

        // ---- S = Q K^T (this warp: 16 x 128) ----
        float sa[16][4];
#pragma unroll
        for (int ni = 0; ni < 16; ni++)
#pragma unroll
            for (int j = 0; j < 4; j++) sa[ni][j] = 0.f;
#pragma unroll
        for (int kc = 0; kc < 4; kc++) {
            uint32_t kh[16][2], kl[16][2];
#pragma unroll
            for (int bi = 0; bi < 8; bi++) {
                int r = bi * 16 + (lane & 15), cg = kc * 2 + (lane >> 4);
                uint32_t sw = (uint32_t)(r * 128 + ((cg ^ (r & 7)) << 4));
                uint32_t t4[4];
                ldsm4(t4, kb + sw);
                kh[bi*2][0]=t4[0]; kh[bi*2][1]=t4[2]; kh[bi*2+1][0]=t4[1]; kh[bi*2+1][1]=t4[3];
                ldsm4(t4, kb + 16384 + sw);
                kl[bi*2][0]=t4[0]; kl[bi*2][1]=t4[2]; kl[bi*2+1][0]=t4[1]; kl[bi*2+1][1]=t4[3];
            }
#pragma unroll
            for (int ni = 0; ni < 16; ni++) {
                mma16816(sa[ni], qh[kc],  kh[ni]);
                mma16816(sa[ni], qh[kc],  kl[ni]);
                mma16816(sa[ni], qlo[kc], kh[ni]);
            }
        }

        // ---- online softmax (rows r1=16w+(lane>>2), r2=r1+8) ----
        float mx1 = -INFINITY, mx2 = -INFINITY;
#pragma unroll
        for (int ni = 0; ni < 16; ni++) {
            mx1 = fmaxf(mx1, fmaxf(sa[ni][0], sa[ni][1]));
            mx2 = fmaxf(mx2, fmaxf(sa[ni][2], sa[ni][3]));
        }
        mx1 = fmaxf(mx1, __shfl_xor_sync(0xffffffffu, mx1, 1));
        mx1 = fmaxf(mx1, __shfl_xor_sync(0xffffffffu, mx1, 2));
        mx2 = fmaxf(mx2, __shfl_xor_sync(0xffffffffu, mx2, 1));
        mx2 = fmaxf(mx2, __shfl_xor_sync(0xffffffffu, mx2, 2));
        float nm1 = fmaxf(m1, mx1), nm2 = fmaxf(m2, mx2);
        float al1 = __expf(m1 - nm1), al2 = __expf(m2 - nm2);
        float s1 = 0.f, s2 = 0.f;
#pragma unroll
        for (int ni = 0; ni < 16; ni++) {
            sa[ni][0] = __expf(sa[ni][0] - nm1); s1 += sa[ni][0];
            sa[ni][1] = __expf(sa[ni][1] - nm1); s1 += sa[ni][1];
            sa[ni][2] = __expf(sa[ni][2] - nm2); s2 += sa[ni][2];
            sa[ni][3] = __expf(sa[ni][3] - nm2); s2 += sa[ni][3];
        }
        s1 += __shfl_xor_sync(0xffffffffu, s1, 1);
        s1 += __shfl_xor_sync(0xffffffffu, s1, 2);
        s2 += __shfl_xor_sync(0xffffffffu, s2, 1);
        s2 += __shfl_xor_sync(0xffffffffu, s2, 2);
        l1 = l1 * al1 + s1; l2 = l2 * al2 + s2;
        m1 = nm1; m2 = nm2;
#pragma unroll
        for (int nf = 0; nf < 8; nf++) {
            ao[nf][0] *= al1; ao[nf][1] *= al1;
            ao[nf][2] *= al2; ao[nf][3] *= al2;
        }

        // ---- O += P V  (K-dim 128 = 8 j-steps) ----
#pragma unroll
        for (int j = 0; j < 8; j++) {
            uint32_t ph[4], pl[4];
            packsplit(sa[2*j][0],   sa[2*j][1],   ph[0], pl[0]);
            packsplit(sa[2*j][2],   sa[2*j][3],   ph[1], pl[1]);
            packsplit(sa[2*j+1][0], sa[2*j+1][1], ph[2], pl[2]);
            packsplit(sa[2*j+1][2], sa[2*j+1][3], ph[3], pl[3]);
            uint32_t vh[8][2], vl[8][2];
#pragma unroll
            for (int q = 0; q < 4; q++) {
                int row = j * 16 + ((lane >> 3) & 1) * 8 + (lane & 7);
                int g   = q * 2 + (lane >> 4);
                uint32_t sw = (uint32_t)(row * 128 + ((g ^ (row & 7)) << 4));
                uint32_t t4[4];
                ldsm4t(t4, kb + 32768 + sw);
                vh[q*2][0]=t4[0]; vh[q*2][1]=t4[1]; vh[q*2+1][0]=t4[2]; vh[q*2+1][1]=t4[3];
                ldsm4t(t4, kb + 49152 + sw);
                vl[q*2][0]=t4[0]; vl[q*2][1]=t4[1]; vl[q*2+1][0]=t4[2]; vl[q*2+1][1]=t4[3];
            }
#pragma unroll
            for (int nf = 0; nf < 8; nf++) {
                mma16816(ao[nf], ph, vh[nf]);
                mma16816(ao[nf], pl, vh[nf]);
                mma16816(ao[nf], ph, vl[nf]);
            }
        }
        __syncthreads();
    }

    float il1 = 1.f / l1, il2 = 1.f / l2;
    int r1 = q0 + wid * 16 + (lane >> 2);
    int cb = 2 * (lane & 3);
    size_t b1 = ((size_t)((b * S_ + r1) * NH + h)) * RK;
    size_t b2 = ((size_t)((b * S_ + r1 + 8) * NH + h)) * RK;
#pragma unroll
    for (int nf = 0; nf < 8; nf++) {
        int c = nf * 8 + cb;
        __nv_bfloat16 hh, ll;
        bsplit(ao[nf][0] * il1, hh, ll); g_oc_h[b1 + c]     = hh; g_oc_l[b1 + c]     = ll;
        bsplit(ao[nf][1] * il1, hh, ll); g_oc_h[b1 + c + 1] = hh; g_oc_l[b1 + c + 1] = ll;
        bsplit(ao[nf][2] * il2, hh, ll); g_oc_h[b2 + c]     = hh; g_oc_l[b2 + c]     = ll;
        bsplit(ao[nf][3] * il2, hh, ll); g_oc_h[b2 + c + 1] = hh; g_oc_l[b2 + c + 1] = ll;
    }
}

// ===================== launch =====================
#define SYMF(p, s) cudaGetSymbolAddress((void**)&p, s)

extern "C" void kernel_launch(void* const* d_in, const int* in_sizes, int n_in,
                              void* d_out, int out_size)
{
    const float* hs  = (const float*)d_in[0];
    const int*   pos = (const int*)  d_in[1];
    const float* Wq  = (const float*)d_in[2];
    const float* Wk  = (const float*)d_in[3];
    const float* Wv  = (const float*)d_in[4];
    const float* Wkc = (const float*)d_in[5];
    const float* Wvc = (const float*)d_in[6];
    const float* Wqa = (const float*)d_in[7];
    const float* Wqg = (const float*)d_in[8];
    const float* Wov = (const float*)d_in[9];
    const float* Wo  = (const float*)d_in[10];
    float* out = (float*)d_out;

    __nv_bfloat16 *hsh,*hsl,*wqh,*wql,*wkh,*wkl,*woh,*wol,*mvh,*mvl;
    __nv_bfloat16 *qrh,*qrl,*krh,*krl;
    __nv_bfloat16 *cth,*ctl,*kch,*kcl,*ovh,*ovl;
    __nv_bfloat16 *och,*ocl,*gth,*gtl;
    __nv_bfloat16 *qah,*qal,*kkh,*kkl,*vvh,*vvl;
    SYMF(hsh,g_hs_h);  SYMF(hsl,g_hs_l);
    SYMF(wqh,g_WqT_h); SYMF(wql,g_WqT_l);
    SYMF(wkh,g_WkT_h); SYMF(wkl,g_WkT_l);
    SYMF(woh,g_WoT_h); SYMF(wol,g_WoT_l);
    SYMF(mvh,g_MvT_h); SYMF(mvl,g_MvT_l);
    SYMF(qrh,g_Qr_h);  SYMF(qrl,g_Qr_l);
    SYMF(krh,g_Kr_h);  SYMF(krl,g_Kr_l);
    SYMF(cth,g_Wcat_h);SYMF(ctl,g_Wcat_l);
    SYMF(kch,g_WkcT_h);SYMF(kcl,g_WkcT_l);
    SYMF(ovh,g_WovT_h);SYMF(ovl,g_WovT_l);
    SYMF(och,g_oc_h);  SYMF(ocl,g_oc_l);
    SYMF(gth,g_gat_h); SYMF(gtl,g_gat_l);
    SYMF(qah,g_qa_h);  SYMF(qal,g_qa_l);
    SYMF(kkh,g_kc_h);  SYMF(kkl,g_kc_l);
    SYMF(vvh,g_vc_h);  SYMF(vvl,g_vc_l);

    // prep — ordered so gemm_qkv is the 6th launch (ncu -s 5 captures it)
    build_trig<<<(S_*32 + 255)/256, 256>>>(pos);                          // 1
    split2<<<4096, 256>>>(hs, hsh, hsl, BS_ROWS*HID);                     // 2
    transpose3<<<dim3(64,64,3), dim3(32,8)>>>(Wq, Wk, Wo,                 // 3
                                              wqh, wql, wkh, wkl, woh, wol);
    cudaFuncSetAttribute(fold_v, cudaFuncAttributeMaxDynamicSharedMemorySize, 65536);
    fold_v<<<dim3(32,16), 256, 65536>>>(Wv, Wvc, mvh, mvl);               // 4
    prep_small<<<224, 256>>>(Wqa, Wqg, Wkc, Wov);                         // 5

    cudaFuncSetAttribute(gemm_one,  cudaFuncAttributeMaxDynamicSharedMemorySize, GSMEM);
    cudaFuncSetAttribute(gemm_qkv,  cudaFuncAttributeMaxDynamicSharedMemorySize, GSMEM);
    cudaFuncSetAttribute(gemm_heads,cudaFuncAttributeMaxDynamicSharedMemorySize, GSMEM);

    // Q (rope+split), K (rope+split), V-folded -> vc split               // 6 (profiled)
    gemm_qkv<<<dim3(32,16,3), 256, GSMEM>>>(hsh, hsl,
                                            wqh, wql, wkh, wkl, mvh, mvl,
                                            qrh, qrl, krh, krl, vvh, vvl);
    // head projections: qa|qg and kc
    gemm_heads<<<dim3(512,2,2), 256, GSMEM>>>(qrh, qrl, cth, ctl,
                                              krh, krl, kch, kcl,
                                              qah, qal, kkh, kkl);
    // attention (tensor cores)
    cudaFuncSetAttribute(attn_mma, cudaFuncAttributeMaxDynamicSharedMemorySize, ATT_SMEM);
    attn_mma<<<dim3(S_/128, B_*NH), 256, ATT_SMEM>>>();
    // uplift + gate
    gemm_one<<<dim3(512,1), 256, GSMEM>>>(och, ocl, ovh, ovl, 64, 4, 128, 128,
                                          nullptr, gth, gtl);
    // final projection
    gemm_one<<<dim3(32,16), 256, GSMEM>>>(gth, gtl, woh, wol, HID, 0, HID, HID,
                                          out, nullptr, nullptr);
}

// round 12
// speedup vs baseline: 3.1648x; 1.0081x over previous
#include <cuda_runtime.h>
#include <cuda_bf16.h>
#include <math.h>
#include <stdint.h>

#define B_   2
#define S_   2048
#define HID  2048
#define NH   16
#define HD   128
#define RK   64
#define BS_ROWS (B_*S_)        // 4096
#define HROWS   (B_*S_*NH)     // 65536

// ===================== scratch (static __device__) =====================
__device__ __nv_bfloat16 g_hs_h[BS_ROWS*HID],  g_hs_l[BS_ROWS*HID];
__device__ __nv_bfloat16 g_WqT_h[HID*HID], g_WqT_l[HID*HID];
__device__ __nv_bfloat16 g_WkT_h[HID*HID], g_WkT_l[HID*HID];
__device__ __nv_bfloat16 g_WoT_h[HID*HID], g_WoT_l[HID*HID];
__device__ __nv_bfloat16 g_MvT_h[1024*HID], g_MvT_l[1024*HID];   // folded (Wv·Wvc)^T
__device__ __nv_bfloat16 g_Wcat_h[256*HD], g_Wcat_l[256*HD];   // [Wqa|Wqg]^T padded
__device__ __nv_bfloat16 g_WkcT_h[256*HD], g_WkcT_l[256*HD];
__device__ __nv_bfloat16 g_WovT_h[256*RK], g_WovT_l[256*RK];
__device__ __nv_bfloat16 g_qa_h[HROWS*RK], g_qa_l[HROWS*RK];   // pre-scaled 1/8
__device__ __nv_bfloat16 g_kc_h[HROWS*RK], g_kc_l[HROWS*RK];
__device__ __nv_bfloat16 g_vc_h[HROWS*RK], g_vc_l[HROWS*RK];
__device__ float g_qg[HROWS*HD];
__device__ __nv_bfloat16 g_oc_h[HROWS*RK], g_oc_l[HROWS*RK];
__device__ __nv_bfloat16 g_gat_h[BS_ROWS*HID], g_gat_l[BS_ROWS*HID];
__device__ float g_cos[S_*32], g_sin[S_*32];

// ===================== PTX helpers (sm_80-era only; sm_100 base target) ====
__device__ __forceinline__ uint32_t smem_u32(const void* p) {
    uint32_t a;
    asm("{ .reg .u64 t; cvta.to.shared.u64 t, %1; cvt.u32.u64 %0, t; }" : "=r"(a) : "l"(p));
    return a;
}
__device__ __forceinline__ void cpasync16(uint32_t dst, const void* src) {
    asm volatile("cp.async.cg.shared.global [%0], [%1], 16;" :: "r"(dst), "l"(src));
}
__device__ __forceinline__ void ldsm4(uint32_t* r, uint32_t addr) {
    asm volatile("ldmatrix.sync.aligned.m8n8.x4.shared.b16 {%0,%1,%2,%3}, [%4];"
        : "=r"(r[0]), "=r"(r[1]), "=r"(r[2]), "=r"(r[3]) : "r"(addr));
}
__device__ __forceinline__ void ldsm4t(uint32_t* r, uint32_t addr) {
    asm volatile("ldmatrix.sync.aligned.m8n8.x4.trans.shared.b16 {%0,%1,%2,%3}, [%4];"
        : "=r"(r[0]), "=r"(r[1]), "=r"(r[2]), "=r"(r[3]) : "r"(addr));
}
__device__ __forceinline__ void mma16816(float* c, const uint32_t* a, const uint32_t* b) {
    asm volatile(
        "mma.sync.aligned.m16n8k16.row.col.f32.bf16.bf16.f32 "
        "{%0,%1,%2,%3}, {%4,%5,%6,%7}, {%8,%9}, {%0,%1,%2,%3};"
        : "+f"(c[0]), "+f"(c[1]), "+f"(c[2]), "+f"(c[3])
        : "r"(a[0]), "r"(a[1]), "r"(a[2]), "r"(a[3]), "r"(b[0]), "r"(b[1]));
}
__device__ __forceinline__ void bsplit(float v, __nv_bfloat16& h, __nv_bfloat16& l) {
    h = __float2bfloat16(v);
    l = __float2bfloat16(v - __bfloat162float(h));
}
__device__ __forceinline__ void packsplit(float lo, float hi, uint32_t& ph, uint32_t& pl) {
    __nv_bfloat16 hl = __float2bfloat16(lo), hh = __float2bfloat16(hi);
    ph = (uint32_t)__bfloat16_as_ushort(hl) | ((uint32_t)__bfloat16_as_ushort(hh) << 16);
    __nv_bfloat16 ll = __float2bfloat16(lo - __bfloat162float(hl));
    __nv_bfloat16 lh = __float2bfloat16(hi - __bfloat162float(hh));
    pl = (uint32_t)__bfloat16_as_ushort(ll) | ((uint32_t)__bfloat16_as_ushort(lh) << 16);
}

// ===================== prep kernels =====================
// trig + all small-weight prep in ONE launch (grid 256 x 256 thr)
__global__ void prep_misc(const int* __restrict__ pos,
                          const float* __restrict__ Wqa, const float* __restrict__ Wqg,
                          const float* __restrict__ Wkc, const float* __restrict__ Wov) {
    int idx = blockIdx.x * blockDim.x + threadIdx.x;
    if (idx < S_ * 32) {
        int s = idx >> 5, i = idx & 31;
        float p = (float)pos[s];
        float inv = 1.0f / powf(10000.0f, (float)(2 * i) * (1.0f / 64.0f));
        float a = p * inv;
        g_cos[idx] = cosf(a);
        g_sin[idx] = sinf(a);
    }
    if (idx < 32768) {                 // cat: 256 rows x 128
        int n = idx >> 7, k = idx & 127;
        float v = (n < 64) ? Wqa[k * 64 + n] : (n < 192) ? Wqg[k * 128 + (n - 64)] : 0.f;
        __nv_bfloat16 h, l; bsplit(v, h, l);
        g_Wcat_h[idx] = h; g_Wcat_l[idx] = l;
    } else if (idx < 49152) {          // kc: 128 rows x 128 (rows 64+ zero)
        int i2 = idx - 32768;
        int n = i2 >> 7, k = i2 & 127;
        float v = (n < 64) ? Wkc[k * 64 + n] : 0.f;
        __nv_bfloat16 h, l; bsplit(v, h, l);
        g_WkcT_h[i2] = h; g_WkcT_l[i2] = l;
    } else if (idx < 57344) {          // ov: 128 rows x 64
        int i2 = idx - 49152;
        int n = i2 >> 6, k = i2 & 63;
        __nv_bfloat16 h, l; bsplit(Wov[k * 128 + n], h, l);
        g_WovT_h[i2] = h; g_WovT_l[i2] = l;
    }
}

__global__ void split2(const float* __restrict__ in, __nv_bfloat16* oh, __nv_bfloat16* ol, int n) {
    for (int i = blockIdx.x * blockDim.x + threadIdx.x; i < n; i += gridDim.x * blockDim.x) {
        __nv_bfloat16 h, l; bsplit(in[i], h, l); oh[i] = h; ol[i] = l;
    }
}

// transpose3 + fold_v in one 1-D launch: blocks [0,12288) transpose, [12288,12800) fold
#define PREPW_SMEM 66560
__global__ void prep_weights(const float* __restrict__ Wq, const float* __restrict__ Wk,
                             const float* __restrict__ Wo,
                             const float* __restrict__ Wv, const float* __restrict__ Wvc) {
    extern __shared__ float fsm[];
    const int gid = blockIdx.x;
    const int t = threadIdx.x;
    if (gid < 12288) {
        // ---- transpose path: z = gid/4096, tile = gid%4096 over 64x64 ----
        int z = gid >> 12, rem = gid & 4095;
        int bx = rem & 63, by = rem >> 6;
        const float* in = (z == 0) ? Wq : (z == 1) ? Wk : Wo;
        __nv_bfloat16* dh = (z == 0) ? g_WqT_h : (z == 1) ? g_WkT_h : g_WoT_h;
        __nv_bfloat16* dl = (z == 0) ? g_WqT_l : (z == 1) ? g_WkT_l : g_WoT_l;
        float (*tt)[33] = (float(*)[33])fsm;
        int x = t & 31, y = t >> 5;             // 32 x 8
        int bc = bx * 32, br = by * 32;
#pragma unroll
        for (int j = 0; j < 32; j += 8)
            tt[y + j][x] = in[(size_t)(br + y + j) * HID + bc + x];
        __syncthreads();
#pragma unroll
        for (int j = 0; j < 32; j += 8) {
            float v = tt[x][y + j];
            __nv_bfloat16 h, l; bsplit(v, h, l);
            size_t o = (size_t)(bc + y + j) * HID + br + x;
            dh[o] = h; dl[o] = l;
        }
    } else {
        // ---- fold_v path: MvT[(h*64+r)*2048 + e] = sum_d Wv[e,h*128+d]*Wvc[d,r]
        int fid = gid - 12288;                   // 0..511
        int e0 = (fid & 31) * 64, h = fid >> 5;
        float* sWv = fsm;                        // [64][128]
        float* sVc = fsm + 8192;                 // [64][132] (transposed, padded)
        for (int i = t; i < 8192; i += 256) {
            int e = i >> 7, d = i & 127;
            sWv[i] = Wv[(size_t)(e0 + e) * HID + h * HD + d];
        }
        for (int i = t; i < 8192; i += 256) {
            int r = i & 63, d = i >> 6;
            sVc[r * 132 + d] = Wvc[d * 64 + r];
        }
        __syncthreads();
        const int r = t & 63, eg = t >> 6;
        float acc[16];
#pragma unroll
        for (int ei = 0; ei < 16; ei++) acc[ei] = 0.f;
        for (int d = 0; d < 128; d += 4) {
            float4 v4 = *(float4*)&sVc[r * 132 + d];
#pragma unroll
            for (int ei = 0; ei < 16; ei++) {
                float4 w4 = *(float4*)&sWv[(eg * 16 + ei) * 128 + d];
                acc[ei] += w4.x * v4.x + w4.y * v4.y + w4.z * v4.z + w4.w * v4.w;
            }
        }
        size_t base = (size_t)(h * 64 + r) * HID + e0 + eg * 16;
#pragma unroll
        for (int ei = 0; ei < 16; ei++) {
            __nv_bfloat16 hh, ll; bsplit(acc[ei], hh, ll);
            g_MvT_h[base + ei] = hh; g_MvT_l[base + ei] = ll;
        }
    }
}

// ===================== split-bf16 warp-MMA GEMM =====================
// mainloop_sC: C tile (128x128, fp32) left in smem[0..67584) (sC stride 132), synced.
#define STAGE_B 65536
#define GSMEM   (3 * STAGE_B)
#define SQ_OFF  69632
#define WB_OFF  135168

__device__ __forceinline__ void mainloop_sC(
    const __nv_bfloat16* __restrict__ Ah, const __nv_bfloat16* __restrict__ Al,
    const __nv_bfloat16* __restrict__ Bh, const __nv_bfloat16* __restrict__ Bl,
    int Kdim, char* smem, int row0, int n0)
{
    const uint32_t sb = smem_u32(smem);
    const int tid  = threadIdx.x;
    const int wid  = tid >> 5, lane = tid & 31;
    const int wm   = wid >> 1, wn = wid & 1;

    float acc[2][8][4];
#pragma unroll
    for (int mi = 0; mi < 2; mi++)
#pragma unroll
        for (int ni = 0; ni < 8; ni++)
#pragma unroll
            for (int j = 0; j < 4; j++) acc[mi][ni][j] = 0.f;

    const int NIT = Kdim >> 6;

    auto load_chunk = [&](int it, int s) {
        const int kc0 = it << 6;
        const uint32_t base = sb + (uint32_t)s * STAGE_B;
#pragma unroll
        for (int q = 0; q < 4; q++) {
            int g = tid + q * 256;
            int r = g >> 3, cg = g & 7;
            uint32_t sw = (uint32_t)(r * 128 + ((cg ^ (r & 7)) << 4));
            size_t ga = (size_t)(row0 + r) * Kdim + kc0 + cg * 8;
            size_t gb = (size_t)(n0   + r) * Kdim + kc0 + cg * 8;
            cpasync16(base +         sw, Ah + ga);
            cpasync16(base + 16384 + sw, Al + ga);
            cpasync16(base + 32768 + sw, Bh + gb);
            cpasync16(base + 49152 + sw, Bl + gb);
        }
        asm volatile("cp.async.commit_group;" ::: "memory");
    };

    auto compute = [&](int s) {
        const uint32_t aB = sb + (uint32_t)s * STAGE_B;
        const uint32_t bB = aB + 32768;
#pragma unroll
        for (int ks = 0; ks < 4; ks++) {
            uint32_t ahf[2][4], alf[2][4], bhf[8][2], blf[8][2];
#pragma unroll
            for (int mi = 0; mi < 2; mi++) {
                int r  = wm * 32 + mi * 16 + (lane & 15);
                int cg = ks * 2 + (lane >> 4);
                uint32_t sw = (uint32_t)(r * 128 + ((cg ^ (r & 7)) << 4));
                ldsm4(ahf[mi], aB + sw);
                ldsm4(alf[mi], aB + 16384 + sw);
            }
#pragma unroll
            for (int bi = 0; bi < 4; bi++) {
                int r  = wn * 64 + bi * 16 + (lane & 15);
                int cg = ks * 2 + (lane >> 4);
                uint32_t sw = (uint32_t)(r * 128 + ((cg ^ (r & 7)) << 4));
                uint32_t t[4];
                ldsm4(t, bB + sw);
                bhf[bi*2][0]   = t[0]; bhf[bi*2][1]   = t[2];
                bhf[bi*2+1][0] = t[1]; bhf[bi*2+1][1] = t[3];
                ldsm4(t, bB + 16384 + sw);
                blf[bi*2][0]   = t[0]; blf[bi*2][1]   = t[2];
                blf[bi*2+1][0] = t[1]; blf[bi*2+1][1] = t[3];
            }
#pragma unroll
            for (int mi = 0; mi < 2; mi++)
#pragma unroll
                for (int ni = 0; ni < 8; ni++) {
                    mma16816(acc[mi][ni], ahf[mi], bhf[ni]);
                    mma16816(acc[mi][ni], ahf[mi], blf[ni]);
                    mma16816(acc[mi][ni], alf[mi], bhf[ni]);
                }
        }
    };

    load_chunk(0, 0);
    int stage = 0;
    for (int it = 0; it < NIT; ++it) {
        if (it + 1 < NIT) {
            int ns = stage + 1; if (ns == 3) ns = 0;
            load_chunk(it + 1, ns);
            asm volatile("cp.async.wait_group 1;" ::: "memory");
        } else {
            asm volatile("cp.async.wait_group 0;" ::: "memory");
        }
        __syncthreads();
        compute(stage);
        if (++stage == 3) stage = 0;
    }
    __syncthreads();

    float* sC = (float*)smem;
#pragma unroll
    for (int mi = 0; mi < 2; mi++)
#pragma unroll
        for (int ni = 0; ni < 8; ni++) {
            int m0 = wm * 32 + mi * 16 + (lane >> 2);
            int c0 = wn * 64 + ni * 8 + (lane & 3) * 2;
            sC[m0 * 132 + c0]           = acc[mi][ni][0];
            sC[m0 * 132 + c0 + 1]       = acc[mi][ni][1];
            sC[(m0 + 8) * 132 + c0]     = acc[mi][ni][2];
            sC[(m0 + 8) * 132 + c0 + 1] = acc[mi][ni][3];
        }
    __syncthreads();
}

// simple epilogues over sC. mode 0: fp32 out; 1: split; 4: silu(qg)*v split
__device__ __forceinline__ void epilogue_simple(
    int mode, int Nvalid, int ostride,
    float* __restrict__ outf, __nv_bfloat16* __restrict__ oh, __nv_bfloat16* __restrict__ ol,
    char* smem, int row0, int n0)
{
    float* sC = (float*)smem;
    const int tid = threadIdx.x;
    for (int x = tid; x < 128 * 128; x += 256) {
        int r = x >> 7, c = x & 127;
        int gr = row0 + r, gc = n0 + c;
        if (gc >= Nvalid) continue;
        float v = sC[r * 132 + c];
        if (mode == 0) {
            outf[(size_t)gr * ostride + gc] = v;
        } else if (mode == 1) {
            __nv_bfloat16 h, l; bsplit(v, h, l);
            size_t o = (size_t)gr * ostride + gc; oh[o] = h; ol[o] = l;
        } else { // 4
            float g = g_qg[(size_t)gr * 128 + gc];
            float sil = g / (1.0f + expf(-g));
            __nv_bfloat16 h, l; bsplit(sil * v, h, l);
            size_t o = (size_t)gr * 128 + gc; oh[o] = h; ol[o] = l;
        }
    }
}

// ===== fused head-projection epilogue =====
// sC holds pre-rope q/k tile [128 rows][cols = head h]. Apply rope, split to
// bf16 smem tiles, GEMM vs W (R rows, K=128 as 2 KC-64 tiles) in-kernel.
// IS_Q: cols 0..63 -> qa (x0.125, split), 64..191 -> qg fp32. else -> kc split.
template<int R, bool IS_Q>
__device__ __forceinline__ void head_epilogue(
    const __nv_bfloat16* __restrict__ Wh, const __nv_bfloat16* __restrict__ Wl,
    char* smem, int row0, int h)
{
    const uint32_t sb = smem_u32(smem);
    float* sC = (float*)smem;
    const int tid = threadIdx.x, wid = tid >> 5, lane = tid & 31;
    const int wm = wid >> 1, wn = wid & 1;
    constexpr int NB = R / 16;          // n-frags per warp (wn covers R/2 cols)

    // (a) kc0 weight tiles -> WB_OFF (h then l)
    for (int i = tid; i < R * 8; i += 256) {
        int r = i >> 3, cg = i & 7;
        uint32_t sw = (uint32_t)(r * 128 + ((cg ^ (r & 7)) << 4));
        cpasync16(sb + WB_OFF + sw,           Wh + (size_t)r * 128 + cg * 8);
        cpasync16(sb + WB_OFF + R * 128 + sw, Wl + (size_t)r * 128 + cg * 8);
    }
    asm volatile("cp.async.commit_group;" ::: "memory");

    // (b) rope + split sC -> sQ tiles (kc0_h, kc0_l, kc1_h, kc1_l @ SQ_OFF)
    for (int x = tid; x < 128 * 128; x += 256) {
        int r = x >> 7, d = x & 127;
        float v = sC[r * 132 + d];
        if (d < 64) {
            int i = d & 31;
            int sdx = ((row0 + r) & (S_ - 1)) * 32 + i;
            float co = g_cos[sdx], si = g_sin[sdx];
            float p = (d < 32) ? sC[r * 132 + d + 32] : sC[r * 132 + d - 32];
            v = (d < 32) ? v * co - p * si : v * co + p * si;
        }
        __nv_bfloat16 hh, ll; bsplit(v, hh, ll);
        int kc = d >> 6, dd = d & 63;
        uint32_t off = (uint32_t)(r * 128 + (((dd >> 3) ^ (r & 7)) << 4) + (dd & 7) * 2);
        *(__nv_bfloat16*)(smem + SQ_OFF + kc * 32768 + off)         = hh;
        *(__nv_bfloat16*)(smem + SQ_OFF + kc * 32768 + 16384 + off) = ll;
    }
    __syncthreads();

    // (c) kc1 weight tiles -> smem[0] (sC dead)
    for (int i = tid; i < R * 8; i += 256) {
        int r = i >> 3, cg = i & 7;
        uint32_t sw = (uint32_t)(r * 128 + ((cg ^ (r & 7)) << 4));
        cpasync16(sb + sw,           Wh + (size_t)r * 128 + 64 + cg * 8);
        cpasync16(sb + R * 128 + sw, Wl + (size_t)r * 128 + 64 + cg * 8);
    }
    asm volatile("cp.async.commit_group;" ::: "memory");
    asm volatile("cp.async.wait_group 1;" ::: "memory");
    __syncthreads();   // sQ + kc0 weights visible

    float acc2[2][NB][4];
#pragma unroll
    for (int mi = 0; mi < 2; mi++)
#pragma unroll
        for (int ni = 0; ni < NB; ni++)
#pragma unroll
            for (int j = 0; j < 4; j++) acc2[mi][ni][j] = 0.f;

#pragma unroll
    for (int kc = 0; kc < 2; kc++) {
        if (kc == 1) {
            asm volatile("cp.async.wait_group 0;" ::: "memory");
            __syncthreads();
        }
        const uint32_t aB = sb + SQ_OFF + kc * 32768;
        const uint32_t bB = (kc == 0) ? sb + WB_OFF : sb;
        const uint32_t bL = bB + R * 128;
#pragma unroll
        for (int ks = 0; ks < 4; ks++) {
            uint32_t ahf[2][4], alf[2][4], bhf[NB][2], blf[NB][2];
#pragma unroll
            for (int mi = 0; mi < 2; mi++) {
                int r  = wm * 32 + mi * 16 + (lane & 15);
                int cg = ks * 2 + (lane >> 4);
                uint32_t sw = (uint32_t)(r * 128 + ((cg ^ (r & 7)) << 4));
                ldsm4(ahf[mi], aB + sw);
                ldsm4(alf[mi], aB + 16384 + sw);
            }
#pragma unroll
            for (int bi = 0; bi < NB / 2; bi++) {
                int r  = wn * (R / 2) + bi * 16 + (lane & 15);
                int cg = ks * 2 + (lane >> 4);
                uint32_t sw = (uint32_t)(r * 128 + ((cg ^ (r & 7)) << 4));
                uint32_t t4[4];
                ldsm4(t4, bB + sw);
                bhf[bi*2][0]   = t4[0]; bhf[bi*2][1]   = t4[2];
                bhf[bi*2+1][0] = t4[1]; bhf[bi*2+1][1] = t4[3];
                ldsm4(t4, bL + sw);
                blf[bi*2][0]   = t4[0]; blf[bi*2][1]   = t4[2];
                blf[bi*2+1][0] = t4[1]; blf[bi*2+1][1] = t4[3];
            }
#pragma unroll
            for (int mi = 0; mi < 2; mi++)
#pragma unroll
                for (int ni = 0; ni < NB; ni++) {
                    mma16816(acc2[mi][ni], ahf[mi], bhf[ni]);
                    mma16816(acc2[mi][ni], ahf[mi], blf[ni]);
                    mma16816(acc2[mi][ni], alf[mi], bhf[ni]);
                }
        }
    }

    // write outputs
#pragma unroll
    for (int mi = 0; mi < 2; mi++)
#pragma unroll
        for (int ni = 0; ni < NB; ni++) {
            int gr = row0 + wm * 32 + mi * 16 + (lane >> 2);
            int c  = wn * (R / 2) + ni * 8 + (lane & 3) * 2;
#pragma unroll
            for (int half = 0; half < 2; half++) {
                int grr = gr + half * 8;
                float v0 = acc2[mi][ni][half * 2], v1 = acc2[mi][ni][half * 2 + 1];
                size_t hr = (size_t)grr * NH + h;
                if (IS_Q) {
                    if (c < 64) {
                        __nv_bfloat16 hh, ll;
                        bsplit(v0 * 0.125f, hh, ll);
                        g_qa_h[hr * 64 + c] = hh;     g_qa_l[hr * 64 + c] = ll;
                        bsplit(v1 * 0.125f, hh, ll);
                        g_qa_h[hr * 64 + c + 1] = hh; g_qa_l[hr * 64 + c + 1] = ll;
                    } else {
                        g_qg[hr * 128 + (c - 64)]     = v0;
                        g_qg[hr * 128 + (c - 63)]     = v1;
                    }
                } else {
                    __nv_bfloat16 hh, ll;
                    bsplit(v0, hh, ll);
                    g_kc_h[hr * 64 + c] = hh;     g_kc_l[hr * 64 + c] = ll;
                    bsplit(v1, hh, ll);
                    g_kc_h[hr * 64 + c + 1] = hh; g_kc_l[hr * 64 + c + 1] = ll;
                }
            }
        }
}

__global__ __launch_bounds__(256) void gemm_one(
    const __nv_bfloat16* Ah, const __nv_bfloat16* Al,
    const __nv_bfloat16* Bh, const __nv_bfloat16* Bl,
    int Kdim, int mode, int Nvalid, int ostride,
    float* outf, __nv_bfloat16* oh, __nv_bfloat16* ol)
{
    extern __shared__ __align__(128) char smem[];
    const int r0 = blockIdx.x * 128, c0 = blockIdx.y * 128;
    mainloop_sC(Ah, Al, Bh, Bl, Kdim, smem, r0, c0);
    epilogue_simple(mode, Nvalid, ostride, outf, oh, ol, smem, r0, c0);
}

// Q (rope + fused qa|qg), K (rope + fused kc), V-folded (split vc): grid (32,16,3)
__global__ __launch_bounds__(256) void gemm_qkv(
    const __nv_bfloat16* Ah, const __nv_bfloat16* Al)
{
    extern __shared__ __align__(128) char smem[];
    const int r0 = blockIdx.x * 128, c0 = blockIdx.y * 128;
    const int z = blockIdx.z;
    if (z == 2 && blockIdx.y >= 8) return;
    const __nv_bfloat16* Bh = (z == 0) ? g_WqT_h : (z == 1) ? g_WkT_h : g_MvT_h;
    const __nv_bfloat16* Bl = (z == 0) ? g_WqT_l : (z == 1) ? g_WkT_l : g_MvT_l;
    mainloop_sC(Ah, Al, Bh, Bl, HID, smem, r0, c0);
    if (z == 0)      head_epilogue<192, true >(g_Wcat_h, g_Wcat_l, smem, r0, blockIdx.y);
    else if (z == 1) head_epilogue<64,  false>(g_WkcT_h, g_WkcT_l, smem, r0, blockIdx.y);
    else             epilogue_simple(1, 1024, 1024, nullptr, g_vc_h, g_vc_l, smem, r0, c0);
}

// ===================== tensor-core flash attention ========================
#define ATT_SMEM (32768 + 2 * 65536)

__global__ __launch_bounds__(256, 1) void attn_mma()
{
    extern __shared__ __align__(128) char smem[];
    const uint32_t sb = smem_u32(smem);
    const int tid = threadIdx.x, wid = tid >> 5, lane = tid & 31;
    const int b = blockIdx.y >> 4, h = blockIdx.y & 15;
    const int q0 = blockIdx.x * 128;

    for (int i = tid; i < 1024; i += 256) {
        int r = i >> 3, g = i & 7;
        uint32_t sw = (uint32_t)(r * 128 + ((g ^ (r & 7)) << 4));
        size_t gl = ((size_t)((b * S_ + q0 + r) * NH + h)) * RK + g * 8;
        cpasync16(sb + sw,         g_qa_h + gl);
        cpasync16(sb + 16384 + sw, g_qa_l + gl);
    }
    auto load_kv = [&](int t, int s) {
        const uint32_t kb = sb + 32768 + (uint32_t)s * 65536;
        for (int i = tid; i < 1024; i += 256) {
            int r = i >> 3, g = i & 7;
            uint32_t sw = (uint32_t)(r * 128 + ((g ^ (r & 7)) << 4));
            size_t gl = ((size_t)((b * S_ + t * 128 + r) * NH + h)) * RK + g * 8;
            cpasync16(kb + sw,         g_kc_h + gl);
            cpasync16(kb + 16384 + sw, g_kc_l + gl);
            cpasync16(kb + 32768 + sw, g_vc_h + gl);
            cpasync16(kb + 49152 + sw, g_vc_l + gl);
        }
    };
    load_kv(0, 0);
    asm volatile("cp.async.commit_group;" ::: "memory");

    float m1 = -INFINITY, m2 = -INFINITY, l1 = 0.f, l2 = 0.f;
    float ao[8][4];
#pragma unroll
    for (int nf = 0; nf < 8; nf++)
#pragma unroll
        for (int j = 0; j < 4; j++) ao[nf][j] = 0.f;
    uint32_t qh[4][4], qlo[4][4];
    int qloaded = 0;

    for (int t = 0; t < 16; ++t) {
        if (t + 1 < 16) {
            load_kv(t + 1, (t + 1) & 1);
            asm volatile("cp.async.commit_group;" ::: "memory");
            asm volatile("cp.async.wait_group 1;" ::: "memory");
        } else {
            asm volatile("cp.async.wait_group 0;" ::: "memory");
        }
        __syncthreads();
        if (!qloaded) {
            qloaded = 1;
#pragma unroll
            for (int kc = 0; kc < 4; kc++) {
                int r = wid * 16 + (lane & 15), cg = kc * 2 + (lane >> 4);
                uint32_t sw = (uint32_t)(r * 128 + ((cg ^ (r & 7)) << 4));
                ldsm4(qh[kc],  sb + sw);
                ldsm4(qlo[kc], sb + 16384 + sw);
            }
        }
        const uint32_t kb = sb + 32768 + (uint32_t)(t & 1) * 65536;

        float sa[16][4];
#pragma unroll
        for (int ni = 0; ni < 16; ni++)
#pragma unroll
            for (int j = 0; j < 4; j++) sa[ni][j] = 0.f;
#pragma unroll
        for (int kc = 0; kc < 4; kc++) {
            uint32_t kh[16][2], kl[16][2];
#pragma unroll
            for (int bi = 0; bi < 8; bi++) {
                int r = bi * 16 + (lane & 15), cg = kc * 2 + (lane >> 4);
                uint32_t sw = (uint32_t)(r * 128 + ((cg ^ (r & 7)) << 4));
                uint32_t t4[4];
                ldsm4(t4, kb + sw);
                kh[bi*2][0]=t4[0]; kh[bi*2][1]=t4[2]; kh[bi*2+1][0]=t4[1]; kh[bi*2+1][1]=t4[3];
                ldsm4(t4, kb + 16384 + sw);
                kl[bi*2][0]=t4[0]; kl[bi*2][1]=t4[2]; kl[bi*2+1][0]=t4[1]; kl[bi*2+1][1]=t4[3];
            }
#pragma unroll
            for (int ni = 0; ni < 16; ni++) {
                mma16816(sa[ni], qh[kc],  kh[ni]);
                mma16816(sa[ni], qh[kc],  kl[ni]);
                mma16816(sa[ni], qlo[kc], kh[ni]);
            }
        }

        float mx1 = -INFINITY, mx2 = -INFINITY;
#pragma unroll
        for (int ni = 0; ni < 16; ni++) {
            mx1 = fmaxf(mx1, fmaxf(sa[ni][0], sa[ni][1]));
            mx2 = fmaxf(mx2, fmaxf(sa[ni][2], sa[ni][3]));
        }
        mx1 = fmaxf(mx1, __shfl_xor_sync(0xffffffffu, mx1, 1));
        mx1 = fmaxf(mx1, __shfl_xor_sync(0xffffffffu, mx1, 2));
        mx2 = fmaxf(mx2, __shfl_xor_sync(0xffffffffu, mx2, 1));
        mx2 = fmaxf(mx2, __shfl_xor_sync(0xffffffffu, mx2, 2));
        float nm1 = fmaxf(m1, mx1), nm2 = fmaxf(m2, mx2);
        float al1 = __expf(m1 - nm1), al2 = __expf(m2 - nm2);
        float s1 = 0.f, s2 = 0.f;
#pragma unroll
        for (int ni = 0; ni < 16; ni++) {
            sa[ni][0] = __expf(sa[ni][0] - nm1); s1 += sa[ni][0];
            sa[ni][1] = __expf(sa[ni][1] - nm1); s1 += sa[ni][1];
            sa[ni][2] = __expf(sa[ni][2] - nm2); s2 += sa[ni][2];
            sa[ni][3] = __expf(sa[ni][3] - nm2); s2 += sa[ni][3];
        }
        s1 += __shfl_xor_sync(0xffffffffu, s1, 1);
        s1 += __shfl_xor_sync(0xffffffffu, s1, 2);
        s2 += __shfl_xor_sync(0xffffffffu, s2, 1);
        s2 += __shfl_xor_sync(0xffffffffu, s2, 2);
        l1 = l1 * al1 + s1; l2 = l2 * al2 + s2;
        m1 = nm1; m2 = nm2;
#pragma unroll
        for (int nf = 0; nf < 8; nf++) {
            ao[nf][0] *= al1; ao[nf][1] *= al1;
            ao[nf][2] *= al2; ao[nf][3] *= al2;
        }

#pragma unroll
        for (int j = 0; j < 8; j++) {
            uint32_t ph[4], pl[4];
            packsplit(sa[2*j][0],   sa[2*j][1],   ph[0], pl[0]);
            packsplit(sa[2*j][2],   sa[2*j][3],   ph[1], pl[1]);
            packsplit(sa[2*j+1][0], sa[2*j+1][1], ph[2], pl[2]);
            packsplit(sa[2*j+1][2], sa[2*j+1][3], ph[3], pl[3]);
            uint32_t vh[8][2], vl[8][2];
#pragma unroll
            for (int q = 0; q < 4; q++) {
                int row = j * 16 + ((lane >> 3) & 1) * 8 + (lane & 7);
                int g   = q * 2 + (lane >> 4);
                uint32_t sw = (uint32_t)(row * 128 + ((g ^ (row & 7)) << 4));
                uint32_t t4[4];
                ldsm4t(t4, kb + 32768 + sw);
                vh[q*2][0]=t4[0]; vh[q*2][1]=t4[1]; vh[q*2+1][0]=t4[2]; vh[q*2+1][1]=t4[3];
                ldsm4t(t4, kb + 49152 + sw);
                vl[q*2][0]=t4[0]; vl[q*2][1]=t4[1]; vl[q*2+1][0]=t4[2]; vl[q*2+1][1]=t4[3];
            }
#pragma unroll
            for (int nf = 0; nf < 8; nf++) {
                mma16816(ao[nf], ph, vh[nf]);
                mma16816(ao[nf], pl, vh[nf]);
                mma16816(ao[nf], ph, vl[nf]);
            }
        }
        __syncthreads();
    }

    float il1 = 1.f / l1, il2 = 1.f / l2;
    int r1 = q0 + wid * 16 + (lane >> 2);
    int cb = 2 * (lane & 3);
    size_t b1 = ((size_t)((b * S_ + r1) * NH + h)) * RK;
    size_t b2 = ((size_t)((b * S_ + r1 + 8) * NH + h)) * RK;
#pragma unroll
    for (int nf = 0; nf < 8; nf++) {
        int c = nf * 8 + cb;
        __nv_bfloat16 hh, ll;
        bsplit(ao[nf][0] * il1, hh, ll); g_oc_h[b1 + c]     = hh; g_oc_l[b1 + c]     = ll;
        bsplit(ao[nf][1] * il1, hh, ll); g_oc_h[b1 + c + 1] = hh; g_oc_l[b1 + c + 1] = ll;
        bsplit(ao[nf][2] * il2, hh, ll); g_oc_h[b2 + c]     = hh; g_oc_l[b2 + c]     = ll;
        bsplit(ao[nf][3] * il2, hh, ll); g_oc_h[b2 + c + 1] = hh; g_oc_l[b2 + c + 1] = ll;
    }
}

// ===================== launch =====================
#define SYMF(p, s) cudaGetSymbolAddress((void**)&p, s)

extern "C" void kernel_launch(void* const* d_in, const int* in_sizes, int n_in,
                              void* d_out, int out_size)
{
    const float* hs  = (const float*)d_in[0];
    const int*   pos = (const int*)  d_in[1];
    const float* Wq  = (const float*)d_in[2];
    const float* Wk  = (const float*)d_in[3];
    const float* Wv  = (const float*)d_in[4];
    const float* Wkc = (const float*)d_in[5];
    const float* Wvc = (const float*)d_in[6];
    const float* Wqa = (const float*)d_in[7];
    const float* Wqg = (const float*)d_in[8];
    const float* Wov = (const float*)d_in[9];
    const float* Wo  = (const float*)d_in[10];
    float* out = (float*)d_out;

    __nv_bfloat16 *hsh,*hsl,*woh,*wol,*ovh,*ovl,*och,*ocl,*gth,*gtl;
    SYMF(hsh,g_hs_h);  SYMF(hsl,g_hs_l);
    SYMF(woh,g_WoT_h); SYMF(wol,g_WoT_l);
    SYMF(ovh,g_WovT_h);SYMF(ovl,g_WovT_l);
    SYMF(och,g_oc_h);  SYMF(ocl,g_oc_l);
    SYMF(gth,g_gat_h); SYMF(gtl,g_gat_l);

    // user launch 1..3 (harness adds 2 before; gemm_qkv = #6 -> profiled)
    prep_misc<<<256, 256>>>(pos, Wqa, Wqg, Wkc, Wov);                     // 1
    split2<<<4096, 256>>>(hs, hsh, hsl, BS_ROWS*HID);                     // 2
    cudaFuncSetAttribute(prep_weights, cudaFuncAttributeMaxDynamicSharedMemorySize, PREPW_SMEM);
    prep_weights<<<12800, 256, PREPW_SMEM>>>(Wq, Wk, Wo, Wv, Wvc);        // 3

    cudaFuncSetAttribute(gemm_one, cudaFuncAttributeMaxDynamicSharedMemorySize, GSMEM);
    cudaFuncSetAttribute(gemm_qkv, cudaFuncAttributeMaxDynamicSharedMemorySize, GSMEM);

    gemm_qkv<<<dim3(32,16,3), 256, GSMEM>>>(hsh, hsl);                    // 4 (profiled)

    cudaFuncSetAttribute(attn_mma, cudaFuncAttributeMaxDynamicSharedMemorySize, ATT_SMEM);
    attn_mma<<<dim3(S_/128, B_*NH), 256, ATT_SMEM>>>();                   // 5

    gemm_one<<<dim3(512,1), 256, GSMEM>>>(och, ocl, ovh, ovl, 64, 4, 128, 128,
                                          nullptr, gth, gtl);             // 6
    gemm_one<<<dim3(32,16), 256, GSMEM>>>(gth, gtl, woh, wol, HID, 0, HID, HID,
                                          out, nullptr, nullptr);         // 7
}

// round 14
// speedup vs baseline: 3.4395x; 1.0868x over previous
#include <cuda_runtime.h>
#include <cuda_bf16.h>
#include <math.h>
#include <stdint.h>

#define B_   2
#define S_   2048
#define HID  2048
#define NH   16
#define HD   128
#define RK   64
#define BS_ROWS (B_*S_)        // 4096
#define HROWS   (B_*S_*NH)     // 65536

// ===================== scratch (static __device__) =====================
__device__ __nv_bfloat16 g_hs_h[BS_ROWS*HID],  g_hs_l[BS_ROWS*HID];
__device__ __nv_bfloat16 g_WqT_h[HID*HID], g_WqT_l[HID*HID];
__device__ __nv_bfloat16 g_WkT_h[HID*HID], g_WkT_l[HID*HID];
__device__ __nv_bfloat16 g_WoT_h[HID*HID], g_WoT_l[HID*HID];
__device__ __nv_bfloat16 g_MvT_h[1024*HID], g_MvT_l[1024*HID];   // folded (Wv·Wvc)^T
__device__ __nv_bfloat16 g_Wcat_h[256*HD], g_Wcat_l[256*HD];   // [Wqa|Wqg]^T padded
__device__ __nv_bfloat16 g_WkcT_h[256*HD], g_WkcT_l[256*HD];
__device__ __nv_bfloat16 g_WovT_h[256*RK], g_WovT_l[256*RK];
__device__ __nv_bfloat16 g_qa_h[HROWS*RK], g_qa_l[HROWS*RK];   // pre-scaled 1/8
__device__ __nv_bfloat16 g_kc_h[HROWS*RK], g_kc_l[HROWS*RK];
__device__ __nv_bfloat16 g_vc_h[HROWS*RK], g_vc_l[HROWS*RK];
__device__ float g_qg[HROWS*HD];
__device__ __nv_bfloat16 g_oc_h[HROWS*RK], g_oc_l[HROWS*RK];
__device__ __nv_bfloat16 g_gat_h[BS_ROWS*HID], g_gat_l[BS_ROWS*HID];
__device__ float g_cos[S_*32], g_sin[S_*32];

// ===================== PTX helpers =====================
__device__ __forceinline__ uint32_t smem_u32(const void* p) {
    uint32_t a;
    asm("{ .reg .u64 t; cvta.to.shared.u64 t, %1; cvt.u32.u64 %0, t; }" : "=r"(a) : "l"(p));
    return a;
}
__device__ __forceinline__ void cpasync16(uint32_t dst, const void* src) {
    asm volatile("cp.async.cg.shared.global [%0], [%1], 16;" :: "r"(dst), "l"(src));
}
__device__ __forceinline__ void ldsm4(uint32_t* r, uint32_t addr) {
    asm volatile("ldmatrix.sync.aligned.m8n8.x4.shared.b16 {%0,%1,%2,%3}, [%4];"
        : "=r"(r[0]), "=r"(r[1]), "=r"(r[2]), "=r"(r[3]) : "r"(addr));
}
__device__ __forceinline__ void ldsm4t(uint32_t* r, uint32_t addr) {
    asm volatile("ldmatrix.sync.aligned.m8n8.x4.trans.shared.b16 {%0,%1,%2,%3}, [%4];"
        : "=r"(r[0]), "=r"(r[1]), "=r"(r[2]), "=r"(r[3]) : "r"(addr));
}
__device__ __forceinline__ void mma16816(float* c, const uint32_t* a, const uint32_t* b) {
    asm volatile(
        "mma.sync.aligned.m16n8k16.row.col.f32.bf16.bf16.f32 "
        "{%0,%1,%2,%3}, {%4,%5,%6,%7}, {%8,%9}, {%0,%1,%2,%3};"
        : "+f"(c[0]), "+f"(c[1]), "+f"(c[2]), "+f"(c[3])
        : "r"(a[0]), "r"(a[1]), "r"(a[2]), "r"(a[3]), "r"(b[0]), "r"(b[1]));
}
__device__ __forceinline__ void bsplit(float v, __nv_bfloat16& h, __nv_bfloat16& l) {
    h = __float2bfloat16(v);
    l = __float2bfloat16(v - __bfloat162float(h));
}
__device__ __forceinline__ void packsplit(float lo, float hi, uint32_t& ph, uint32_t& pl) {
    __nv_bfloat16 hl = __float2bfloat16(lo), hh = __float2bfloat16(hi);
    ph = (uint32_t)__bfloat16_as_ushort(hl) | ((uint32_t)__bfloat16_as_ushort(hh) << 16);
    __nv_bfloat16 ll = __float2bfloat16(lo - __bfloat162float(hl));
    __nv_bfloat16 lh = __float2bfloat16(hi - __bfloat162float(hh));
    pl = (uint32_t)__bfloat16_as_ushort(ll) | ((uint32_t)__bfloat16_as_ushort(lh) << 16);
}

// ===================== prep kernels =====================
__global__ void prep_misc(const int* __restrict__ pos,
                          const float* __restrict__ Wqa, const float* __restrict__ Wqg,
                          const float* __restrict__ Wkc, const float* __restrict__ Wov) {
    int idx = blockIdx.x * blockDim.x + threadIdx.x;
    if (idx < S_ * 32) {
        int s = idx >> 5, i = idx & 31;
        float p = (float)pos[s];
        float inv = 1.0f / powf(10000.0f, (float)(2 * i) * (1.0f / 64.0f));
        float a = p * inv;
        g_cos[idx] = cosf(a);
        g_sin[idx] = sinf(a);
    }
    if (idx < 32768) {                 // cat: 256 rows x 128
        int n = idx >> 7, k = idx & 127;
        float v = (n < 64) ? Wqa[k * 64 + n] : (n < 192) ? Wqg[k * 128 + (n - 64)] : 0.f;
        __nv_bfloat16 h, l; bsplit(v, h, l);
        g_Wcat_h[idx] = h; g_Wcat_l[idx] = l;
    } else if (idx < 49152) {          // kc: 128 rows x 128 (rows 64+ zero)
        int i2 = idx - 32768;
        int n = i2 >> 7, k = i2 & 127;
        float v = (n < 64) ? Wkc[k * 64 + n] : 0.f;
        __nv_bfloat16 h, l; bsplit(v, h, l);
        g_WkcT_h[i2] = h; g_WkcT_l[i2] = l;
    } else if (idx < 57344) {          // ov: 128 rows x 64
        int i2 = idx - 49152;
        int n = i2 >> 6, k = i2 & 63;
        __nv_bfloat16 h, l; bsplit(Wov[k * 128 + n], h, l);
        g_WovT_h[i2] = h; g_WovT_l[i2] = l;
    }
}

__global__ void split2(const float* __restrict__ in, __nv_bfloat16* oh, __nv_bfloat16* ol, int n) {
    for (int i = blockIdx.x * blockDim.x + threadIdx.x; i < n; i += gridDim.x * blockDim.x) {
        __nv_bfloat16 h, l; bsplit(in[i], h, l); oh[i] = h; ol[i] = l;
    }
}

#define PREPW_SMEM 66560
__global__ void prep_weights(const float* __restrict__ Wq, const float* __restrict__ Wk,
                             const float* __restrict__ Wo,
                             const float* __restrict__ Wv, const float* __restrict__ Wvc) {
    extern __shared__ float fsm[];
    const int gid = blockIdx.x;
    const int t = threadIdx.x;
    if (gid < 12288) {
        int z = gid >> 12, rem = gid & 4095;
        int bx = rem & 63, by = rem >> 6;
        const float* in = (z == 0) ? Wq : (z == 1) ? Wk : Wo;
        __nv_bfloat16* dh = (z == 0) ? g_WqT_h : (z == 1) ? g_WkT_h : g_WoT_h;
        __nv_bfloat16* dl = (z == 0) ? g_WqT_l : (z == 1) ? g_WkT_l : g_WoT_l;
        float (*tt)[33] = (float(*)[33])fsm;
        int x = t & 31, y = t >> 5;
        int bc = bx * 32, br = by * 32;
#pragma unroll
        for (int j = 0; j < 32; j += 8)
            tt[y + j][x] = in[(size_t)(br + y + j) * HID + bc + x];
        __syncthreads();
#pragma unroll
        for (int j = 0; j < 32; j += 8) {
            float v = tt[x][y + j];
            __nv_bfloat16 h, l; bsplit(v, h, l);
            size_t o = (size_t)(bc + y + j) * HID + br + x;
            dh[o] = h; dl[o] = l;
        }
    } else {
        int fid = gid - 12288;
        int e0 = (fid & 31) * 64, h = fid >> 5;
        float* sWv = fsm;
        float* sVc = fsm + 8192;
        for (int i = t; i < 8192; i += 256) {
            int e = i >> 7, d = i & 127;
            sWv[i] = Wv[(size_t)(e0 + e) * HID + h * HD + d];
        }
        for (int i = t; i < 8192; i += 256) {
            int r = i & 63, d = i >> 6;
            sVc[r * 132 + d] = Wvc[d * 64 + r];
        }
        __syncthreads();
        const int r = t & 63, eg = t >> 6;
        float acc[16];
#pragma unroll
        for (int ei = 0; ei < 16; ei++) acc[ei] = 0.f;
        for (int d = 0; d < 128; d += 4) {
            float4 v4 = *(float4*)&sVc[r * 132 + d];
#pragma unroll
            for (int ei = 0; ei < 16; ei++) {
                float4 w4 = *(float4*)&sWv[(eg * 16 + ei) * 128 + d];
                acc[ei] += w4.x * v4.x + w4.y * v4.y + w4.z * v4.z + w4.w * v4.w;
            }
        }
        size_t base = (size_t)(h * 64 + r) * HID + e0 + eg * 16;
#pragma unroll
        for (int ei = 0; ei < 16; ei++) {
            __nv_bfloat16 hh, ll; bsplit(acc[ei], hh, ll);
            g_MvT_h[base + ei] = hh; g_MvT_l[base + ei] = ll;
        }
    }
}

// ===================== split-bf16 warp-MMA GEMM (512 thr, 16 warps) ======
// 4x4 warp grid, 32x32 warp tiles, KC=64, 3-stage cp.async.
#define NTHR    512
#define STAGE_B 65536
#define GSMEM   (3 * STAGE_B)
#define SQ_OFF  69632
#define WB_OFF  135168

__device__ __forceinline__ void mainloop_sC(
    const __nv_bfloat16* __restrict__ Ah, const __nv_bfloat16* __restrict__ Al,
    const __nv_bfloat16* __restrict__ Bh, const __nv_bfloat16* __restrict__ Bl,
    int Kdim, char* smem, int row0, int n0)
{
    const uint32_t sb = smem_u32(smem);
    const int tid  = threadIdx.x;
    const int wid  = tid >> 5, lane = tid & 31;
    const int wm   = wid >> 2, wn = wid & 3;

    float acc[2][4][4];
#pragma unroll
    for (int mi = 0; mi < 2; mi++)
#pragma unroll
        for (int ni = 0; ni < 4; ni++)
#pragma unroll
            for (int j = 0; j < 4; j++) acc[mi][ni][j] = 0.f;

    const int NIT = Kdim >> 6;

    auto load_chunk = [&](int it, int s) {
        const int kc0 = it << 6;
        const uint32_t base = sb + (uint32_t)s * STAGE_B;
#pragma unroll
        for (int q = 0; q < 2; q++) {
            int g = tid + q * NTHR;            // 0..1023 : 128 rows x 8 granules
            int r = g >> 3, cg = g & 7;
            uint32_t sw = (uint32_t)(r * 128 + ((cg ^ (r & 7)) << 4));
            size_t ga = (size_t)(row0 + r) * Kdim + kc0 + cg * 8;
            size_t gb = (size_t)(n0   + r) * Kdim + kc0 + cg * 8;
            cpasync16(base +         sw, Ah + ga);
            cpasync16(base + 16384 + sw, Al + ga);
            cpasync16(base + 32768 + sw, Bh + gb);
            cpasync16(base + 49152 + sw, Bl + gb);
        }
        asm volatile("cp.async.commit_group;" ::: "memory");
    };

    auto compute = [&](int s) {
        const uint32_t aB = sb + (uint32_t)s * STAGE_B;
        const uint32_t bB = aB + 32768;
#pragma unroll
        for (int ks = 0; ks < 4; ks++) {
            uint32_t ahf[2][4], alf[2][4], bhf[4][2], blf[4][2];
#pragma unroll
            for (int mi = 0; mi < 2; mi++) {
                int r  = wm * 32 + mi * 16 + (lane & 15);
                int cg = ks * 2 + (lane >> 4);
                uint32_t sw = (uint32_t)(r * 128 + ((cg ^ (r & 7)) << 4));
                ldsm4(ahf[mi], aB + sw);
                ldsm4(alf[mi], aB + 16384 + sw);
            }
#pragma unroll
            for (int bi = 0; bi < 2; bi++) {
                int r  = wn * 32 + bi * 16 + (lane & 15);
                int cg = ks * 2 + (lane >> 4);
                uint32_t sw = (uint32_t)(r * 128 + ((cg ^ (r & 7)) << 4));
                uint32_t t[4];
                ldsm4(t, bB + sw);
                bhf[bi*2][0]   = t[0]; bhf[bi*2][1]   = t[2];
                bhf[bi*2+1][0] = t[1]; bhf[bi*2+1][1] = t[3];
                ldsm4(t, bB + 16384 + sw);
                blf[bi*2][0]   = t[0]; blf[bi*2][1]   = t[2];
                blf[bi*2+1][0] = t[1]; blf[bi*2+1][1] = t[3];
            }
#pragma unroll
            for (int mi = 0; mi < 2; mi++)
#pragma unroll
                for (int ni = 0; ni < 4; ni++) {
                    mma16816(acc[mi][ni], ahf[mi], bhf[ni]);
                    mma16816(acc[mi][ni], ahf[mi], blf[ni]);
                    mma16816(acc[mi][ni], alf[mi], bhf[ni]);
                }
        }
    };

    load_chunk(0, 0);
    int stage = 0;
    for (int it = 0; it < NIT; ++it) {
        if (it + 1 < NIT) {
            int ns = stage + 1; if (ns == 3) ns = 0;
            load_chunk(it + 1, ns);
            asm volatile("cp.async.wait_group 1;" ::: "memory");
        } else {
            asm volatile("cp.async.wait_group 0;" ::: "memory");
        }
        __syncthreads();
        compute(stage);
        if (++stage == 3) stage = 0;
    }
    __syncthreads();

    float* sC = (float*)smem;
#pragma unroll
    for (int mi = 0; mi < 2; mi++)
#pragma unroll
        for (int ni = 0; ni < 4; ni++) {
            int m0 = wm * 32 + mi * 16 + (lane >> 2);
            int c0 = wn * 32 + ni * 8 + (lane & 3) * 2;
            sC[m0 * 132 + c0]           = acc[mi][ni][0];
            sC[m0 * 132 + c0 + 1]       = acc[mi][ni][1];
            sC[(m0 + 8) * 132 + c0]     = acc[mi][ni][2];
            sC[(m0 + 8) * 132 + c0 + 1] = acc[mi][ni][3];
        }
    __syncthreads();
}

// simple epilogues over sC. mode 0: fp32 out; 1: split; 4: silu(qg)*v split
__device__ __forceinline__ void epilogue_simple(
    int mode, int Nvalid, int ostride,
    float* __restrict__ outf, __nv_bfloat16* __restrict__ oh, __nv_bfloat16* __restrict__ ol,
    char* smem, int row0, int n0)
{
    float* sC = (float*)smem;
    const int tid = threadIdx.x;
    for (int x = tid; x < 128 * 128; x += NTHR) {
        int r = x >> 7, c = x & 127;
        int gr = row0 + r, gc = n0 + c;
        if (gc >= Nvalid) continue;
        float v = sC[r * 132 + c];
        if (mode == 0) {
            outf[(size_t)gr * ostride + gc] = v;
        } else if (mode == 1) {
            __nv_bfloat16 h, l; bsplit(v, h, l);
            size_t o = (size_t)gr * ostride + gc; oh[o] = h; ol[o] = l;
        } else { // 4
            float g = g_qg[(size_t)gr * 128 + gc];
            float sil = g / (1.0f + expf(-g));
            __nv_bfloat16 h, l; bsplit(sil * v, h, l);
            size_t o = (size_t)gr * 128 + gc; oh[o] = h; ol[o] = l;
        }
    }
}

// ===== fused head-projection epilogue (512 thr) =====
// warp (wm,wn): rows wm*32+, out-cols wn*(R/4)+. NB = R/32 n-frags.
template<int R, bool IS_Q>
__device__ __forceinline__ void head_epilogue(
    const __nv_bfloat16* __restrict__ Wh, const __nv_bfloat16* __restrict__ Wl,
    char* smem, int row0, int h)
{
    const uint32_t sb = smem_u32(smem);
    float* sC = (float*)smem;
    const int tid = threadIdx.x, wid = tid >> 5, lane = tid & 31;
    const int wm = wid >> 2, wn = wid & 3;
    constexpr int NB = R / 32;

    // (a) kc0 weight tiles -> WB_OFF (h then l)
    for (int i = tid; i < R * 8; i += NTHR) {
        int r = i >> 3, cg = i & 7;
        uint32_t sw = (uint32_t)(r * 128 + ((cg ^ (r & 7)) << 4));
        cpasync16(sb + WB_OFF + sw,           Wh + (size_t)r * 128 + cg * 8);
        cpasync16(sb + WB_OFF + R * 128 + sw, Wl + (size_t)r * 128 + cg * 8);
    }
    asm volatile("cp.async.commit_group;" ::: "memory");

    // (b) rope + split sC -> sQ tiles (kc0_h, kc0_l, kc1_h, kc1_l @ SQ_OFF)
    for (int x = tid; x < 128 * 128; x += NTHR) {
        int r = x >> 7, d = x & 127;
        float v = sC[r * 132 + d];
        if (d < 64) {
            int i = d & 31;
            int sdx = ((row0 + r) & (S_ - 1)) * 32 + i;
            float co = g_cos[sdx], si = g_sin[sdx];
            float p = (d < 32) ? sC[r * 132 + d + 32] : sC[r * 132 + d - 32];
            v = (d < 32) ? v * co - p * si : v * co + p * si;
        }
        __nv_bfloat16 hh, ll; bsplit(v, hh, ll);
        int kc = d >> 6, dd = d & 63;
        uint32_t off = (uint32_t)(r * 128 + (((dd >> 3) ^ (r & 7)) << 4) + (dd & 7) * 2);
        *(__nv_bfloat16*)(smem + SQ_OFF + kc * 32768 + off)         = hh;
        *(__nv_bfloat16*)(smem + SQ_OFF + kc * 32768 + 16384 + off) = ll;
    }
    __syncthreads();

    // (c) kc1 weight tiles -> smem[0] (sC dead)
    for (int i = tid; i < R * 8; i += NTHR) {
        int r = i >> 3, cg = i & 7;
        uint32_t sw = (uint32_t)(r * 128 + ((cg ^ (r & 7)) << 4));
        cpasync16(sb + sw,           Wh + (size_t)r * 128 + 64 + cg * 8);
        cpasync16(sb + R * 128 + sw, Wl + (size_t)r * 128 + 64 + cg * 8);
    }
    asm volatile("cp.async.commit_group;" ::: "memory");
    asm volatile("cp.async.wait_group 1;" ::: "memory");
    __syncthreads();

    float acc2[2][NB][4];
#pragma unroll
    for (int mi = 0; mi < 2; mi++)
#pragma unroll
        for (int ni = 0; ni < NB; ni++)
#pragma unroll
            for (int j = 0; j < 4; j++) acc2[mi][ni][j] = 0.f;

#pragma unroll
    for (int kc = 0; kc < 2; kc++) {
        if (kc == 1) {
            asm volatile("cp.async.wait_group 0;" ::: "memory");
            __syncthreads();
        }
        const uint32_t aB = sb + SQ_OFF + kc * 32768;
        const uint32_t bB = (kc == 0) ? sb + WB_OFF : sb;
        const uint32_t bL = bB + R * 128;
#pragma unroll
        for (int ks = 0; ks < 4; ks++) {
            uint32_t ahf[2][4], alf[2][4], bhf[NB][2], blf[NB][2];
#pragma unroll
            for (int mi = 0; mi < 2; mi++) {
                int r  = wm * 32 + mi * 16 + (lane & 15);
                int cg = ks * 2 + (lane >> 4);
                uint32_t sw = (uint32_t)(r * 128 + ((cg ^ (r & 7)) << 4));
                ldsm4(ahf[mi], aB + sw);
                ldsm4(alf[mi], aB + 16384 + sw);
            }
#pragma unroll
            for (int bi = 0; bi < NB / 2; bi++) {
                int r  = wn * (R / 4) + bi * 16 + (lane & 15);
                int cg = ks * 2 + (lane >> 4);
                uint32_t sw = (uint32_t)(r * 128 + ((cg ^ (r & 7)) << 4));
                uint32_t t4[4];
                ldsm4(t4, bB + sw);
                bhf[bi*2][0]   = t4[0]; bhf[bi*2][1]   = t4[2];
                bhf[bi*2+1][0] = t4[1]; bhf[bi*2+1][1] = t4[3];
                ldsm4(t4, bL + sw);
                blf[bi*2][0]   = t4[0]; blf[bi*2][1]   = t4[2];
                blf[bi*2+1][0] = t4[1]; blf[bi*2+1][1] = t4[3];
            }
#pragma unroll
            for (int mi = 0; mi < 2; mi++)
#pragma unroll
                for (int ni = 0; ni < NB; ni++) {
                    mma16816(acc2[mi][ni], ahf[mi], bhf[ni]);
                    mma16816(acc2[mi][ni], ahf[mi], blf[ni]);
                    mma16816(acc2[mi][ni], alf[mi], bhf[ni]);
                }
        }
    }

    // write outputs
#pragma unroll
    for (int mi = 0; mi < 2; mi++)
#pragma unroll
        for (int ni = 0; ni < NB; ni++) {
            int gr = row0 + wm * 32 + mi * 16 + (lane >> 2);
            int c  = wn * (R / 4) + ni * 8 + (lane & 3) * 2;
#pragma unroll
            for (int half = 0; half < 2; half++) {
                int grr = gr + half * 8;
                float v0 = acc2[mi][ni][half * 2], v1 = acc2[mi][ni][half * 2 + 1];
                size_t hr = (size_t)grr * NH + h;
                if (IS_Q) {
                    if (c < 64) {
                        __nv_bfloat16 hh, ll;
                        bsplit(v0 * 0.125f, hh, ll);
                        g_qa_h[hr * 64 + c] = hh;     g_qa_l[hr * 64 + c] = ll;
                        bsplit(v1 * 0.125f, hh, ll);
                        g_qa_h[hr * 64 + c + 1] = hh; g_qa_l[hr * 64 + c + 1] = ll;
                    } else {
                        g_qg[hr * 128 + (c - 64)]     = v0;
                        g_qg[hr * 128 + (c - 63)]     = v1;
                    }
                } else {
                    __nv_bfloat16 hh, ll;
                    bsplit(v0, hh, ll);
                    g_kc_h[hr * 64 + c] = hh;     g_kc_l[hr * 64 + c] = ll;
                    bsplit(v1, hh, ll);
                    g_kc_h[hr * 64 + c + 1] = hh; g_kc_l[hr * 64 + c + 1] = ll;
                }
            }
        }
}

__global__ __launch_bounds__(NTHR) void gemm_one(
    const __nv_bfloat16* Ah, const __nv_bfloat16* Al,
    const __nv_bfloat16* Bh, const __nv_bfloat16* Bl,
    int Kdim, int mode, int Nvalid, int ostride,
    float* outf, __nv_bfloat16* oh, __nv_bfloat16* ol)
{
    extern __shared__ __align__(128) char smem[];
    const int r0 = blockIdx.x * 128, c0 = blockIdx.y * 128;
    mainloop_sC(Ah, Al, Bh, Bl, Kdim, smem, r0, c0);
    epilogue_simple(mode, Nvalid, ostride, outf, oh, ol, smem, r0, c0);
}

// Q (rope + fused qa|qg), K (rope + fused kc), V-folded (split vc): grid (32,16,3)
__global__ __launch_bounds__(NTHR) void gemm_qkv(
    const __nv_bfloat16* Ah, const __nv_bfloat16* Al)
{
    extern __shared__ __align__(128) char smem[];
    const int r0 = blockIdx.x * 128, c0 = blockIdx.y * 128;
    const int z = blockIdx.z;
    if (z == 2 && blockIdx.y >= 8) return;
    const __nv_bfloat16* Bh = (z == 0) ? g_WqT_h : (z == 1) ? g_WkT_h : g_MvT_h;
    const __nv_bfloat16* Bl = (z == 0) ? g_WqT_l : (z == 1) ? g_WkT_l : g_MvT_l;
    mainloop_sC(Ah, Al, Bh, Bl, HID, smem, r0, c0);
    if (z == 0)      head_epilogue<192, true >(g_Wcat_h, g_Wcat_l, smem, r0, blockIdx.y);
    else if (z == 1) head_epilogue<64,  false>(g_WkcT_h, g_WkcT_l, smem, r0, blockIdx.y);
    else             epilogue_simple(1, 1024, 1024, nullptr, g_vc_h, g_vc_l, smem, r0, c0);
}

// ===================== tensor-core flash attention (unchanged) ===========
#define ATT_SMEM (32768 + 2 * 65536)

__global__ __launch_bounds__(256, 1) void attn_mma()
{
    extern __shared__ __align__(128) char smem[];
    const uint32_t sb = smem_u32(smem);
    const int tid = threadIdx.x, wid = tid >> 5, lane = tid & 31;
    const int b = blockIdx.y >> 4, h = blockIdx.y & 15;
    const int q0 = blockIdx.x * 128;

    for (int i = tid; i < 1024; i += 256) {
        int r = i >> 3, g = i & 7;
        uint32_t sw = (uint32_t)(r * 128 + ((g ^ (r & 7)) << 4));
        size_t gl = ((size_t)((b * S_ + q0 + r) * NH + h)) * RK + g * 8;
        cpasync16(sb + sw,         g_qa_h + gl);
        cpasync16(sb + 16384 + sw, g_qa_l + gl);
    }
    auto load_kv = [&](int t, int s) {
        const uint32_t kb = sb + 32768 + (uint32_t)s * 65536;
        for (int i = tid; i < 1024; i += 256) {
            int r = i >> 3, g = i & 7;
            uint32_t sw = (uint32_t)(r * 128 + ((g ^ (r & 7)) << 4));
            size_t gl = ((size_t)((b * S_ + t * 128 + r) * NH + h)) * RK + g * 8;
            cpasync16(kb + sw,         g_kc_h + gl);
            cpasync16(kb + 16384 + sw, g_kc_l + gl);
            cpasync16(kb + 32768 + sw, g_vc_h + gl);
            cpasync16(kb + 49152 + sw, g_vc_l + gl);
        }
    };
    load_kv(0, 0);
    asm volatile("cp.async.commit_group;" ::: "memory");

    float m1 = -INFINITY, m2 = -INFINITY, l1 = 0.f, l2 = 0.f;
    float ao[8][4];
#pragma unroll
    for (int nf = 0; nf < 8; nf++)
#pragma unroll
        for (int j = 0; j < 4; j++) ao[nf][j] = 0.f;
    uint32_t qh[4][4], qlo[4][4];
    int qloaded = 0;

    for (int t = 0; t < 16; ++t) {
        if (t + 1 < 16) {
            load_kv(t + 1, (t + 1) & 1);
            asm volatile("cp.async.commit_group;" ::: "memory");
            asm volatile("cp.async.wait_group 1;" ::: "memory");
        } else {
            asm volatile("cp.async.wait_group 0;" ::: "memory");
        }
        __syncthreads();
        if (!qloaded) {
            qloaded = 1;
#pragma unroll
            for (int kc = 0; kc < 4; kc++) {
                int r = wid * 16 + (lane & 15), cg = kc * 2 + (lane >> 4);
                uint32_t sw = (uint32_t)(r * 128 + ((cg ^ (r & 7)) << 4));
                ldsm4(qh[kc],  sb + sw);
                ldsm4(qlo[kc], sb + 16384 + sw);
            }
        }
        const uint32_t kb = sb + 32768 + (uint32_t)(t & 1) * 65536;

        float sa[16][4];
#pragma unroll
        for (int ni = 0; ni < 16; ni++)
#pragma unroll
            for (int j = 0; j < 4; j++) sa[ni][j] = 0.f;
#pragma unroll
        for (int kc = 0; kc < 4; kc++) {
            uint32_t kh[16][2], kl[16][2];
#pragma unroll
            for (int bi = 0; bi < 8; bi++) {
                int r = bi * 16 + (lane & 15), cg = kc * 2 + (lane >> 4);
                uint32_t sw = (uint32_t)(r * 128 + ((cg ^ (r & 7)) << 4));
                uint32_t t4[4];
                ldsm4(t4, kb + sw);
                kh[bi*2][0]=t4[0]; kh[bi*2][1]=t4[2]; kh[bi*2+1][0]=t4[1]; kh[bi*2+1][1]=t4[3];
                ldsm4(t4, kb + 16384 + sw);
                kl[bi*2][0]=t4[0]; kl[bi*2][1]=t4[2]; kl[bi*2+1][0]=t4[1]; kl[bi*2+1][1]=t4[3];
            }
#pragma unroll
            for (int ni = 0; ni < 16; ni++) {
                mma16816(sa[ni], qh[kc],  kh[ni]);
                mma16816(sa[ni], qh[kc],  kl[ni]);
                mma16816(sa[ni], qlo[kc], kh[ni]);
            }
        }

        float mx1 = -INFINITY, mx2 = -INFINITY;
#pragma unroll
        for (int ni = 0; ni < 16; ni++) {
            mx1 = fmaxf(mx1, fmaxf(sa[ni][0], sa[ni][1]));
            mx2 = fmaxf(mx2, fmaxf(sa[ni][2], sa[ni][3]));
        }
        mx1 = fmaxf(mx1, __shfl_xor_sync(0xffffffffu, mx1, 1));
        mx1 = fmaxf(mx1, __shfl_xor_sync(0xffffffffu, mx1, 2));
        mx2 = fmaxf(mx2, __shfl_xor_sync(0xffffffffu, mx2, 1));
        mx2 = fmaxf(mx2, __shfl_xor_sync(0xffffffffu, mx2, 2));
        float nm1 = fmaxf(m1, mx1), nm2 = fmaxf(m2, mx2);
        float al1 = __expf(m1 - nm1), al2 = __expf(m2 - nm2);
        float s1 = 0.f, s2 = 0.f;
#pragma unroll
        for (int ni = 0; ni < 16; ni++) {
            sa[ni][0] = __expf(sa[ni][0] - nm1); s1 += sa[ni][0];
            sa[ni][1] = __expf(sa[ni][1] - nm1); s1 += sa[ni][1];
            sa[ni][2] = __expf(sa[ni][2] - nm2); s2 += sa[ni][2];
            sa[ni][3] = __expf(sa[ni][3] - nm2); s2 += sa[ni][3];
        }
        s1 += __shfl_xor_sync(0xffffffffu, s1, 1);
        s1 += __shfl_xor_sync(0xffffffffu, s1, 2);
        s2 += __shfl_xor_sync(0xffffffffu, s2, 1);
        s2 += __shfl_xor_sync(0xffffffffu, s2, 2);
        l1 = l1 * al1 + s1; l2 = l2 * al2 + s2;
        m1 = nm1; m2 = nm2;
#pragma unroll
        for (int nf = 0; nf < 8; nf++) {
            ao[nf][0] *= al1; ao[nf][1] *= al1;
            ao[nf][2] *= al2; ao[nf][3] *= al2;
        }

#pragma unroll
        for (int j = 0; j < 8; j++) {
            uint32_t ph[4], pl[4];
            packsplit(sa[2*j][0],   sa[2*j][1],   ph[0], pl[0]);
            packsplit(sa[2*j][2],   sa[2*j][3],   ph[1], pl[1]);
            packsplit(sa[2*j+1][0], sa[2*j+1][1], ph[2], pl[2]);
            packsplit(sa[2*j+1][2], sa[2*j+1][3], ph[3], pl[3]);
            uint32_t vh[8][2], vl[8][2];
#pragma unroll
            for (int q = 0; q < 4; q++) {
                int row = j * 16 + ((lane >> 3) & 1) * 8 + (lane & 7);
                int g   = q * 2 + (lane >> 4);
                uint32_t sw = (uint32_t)(row * 128 + ((g ^ (row & 7)) << 4));
                uint32_t t4[4];
                ldsm4t(t4, kb + 32768 + sw);
                vh[q*2][0]=t4[0]; vh[q*2][1]=t4[1]; vh[q*2+1][0]=t4[2]; vh[q*2+1][1]=t4[3];
                ldsm4t(t4, kb + 49152 + sw);
                vl[q*2][0]=t4[0]; vl[q*2][1]=t4[1]; vl[q*2+1][0]=t4[2]; vl[q*2+1][1]=t4[3];
            }
#pragma unroll
            for (int nf = 0; nf < 8; nf++) {
                mma16816(ao[nf], ph, vh[nf]);
                mma16816(ao[nf], pl, vh[nf]);
                mma16816(ao[nf], ph, vl[nf]);
            }
        }
        __syncthreads();
    }

    float il1 = 1.f / l1, il2 = 1.f / l2;
    int r1 = q0 + wid * 16 + (lane >> 2);
    int cb = 2 * (lane & 3);
    size_t b1 = ((size_t)((b * S_ + r1) * NH + h)) * RK;
    size_t b2 = ((size_t)((b * S_ + r1 + 8) * NH + h)) * RK;
#pragma unroll
    for (int nf = 0; nf < 8; nf++) {
        int c = nf * 8 + cb;
        __nv_bfloat16 hh, ll;
        bsplit(ao[nf][0] * il1, hh, ll); g_oc_h[b1 + c]     = hh; g_oc_l[b1 + c]     = ll;
        bsplit(ao[nf][1] * il1, hh, ll); g_oc_h[b1 + c + 1] = hh; g_oc_l[b1 + c + 1] = ll;
        bsplit(ao[nf][2] * il2, hh, ll); g_oc_h[b2 + c]     = hh; g_oc_l[b2 + c]     = ll;
        bsplit(ao[nf][3] * il2, hh, ll); g_oc_h[b2 + c + 1] = hh; g_oc_l[b2 + c + 1] = ll;
    }
}

// ===================== launch =====================
#define SYMF(p, s) cudaGetSymbolAddress((void**)&p, s)

extern "C" void kernel_launch(void* const* d_in, const int* in_sizes, int n_in,
                              void* d_out, int out_size)
{
    const float* hs  = (const float*)d_in[0];
    const int*   pos = (const int*)  d_in[1];
    const float* Wq  = (const float*)d_in[2];
    const float* Wk  = (const float*)d_in[3];
    const float* Wv  = (const float*)d_in[4];
    const float* Wkc = (const float*)d_in[5];
    const float* Wvc = (const float*)d_in[6];
    const float* Wqa = (const float*)d_in[7];
    const float* Wqg = (const float*)d_in[8];
    const float* Wov = (const float*)d_in[9];
    const float* Wo  = (const float*)d_in[10];
    float* out = (float*)d_out;

    __nv_bfloat16 *hsh,*hsl,*woh,*wol,*ovh,*ovl,*och,*ocl,*gth,*gtl;
    SYMF(hsh,g_hs_h);  SYMF(hsl,g_hs_l);
    SYMF(woh,g_WoT_h); SYMF(wol,g_WoT_l);
    SYMF(ovh,g_WovT_h);SYMF(ovl,g_WovT_l);
    SYMF(och,g_oc_h);  SYMF(ocl,g_oc_l);
    SYMF(gth,g_gat_h); SYMF(gtl,g_gat_l);

    prep_misc<<<256, 256>>>(pos, Wqa, Wqg, Wkc, Wov);                     // 1
    split2<<<4096, 256>>>(hs, hsh, hsl, BS_ROWS*HID);                     // 2
    cudaFuncSetAttribute(prep_weights, cudaFuncAttributeMaxDynamicSharedMemorySize, PREPW_SMEM);
    prep_weights<<<12800, 256, PREPW_SMEM>>>(Wq, Wk, Wo, Wv, Wvc);        // 3

    cudaFuncSetAttribute(gemm_one, cudaFuncAttributeMaxDynamicSharedMemorySize, GSMEM);
    cudaFuncSetAttribute(gemm_qkv, cudaFuncAttributeMaxDynamicSharedMemorySize, GSMEM);

    gemm_qkv<<<dim3(32,16,3), NTHR, GSMEM>>>(hsh, hsl);                   // 4 (profiled)

    cudaFuncSetAttribute(attn_mma, cudaFuncAttributeMaxDynamicSharedMemorySize, ATT_SMEM);
    attn_mma<<<dim3(S_/128, B_*NH), 256, ATT_SMEM>>>();                   // 5

    gemm_one<<<dim3(512,1), NTHR, GSMEM>>>(och, ocl, ovh, ovl, 64, 4, 128, 128,
                                           nullptr, gth, gtl);            // 6
    gemm_one<<<dim3(32,16), NTHR, GSMEM>>>(gth, gtl, woh, wol, HID, 0, HID, HID,
                                           out, nullptr, nullptr);        // 7
}